// round 9
// baseline (speedup 1.0000x reference)
#include <cuda_runtime.h>
#include <cuda_bf16.h>
#include <math.h>

#define BB 8
#define NN 8192
#define DD 128
#define DVV 128
#define MM 256
#define NSPLIT 16

#define SCALE_U 0.29730177875068026f   // 128^-0.25
#define H_SCALE 0.04419417382415922f   // 1/(2*sqrt(128))
#define INV_SQRT_M 0.0625f             // 1/sqrt(256)
#define EPSC (1e-4f * INV_SQRT_M)

typedef unsigned long long ull;
typedef unsigned int u32;

// ---------------------------------------------------------------------------
// Device scratch.  g_Qp_* double as Kp' (K pass) then Qp (Q pass) — the
// launches are stream-serial so the reuse is safe.
// ---------------------------------------------------------------------------
__device__ float g_lmax[BB * NN];                 // per-token max_m U
__device__ float g_bmax[BB];
__device__ float g_KVpart[NSPLIT][BB * DVV * MM]; // KV^T partials [b][dv][m]
__device__ float g_KsumPart[NSPLIT][BB * MM];
__device__ float g_Ksum[BB * MM];
__device__ float g_rinv[BB * NN];
__device__ float g_CvecPart[16][BB * DVV];
__device__ float g_SmaskPart[16][BB];
__device__ float g_Cvec[BB * DVV];
__device__ float g_SmaskEps[BB];
// omega pre-packed as mma B-fragments: [kstep(8)][nb(32)][reg(2)][lane(32)]
__device__ u32 g_wfrag_hi[8 * 32 * 2 * 32];
__device__ u32 g_wfrag_lo[8 * 32 * 2 * 32];
__device__ __nv_bfloat16 g_Qp_hi[(size_t)BB * NN * MM];   // [b][n][m]
__device__ __nv_bfloat16 g_Qp_lo[(size_t)BB * NN * MM];
__device__ __nv_bfloat16 g_KVT_hi[BB * DVV * MM];         // [b][dv][m]
__device__ __nv_bfloat16 g_KVT_lo[BB * DVV * MM];

// ---------------------------------------------------------------------------
// PTX helpers (sm_80-level)
// ---------------------------------------------------------------------------
__device__ __forceinline__ u32 smem_u32(const void* p) {
    u32 a;
    asm("{ .reg .u64 t; cvta.to.shared.u64 t, %1; cvt.u32.u64 %0, t; }" : "=r"(a) : "l"(p));
    return a;
}
__device__ __forceinline__ void ldsm_x4(u32& r0, u32& r1, u32& r2, u32& r3, u32 addr) {
    asm volatile("ldmatrix.sync.aligned.m8n8.x4.shared.b16 {%0,%1,%2,%3}, [%4];"
                 : "=r"(r0), "=r"(r1), "=r"(r2), "=r"(r3) : "r"(addr));
}
__device__ __forceinline__ void ldsm_x4t(u32& r0, u32& r1, u32& r2, u32& r3, u32 addr) {
    asm volatile("ldmatrix.sync.aligned.m8n8.x4.trans.shared.b16 {%0,%1,%2,%3}, [%4];"
                 : "=r"(r0), "=r"(r1), "=r"(r2), "=r"(r3) : "r"(addr));
}
__device__ __forceinline__ void mma_bf16(float* c, const u32* a, const u32* b) {
    asm volatile("mma.sync.aligned.m16n8k16.row.col.f32.bf16.bf16.f32 "
                 "{%0,%1,%2,%3}, {%4,%5,%6,%7}, {%8,%9}, {%0,%1,%2,%3};"
                 : "+f"(c[0]), "+f"(c[1]), "+f"(c[2]), "+f"(c[3])
                 : "r"(a[0]), "r"(a[1]), "r"(a[2]), "r"(a[3]), "r"(b[0]), "r"(b[1]));
}
__device__ __forceinline__ u32 bpack(float lo, float hi) {
    u32 r;
    asm("cvt.rn.bf16x2.f32 %0, %1, %2;" : "=r"(r) : "f"(hi), "f"(lo));
    return r;
}
__device__ __forceinline__ void cvt8(const float* x, uint4& h4, uint4& l4) {
    u32 h[4], l[4];
    #pragma unroll
    for (int i = 0; i < 4; i++) {
        u32 p = bpack(x[2 * i], x[2 * i + 1]);
        h[i] = p;
        float r0 = x[2 * i]     - __uint_as_float(p << 16);
        float r1 = x[2 * i + 1] - __uint_as_float(p & 0xFFFF0000u);
        l[i] = bpack(r0, r1);
    }
    h4 = make_uint4(h[0], h[1], h[2], h[3]);
    l4 = make_uint4(l[0], l[1], l[2], l[3]);
}

__device__ __forceinline__ float fexp(float x) {
    x = fmaxf(x, -87.0f);
    float t = x * 1.4426950408889634f;
    float r = rintf(t);
    float f = t - r;
    float z = f * 0.6931471805599453f;
    float p = 1.0f + z * (1.0f + z * (0.5f + z * (0.16666667f +
              z * (0.041666667f + z * (0.0083333333f + z * 0.0013888889f)))));
    return __int_as_float(((int)r + 127) << 23) * p;
}
__device__ __forceinline__ float warpMax(float v) {
    #pragma unroll
    for (int o = 16; o; o >>= 1) v = fmaxf(v, __shfl_xor_sync(0xffffffffu, v, o));
    return v;
}
__device__ __forceinline__ void atomicMaxFloat(float* addr, float val) {
    int old = __float_as_int(*addr);
    while (__int_as_float(old) < val) {
        int prev = atomicCAS((int*)addr, old, __float_as_int(val));
        if (prev == old) break;
        old = prev;
    }
}

__global__ void init_kernel() {
    if (threadIdx.x < BB) g_bmax[threadIdx.x] = -INFINITY;
}

__global__ void prep_omega(const float* __restrict__ omega) {
    int id = blockIdx.x * 256 + threadIdx.x;   // 16384 total
    int m = id >> 6;
    int dp = id & 63;
    int d = dp * 2;
    float w0 = omega[(size_t)d * MM + m] * SCALE_U;
    float w1 = omega[(size_t)(d + 1) * MM + m] * SCALE_U;
    u32 hp = bpack(w0, w1);
    float r0 = w0 - __uint_as_float(hp << 16);
    float r1 = w1 - __uint_as_float(hp & 0xFFFF0000u);
    u32 lp = bpack(r0, r1);
    int idx = (((d >> 4) * 32 + (m >> 3)) * 2 + ((d >> 3) & 1)) * 32
            + (m & 7) * 4 + ((d & 7) >> 1);
    g_wfrag_hi[idx] = hp;
    g_wfrag_lo[idx] = lp;
}

// ---------------------------------------------------------------------------
// vsum: deterministic partials of Cvec[b][dv]=sum_n mask*V and Smask[b].
// ---------------------------------------------------------------------------
__global__ void __launch_bounds__(256)
vsum_kernel(const float* __restrict__ V, const float* __restrict__ mask) {
    __shared__ float sred[256];
    const int part = blockIdx.x;   // 16
    const int b = blockIdx.y;
    const int tid = threadIdx.x;
    const int dv = tid & 127, g = tid >> 7;

    float acc = 0.f;
    const int nb = part * 512 + g * 256;
    #pragma unroll 4
    for (int r = 0; r < 256; r++) {
        int n = nb + r;
        acc = fmaf(mask[b * NN + n], V[((size_t)(b * NN + n)) * DVV + dv], acc);
    }
    sred[tid] = acc;
    __syncthreads();
    if (tid < 128) g_CvecPart[part][b * DVV + tid] = sred[tid] + sred[tid + 128];
    __syncthreads();
    {
        int n0m = part * 512 + tid * 2;
        sred[tid] = mask[b * NN + n0m] + mask[b * NN + n0m + 1];
    }
    __syncthreads();
    for (int s = 128; s > 0; s >>= 1) {
        if (tid < s) sred[tid] += sred[tid + s];
        __syncthreads();
    }
    if (tid == 0) g_SmaskPart[part][b] = sred[0];
}

__global__ void fold_kernel() {
    int i = blockIdx.x * 256 + threadIdx.x;
    if (i < BB * DVV) {
        float s = 0.f;
        #pragma unroll
        for (int p = 0; p < 16; p++) s += g_CvecPart[p][i];
        g_Cvec[i] = s * EPSC;
    }
    if (i < BB) {
        float s = 0.f;
        #pragma unroll
        for (int p = 0; p < 16; p++) s += g_SmaskPart[p][i];
        g_SmaskEps[i] = s * EPSC;
    }
}

// ---------------------------------------------------------------------------
// Projections: CTA = 64 tok x 256 m, K=128. Warp tile 32 tok x 64 m.
// B (omega) streamed per-nb from gmem frags. smem: sA hi/lo; sU overlays.
// ---------------------------------------------------------------------------
#define P_SA 0
#define P_SA_LO 16384
#define P_SMEM 67584
#define SU_STRIDE 264

__device__ __forceinline__ void proj_mma_main(
    const float* __restrict__ Xb, char* dyn, u32 sb,
    float c[2][8][4], float* sHred)
{
    const int tid = threadIdx.x;
    const int lane = tid & 31;
    const int w = tid >> 5;

    {   // A: 64 tok x 128 d, f32 -> bf16 hi/lo, swizzled; h partials
        int row = tid >> 2, seg = (tid & 3) * 32;
        const float* src = Xb + (size_t)row * DD + seg;
        float hs = 0.f;
        #pragma unroll
        for (int q = 0; q < 4; q++) {
            float x[8];
            float4 v0 = *(const float4*)(src + q * 8);
            float4 v1 = *(const float4*)(src + q * 8 + 4);
            x[0] = v0.x; x[1] = v0.y; x[2] = v0.z; x[3] = v0.w;
            x[4] = v1.x; x[5] = v1.y; x[6] = v1.z; x[7] = v1.w;
            #pragma unroll
            for (int e = 0; e < 8; e++) hs = fmaf(x[e], x[e], hs);
            uint4 h4, l4;
            cvt8(x, h4, l4);
            int chunk = ((seg >> 3) + q) ^ (row & 7);
            *(uint4*)(dyn + P_SA + row * 256 + (chunk << 4)) = h4;
            *(uint4*)(dyn + P_SA_LO + row * 256 + (chunk << 4)) = l4;
        }
        sHred[tid] = hs;
    }
    __syncthreads();

    const int tok0 = (w & 1) * 32;
    const int m0w = (w >> 1) * 64;
    const int rowA0 = tok0 + ((lane >> 3) & 1) * 8 + (lane & 7);
    const int kselA = (lane >> 4) & 1;
    const int nbBase = (m0w >> 3);

    #pragma unroll
    for (int ks = 0; ks < 8; ks++) {
        int kc = ks * 2;
        u32 ah[2][4], al[2][4];
        #pragma unroll
        for (int mb = 0; mb < 2; mb++) {
            int row = rowA0 + mb * 16;
            u32 adr = sb + P_SA + row * 256 + (((kc + kselA) ^ (row & 7)) << 4);
            ldsm_x4(ah[mb][0], ah[mb][1], ah[mb][2], ah[mb][3], adr);
            ldsm_x4(al[mb][0], al[mb][1], al[mb][2], al[mb][3], adr + 16384);
        }
        #pragma unroll
        for (int nb = 0; nb < 8; nb++) {
            int base = ((ks * 32 + nbBase + nb) * 2) * 32 + lane;
            u32 bh[2], bl[2];
            bh[0] = g_wfrag_hi[base];
            bh[1] = g_wfrag_hi[base + 32];
            bl[0] = g_wfrag_lo[base];
            bl[1] = g_wfrag_lo[base + 32];
            #pragma unroll
            for (int mb = 0; mb < 2; mb++) {
                mma_bf16(c[mb][nb], ah[mb], bh);
                mma_bf16(c[mb][nb], al[mb], bh);
                mma_bf16(c[mb][nb], ah[mb], bl);
            }
        }
    }
    __syncthreads();
}

__device__ __forceinline__ void store_sU(float c[2][8][4], float* sU, int tid) {
    const int lane = tid & 31, w = tid >> 5;
    const int tok0 = (w & 1) * 32, m0w = (w >> 1) * 64;
    const int gid = lane >> 2, tig = lane & 3;
    #pragma unroll
    for (int mb = 0; mb < 2; mb++)
        #pragma unroll
        for (int nb = 0; nb < 8; nb++) {
            int r0 = tok0 + mb * 16 + gid;
            int m = m0w + nb * 8 + 2 * tig;
            *(float2*)&sU[r0 * SU_STRIDE + m] = make_float2(c[mb][nb][0], c[mb][nb][1]);
            *(float2*)&sU[(r0 + 8) * SU_STRIDE + m] = make_float2(c[mb][nb][2], c[mb][nb][3]);
        }
}

// kproj: writes Kp' = exp(U - h - lmax) as bf16 hi/lo into g_Qp_*, plus lmax.
__global__ void __launch_bounds__(256, 2)
kproj_mma(const float* __restrict__ Kin) {
    extern __shared__ __align__(16) char dyn[];
    __shared__ float sHred[256];
    __shared__ float wred[8];

    const int tid = threadIdx.x;
    const int b = blockIdx.y;
    const int n0 = blockIdx.x * 64;
    const u32 sbase = smem_u32(dyn);

    float c[2][8][4];
    #pragma unroll
    for (int mb = 0; mb < 2; mb++)
        #pragma unroll
        for (int nb = 0; nb < 8; nb++)
            #pragma unroll
            for (int q = 0; q < 4; q++) c[mb][nb][q] = 0.f;

    proj_mma_main(Kin + ((size_t)b * NN + n0) * DD, dyn, sbase, c, sHred);

    float* sU = (float*)dyn;
    store_sU(c, sU, tid);
    __syncthreads();

    const int tok = tid >> 2, t4 = tid & 3;
    const int seg = t4 * 64;
    const float* Urow = sU + tok * SU_STRIDE + seg;

    float mx = -INFINITY;
    #pragma unroll
    for (int i = 0; i < 64; i++) mx = fmaxf(mx, Urow[i]);
    mx = fmaxf(mx, __shfl_xor_sync(0xffffffffu, mx, 1));
    mx = fmaxf(mx, __shfl_xor_sync(0xffffffffu, mx, 2));   // per-token lmax

    float h = (sHred[tok * 4] + sHred[tok * 4 + 1] + sHred[tok * 4 + 2] + sHred[tok * 4 + 3]) * H_SCALE;
    float off = h + mx;
    const size_t gbase = ((size_t)(b * NN + n0 + tok)) * MM + seg;

    #pragma unroll
    for (int q = 0; q < 8; q++) {
        u32 h4[4], l4[4];
        #pragma unroll
        for (int e = 0; e < 4; e++) {
            int i = q * 8 + 2 * e;
            float q0 = fexp(Urow[i] - off);
            float q1 = fexp(Urow[i + 1] - off);
            u32 p = bpack(q0, q1);
            h4[e] = p;
            float r0 = q0 - __uint_as_float(p << 16);
            float r1 = q1 - __uint_as_float(p & 0xFFFF0000u);
            l4[e] = bpack(r0, r1);
        }
        *(uint4*)&g_Qp_hi[gbase + q * 8] = make_uint4(h4[0], h4[1], h4[2], h4[3]);
        *(uint4*)&g_Qp_lo[gbase + q * 8] = make_uint4(l4[0], l4[1], l4[2], l4[3]);
    }
    if (t4 == 0) g_lmax[b * NN + n0 + tok] = mx;

    float bm = warpMax(mx);
    if ((tid & 31) == 0) wred[tid >> 5] = bm;
    __syncthreads();
    if (tid == 0) {
        float m = wred[0];
        #pragma unroll
        for (int q = 1; q < 8; q++) m = fmaxf(m, wred[q]);
        atomicMaxFloat(&g_bmax[b], m);
    }
}

__global__ void __launch_bounds__(256, 2)
qproj_mma(const float* __restrict__ Qin, const float* __restrict__ mask) {
    extern __shared__ __align__(16) char dyn[];
    __shared__ float sHred[256];
    __shared__ float sKsum[MM];

    const int tid = threadIdx.x;
    const int b = blockIdx.y;
    const int n0 = blockIdx.x * 64;
    const u32 sbase = smem_u32(dyn);

    if (tid < MM) sKsum[tid] = g_Ksum[b * MM + tid];

    float c[2][8][4];
    #pragma unroll
    for (int mb = 0; mb < 2; mb++)
        #pragma unroll
        for (int nb = 0; nb < 8; nb++)
            #pragma unroll
            for (int q = 0; q < 4; q++) c[mb][nb][q] = 0.f;

    proj_mma_main(Qin + ((size_t)b * NN + n0) * DD, dyn, sbase, c, sHred);

    float* sU = (float*)dyn;
    store_sU(c, sU, tid);
    __syncthreads();

    const int tok = tid >> 2, t4 = tid & 3;
    const int seg = t4 * 64;
    const float* Urow = sU + tok * SU_STRIDE + seg;

    float mx = -INFINITY;
    #pragma unroll
    for (int i = 0; i < 64; i++) mx = fmaxf(mx, Urow[i]);
    mx = fmaxf(mx, __shfl_xor_sync(0xffffffffu, mx, 1));
    mx = fmaxf(mx, __shfl_xor_sync(0xffffffffu, mx, 2));

    float h = (sHred[tok * 4] + sHred[tok * 4 + 1] + sHred[tok * 4 + 2] + sHred[tok * 4 + 3]) * H_SCALE;
    float s = INV_SQRT_M * mask[b * NN + n0 + tok];
    const size_t gbase = ((size_t)(b * NN + n0 + tok)) * MM + seg;

    float np = 0.f;
    #pragma unroll
    for (int q = 0; q < 8; q++) {
        u32 h4[4], l4[4];
        #pragma unroll
        for (int e = 0; e < 4; e++) {
            int i = q * 8 + 2 * e;
            float q0 = (fexp(Urow[i] - h - mx) + 1e-4f) * s;
            float q1 = (fexp(Urow[i + 1] - h - mx) + 1e-4f) * s;
            np = fmaf(q0, sKsum[seg + i], np);
            np = fmaf(q1, sKsum[seg + i + 1], np);
            u32 p = bpack(q0, q1);
            h4[e] = p;
            float r0 = q0 - __uint_as_float(p << 16);
            float r1 = q1 - __uint_as_float(p & 0xFFFF0000u);
            l4[e] = bpack(r0, r1);
        }
        *(uint4*)&g_Qp_hi[gbase + q * 8] = make_uint4(h4[0], h4[1], h4[2], h4[3]);
        *(uint4*)&g_Qp_lo[gbase + q * 8] = make_uint4(l4[0], l4[1], l4[2], l4[3]);
    }
    np += __shfl_xor_sync(0xffffffffu, np, 1);
    np += __shfl_xor_sync(0xffffffffu, np, 2);
    if (t4 == 0) g_rinv[b * NN + n0 + tok] = 1.0f / (np + 1e-8f);
}

// ---------------------------------------------------------------------------
// kv_mma: KVT[dv][m] = sum_n a(n)*V[n][dv]*Kp'[n][m]. CTA 128 dv x 128 m.
// Kp' pre-split bf16 from kproj: plain swizzled copy. a(n)=exp(lmax-mx)*s(n)
// folded into the V conversion. Ksum accumulated from unpacked Kp' frags.
// ---------------------------------------------------------------------------
#define KV_SV 0
#define KV_SV_LO 16384
#define KV_SKP 32768
#define KV_SKP_LO 49152
#define KV_SMEM 65536

__global__ void __launch_bounds__(256, 2)
kv_mma(const float* __restrict__ V, const float* __restrict__ mask) {
    extern __shared__ __align__(16) char dyn[];

    const int tid = threadIdx.x;
    const int lane = tid & 31;
    const int w = tid >> 5;
    const int b = blockIdx.z;
    const int m0blk = blockIdx.y * 128;
    const int split = blockIdx.x;
    const float mx = g_bmax[b];
    const u32 sbase = smem_u32(dyn);

    const int dv0 = (w & 3) * 32;
    const int m0w = (w >> 2) * 64;
    const int gid = lane >> 2, tig = lane & 3;

    float c[2][8][4];
    #pragma unroll
    for (int mb = 0; mb < 2; mb++)
        #pragma unroll
        for (int nb = 0; nb < 8; nb++)
            #pragma unroll
            for (int q = 0; q < 4; q++) c[mb][nb][q] = 0.f;
    float ksloc[8];
    #pragma unroll
    for (int i = 0; i < 8; i++) ksloc[i] = 0.f;

    const int mg2 = tid & 15;          // Kp loader: 1 uint4 chunk (8 m)
    const int ng = tid >> 4;           // Kp loader: 4 rows each

    const int nbase = split * (NN / NSPLIT);
    for (int ch = 0; ch < (NN / NSPLIT) / 64; ch++) {
        const int n0c = nbase + ch * 64;
        {   // V: [64 n][128 dv] -> bf16 hi/lo swizzled, scaled by a(n)
            int row = tid >> 2, seg = (tid & 3) * 32;
            int bn = b * NN + n0c + row;
            float av = fexp(g_lmax[bn] - mx) * (INV_SQRT_M * mask[bn]);
            const float* src = V + ((size_t)bn) * DVV + seg;
            #pragma unroll
            for (int q = 0; q < 4; q++) {
                float x[8];
                float4 v0 = *(const float4*)(src + q * 8);
                float4 v1 = *(const float4*)(src + q * 8 + 4);
                x[0] = v0.x * av; x[1] = v0.y * av; x[2] = v0.z * av; x[3] = v0.w * av;
                x[4] = v1.x * av; x[5] = v1.y * av; x[6] = v1.z * av; x[7] = v1.w * av;
                uint4 h4, l4;
                cvt8(x, h4, l4);
                int chunk = ((seg >> 3) + q) ^ (row & 7);
                *(uint4*)(dyn + KV_SV + row * 256 + (chunk << 4)) = h4;
                *(uint4*)(dyn + KV_SV_LO + row * 256 + (chunk << 4)) = l4;
            }
        }
        {   // Kp': plain copy of pre-split bf16 + ksum accumulation
            #pragma unroll
            for (int r = 0; r < 4; r++) {
                int n = ng * 4 + r;
                int bn = b * NN + n0c + n;
                const uint4 hi4 = *(const uint4*)&g_Qp_hi[((size_t)bn) * MM + m0blk + mg2 * 8];
                const uint4 lo4 = *(const uint4*)&g_Qp_lo[((size_t)bn) * MM + m0blk + mg2 * 8];
                int chunk = mg2 ^ (n & 7);
                *(uint4*)(dyn + KV_SKP + n * 256 + (chunk << 4)) = hi4;
                *(uint4*)(dyn + KV_SKP_LO + n * 256 + (chunk << 4)) = lo4;
                float a = fexp(g_lmax[bn] - mx) * (INV_SQRT_M * mask[bn]);
                u32 hv[4] = {hi4.x, hi4.y, hi4.z, hi4.w};
                u32 lv[4] = {lo4.x, lo4.y, lo4.z, lo4.w};
                #pragma unroll
                for (int j = 0; j < 4; j++) {
                    float v0 = __uint_as_float(hv[j] << 16) + __uint_as_float(lv[j] << 16);
                    float v1 = __uint_as_float(hv[j] & 0xFFFF0000u) + __uint_as_float(lv[j] & 0xFFFF0000u);
                    ksloc[2 * j]     = fmaf(a, v0, ksloc[2 * j]);
                    ksloc[2 * j + 1] = fmaf(a, v1, ksloc[2 * j + 1]);
                }
            }
        }
        __syncthreads();

        #pragma unroll
        for (int ks = 0; ks < 4; ks++) {
            const int kk = ks * 16;
            u32 avh[2][4], avl[2][4];
            {
                int row = kk + ((lane >> 4) & 1) * 8 + (lane & 7);
                int cb = (dv0 >> 3) + ((lane >> 3) & 1);
                #pragma unroll
                for (int mb = 0; mb < 2; mb++) {
                    int chunk = (cb + mb * 2) ^ (row & 7);
                    u32 adr = sbase + KV_SV + row * 256 + (chunk << 4);
                    ldsm_x4t(avh[mb][0], avh[mb][1], avh[mb][2], avh[mb][3], adr);
                    ldsm_x4t(avl[mb][0], avl[mb][1], avl[mb][2], avl[mb][3], adr + 16384);
                }
            }
            {
                int row = kk + ((lane >> 3) & 1) * 8 + (lane & 7);
                int cb = (m0w >> 3) + ((lane >> 4) & 1);
                #pragma unroll
                for (int nbp = 0; nbp < 4; nbp++) {
                    int chunk = (cb + nbp * 2) ^ (row & 7);
                    u32 adr = sbase + KV_SKP + row * 256 + (chunk << 4);
                    u32 bh0[2], bh1[2], bl0[2], bl1[2];
                    ldsm_x4t(bh0[0], bh0[1], bh1[0], bh1[1], adr);
                    ldsm_x4t(bl0[0], bl0[1], bl1[0], bl1[1], adr + 16384);
                    #pragma unroll
                    for (int mb = 0; mb < 2; mb++) {
                        mma_bf16(c[mb][2 * nbp], avh[mb], bh0);
                        mma_bf16(c[mb][2 * nbp], avl[mb], bh0);
                        mma_bf16(c[mb][2 * nbp], avh[mb], bl0);
                        mma_bf16(c[mb][2 * nbp + 1], avh[mb], bh1);
                        mma_bf16(c[mb][2 * nbp + 1], avl[mb], bh1);
                        mma_bf16(c[mb][2 * nbp + 1], avh[mb], bl1);
                    }
                }
            }
        }
        __syncthreads();
    }

    float* outp = g_KVpart[split];
    #pragma unroll
    for (int mb = 0; mb < 2; mb++)
        #pragma unroll
        for (int nb = 0; nb < 8; nb++) {
            int dv = dv0 + mb * 16 + gid;
            int m = m0blk + m0w + nb * 8 + 2 * tig;
            *(float2*)&outp[(size_t)(b * DVV + dv) * MM + m] =
                make_float2(c[mb][nb][0], c[mb][nb][1]);
            *(float2*)&outp[(size_t)(b * DVV + dv + 8) * MM + m] =
                make_float2(c[mb][nb][2], c[mb][nb][3]);
        }

    // ksum: sKs [16 ng][128 m] f32 (overlays sV)
    float* sKs = (float*)dyn;
    __syncthreads();
    #pragma unroll
    for (int i = 0; i < 8; i++) sKs[ng * 128 + mg2 * 8 + i] = ksloc[i];
    __syncthreads();
    if (tid < 128) {
        float s = 0.f;
        #pragma unroll
        for (int r = 0; r < 16; r++) s += sKs[r * 128 + tid];
        g_KsumPart[split][b * MM + m0blk + tid] = s;
    }
}

__global__ void reduce_kernel() {
    int i = blockIdx.x * 256 + threadIdx.x;
    if (i < BB * DVV * MM) {
        float s = 0.f;
        #pragma unroll
        for (int p = 0; p < NSPLIT; p++) s += g_KVpart[p][i];
        int dv = (i >> 8) & 127, bb = i >> 15;
        s += g_Cvec[bb * DVV + dv];
        __nv_bfloat16 h = __float2bfloat16(s);
        g_KVT_hi[i] = h;
        g_KVT_lo[i] = __float2bfloat16(s - __bfloat162float(h));
    }
    int j = i - BB * DVV * MM;
    if (j >= 0 && j < BB * MM) {
        float s = 0.f;
        #pragma unroll
        for (int p = 0; p < NSPLIT; p++) s += g_KsumPart[p][j];
        g_Ksum[j] = s + g_SmaskEps[j >> 8];
    }
}

// ---------------------------------------------------------------------------
// out_mma: unchanged from R8.
// ---------------------------------------------------------------------------
#define O_SA 0
#define O_SA_LO 16384
#define O_SB 32768
#define O_SB_LO 49152
#define O_SMEM 65536

__global__ void __launch_bounds__(256, 2)
out_mma(float* __restrict__ out) {
    extern __shared__ __align__(16) char dyn[];
    const int tid = threadIdx.x;
    const int lane = tid & 31;
    const int w = tid >> 5;
    const int b = blockIdx.y;
    const int n0 = blockIdx.x * 128;
    const u32 sbase = smem_u32(dyn);

    const int tok0 = (w & 3) * 32;
    const int dv0 = (w >> 2) * 64;
    const int gid = lane >> 2, tig = lane & 3;

    float c[2][8][4];
    #pragma unroll
    for (int mb = 0; mb < 2; mb++)
        #pragma unroll
        for (int nb = 0; nb < 8; nb++)
            #pragma unroll
            for (int q = 0; q < 4; q++) c[mb][nb][q] = 0.f;

    const int rowA0 = tok0 + ((lane >> 3) & 1) * 8 + (lane & 7);
    const int kselA = (lane >> 4) & 1;
    const int rowB0 = dv0 + ((lane >> 4) & 1) * 8 + (lane & 7);
    const int kselB = (lane >> 3) & 1;

    for (int kc = 0; kc < 4; kc++) {
        const int mbase = kc * 64;
        {
            int row = tid >> 1, hf = tid & 1;
            const uint4* ah = (const uint4*)(g_Qp_hi + ((size_t)(b * NN + n0 + row)) * MM + mbase + hf * 32);
            const uint4* al = (const uint4*)(g_Qp_lo + ((size_t)(b * NN + n0 + row)) * MM + mbase + hf * 32);
            const uint4* kh = (const uint4*)(g_KVT_hi + (size_t)(b * DVV + row) * MM + mbase + hf * 32);
            const uint4* kl = (const uint4*)(g_KVT_lo + (size_t)(b * DVV + row) * MM + mbase + hf * 32);
            #pragma unroll
            for (int q = 0; q < 4; q++) {
                int chunk = (hf * 4 + q) ^ (row & 7);
                *(uint4*)(dyn + O_SA + row * 128 + (chunk << 4)) = ah[q];
                *(uint4*)(dyn + O_SA_LO + row * 128 + (chunk << 4)) = al[q];
                *(uint4*)(dyn + O_SB + row * 128 + (chunk << 4)) = kh[q];
                *(uint4*)(dyn + O_SB_LO + row * 128 + (chunk << 4)) = kl[q];
            }
        }
        __syncthreads();
        #pragma unroll
        for (int ks = 0; ks < 4; ks++) {
            int kcc = ks * 2;
            u32 ah[2][4], al[2][4];
            #pragma unroll
            for (int mb = 0; mb < 2; mb++) {
                int row = rowA0 + mb * 16;
                u32 adr = sbase + O_SA + row * 128 + (((kcc + kselA) ^ (row & 7)) << 4);
                ldsm_x4(ah[mb][0], ah[mb][1], ah[mb][2], ah[mb][3], adr);
                ldsm_x4(al[mb][0], al[mb][1], al[mb][2], al[mb][3], adr + 16384);
            }
            #pragma unroll
            for (int nbp = 0; nbp < 4; nbp++) {
                int row = rowB0 + nbp * 16;
                u32 adr = sbase + O_SB + row * 128 + (((kcc + kselB) ^ (row & 7)) << 4);
                u32 bh0[2], bh1[2], bl0[2], bl1[2];
                ldsm_x4(bh0[0], bh0[1], bh1[0], bh1[1], adr);
                ldsm_x4(bl0[0], bl0[1], bl1[0], bl1[1], adr + 16384);
                #pragma unroll
                for (int mb = 0; mb < 2; mb++) {
                    mma_bf16(c[mb][2 * nbp], ah[mb], bh0);
                    mma_bf16(c[mb][2 * nbp], al[mb], bh0);
                    mma_bf16(c[mb][2 * nbp], ah[mb], bl0);
                    mma_bf16(c[mb][2 * nbp + 1], ah[mb], bh1);
                    mma_bf16(c[mb][2 * nbp + 1], al[mb], bh1);
                    mma_bf16(c[mb][2 * nbp + 1], ah[mb], bl1);
                }
            }
        }
        __syncthreads();
    }

    #pragma unroll
    for (int mb = 0; mb < 2; mb++) {
        int t0 = tok0 + mb * 16 + gid;
        float r0 = g_rinv[b * NN + n0 + t0];
        float r1 = g_rinv[b * NN + n0 + t0 + 8];
        float* d0 = out + ((size_t)(b * NN + n0 + t0)) * DVV;
        float* d1 = d0 + (size_t)8 * DVV;
        #pragma unroll
        for (int nb = 0; nb < 8; nb++) {
            int dv = dv0 + nb * 8 + 2 * tig;
            *(float2*)(d0 + dv) = make_float2(c[mb][nb][0] * r0, c[mb][nb][1] * r0);
            *(float2*)(d1 + dv) = make_float2(c[mb][nb][2] * r1, c[mb][nb][3] * r1);
        }
    }
}

// ---------------------------------------------------------------------------
extern "C" void kernel_launch(void* const* d_in, const int* in_sizes, int n_in,
                              void* d_out, int out_size) {
    const float* Q     = (const float*)d_in[0];
    const float* K     = (const float*)d_in[1];
    const float* V     = (const float*)d_in[2];
    const float* amask = (const float*)d_in[3];
    const float* omega = (const float*)d_in[4];
    float* out = (float*)d_out;

    cudaFuncSetAttribute(kproj_mma, cudaFuncAttributeMaxDynamicSharedMemorySize, P_SMEM);
    cudaFuncSetAttribute(qproj_mma, cudaFuncAttributeMaxDynamicSharedMemorySize, P_SMEM);
    cudaFuncSetAttribute(kv_mma,    cudaFuncAttributeMaxDynamicSharedMemorySize, KV_SMEM);
    cudaFuncSetAttribute(out_mma,   cudaFuncAttributeMaxDynamicSharedMemorySize, O_SMEM);

    init_kernel<<<1, 32>>>();
    prep_omega<<<64, 256>>>(omega);
    vsum_kernel<<<dim3(16, BB), 256>>>(V, amask);
    fold_kernel<<<4, 256>>>();
    kproj_mma<<<dim3(NN / 64, BB), 256, P_SMEM>>>(K);
    kv_mma<<<dim3(NSPLIT, MM / 128, BB), 256, KV_SMEM>>>(V, amask);
    reduce_kernel<<<(BB * DVV * MM + BB * MM + 255) / 256, 256>>>();
    qproj_mma<<<dim3(NN / 64, BB), 256, P_SMEM>>>(Q, amask);
    out_mma<<<dim3(NN / 128, BB), 256, O_SMEM>>>(out);
}

// round 10
// speedup vs baseline: 1.4579x; 1.4579x over previous
#include <cuda_runtime.h>
#include <cuda_bf16.h>
#include <math.h>

#define BB 8
#define NN 8192
#define DD 128
#define DVV 128
#define MM 256
#define NSPLIT 16

#define SCALE_U 0.29730177875068026f   // 128^-0.25
#define H_SCALE 0.04419417382415922f   // 1/(2*sqrt(128))
#define INV_SQRT_M 0.0625f             // 1/sqrt(256)
#define EPSC (1e-4f * INV_SQRT_M)

typedef unsigned long long ull;
typedef unsigned int u32;

// ---------------------------------------------------------------------------
// Device scratch.  g_Qp_* double as Kp' (K pass) then Qp (Q pass) — the
// launches are stream-serial so the reuse is safe.
// ---------------------------------------------------------------------------
__device__ float g_lmax[BB * NN];                 // per-token max_m U
__device__ float g_bmax[BB];
__device__ float g_KVpart[NSPLIT][BB * DVV * MM]; // KV^T partials [b][dv][m]
__device__ float g_KsumPart[NSPLIT][BB * MM];
__device__ float g_Ksum[BB * MM];
__device__ float g_rinv[BB * NN];
__device__ float g_CvecPart[16][BB * DVV];
__device__ float g_SmaskPart[16][BB];
__device__ float g_Cvec[BB * DVV];
__device__ float g_SmaskEps[BB];
// omega pre-packed as mma B-fragments: [kstep(8)][nb(32)][reg(2)][lane(32)]
__device__ u32 g_wfrag_hi[8 * 32 * 2 * 32];
__device__ u32 g_wfrag_lo[8 * 32 * 2 * 32];
__device__ __nv_bfloat16 g_Qp_hi[(size_t)BB * NN * MM];   // [b][n][m]
__device__ __nv_bfloat16 g_Qp_lo[(size_t)BB * NN * MM];
__device__ __nv_bfloat16 g_KVT_hi[BB * DVV * MM];         // [b][dv][m]
__device__ __nv_bfloat16 g_KVT_lo[BB * DVV * MM];

// ---------------------------------------------------------------------------
// PTX helpers (sm_80-level)
// ---------------------------------------------------------------------------
__device__ __forceinline__ u32 smem_u32(const void* p) {
    u32 a;
    asm("{ .reg .u64 t; cvta.to.shared.u64 t, %1; cvt.u32.u64 %0, t; }" : "=r"(a) : "l"(p));
    return a;
}
__device__ __forceinline__ void ldsm_x4(u32& r0, u32& r1, u32& r2, u32& r3, u32 addr) {
    asm volatile("ldmatrix.sync.aligned.m8n8.x4.shared.b16 {%0,%1,%2,%3}, [%4];"
                 : "=r"(r0), "=r"(r1), "=r"(r2), "=r"(r3) : "r"(addr));
}
__device__ __forceinline__ void ldsm_x4t(u32& r0, u32& r1, u32& r2, u32& r3, u32 addr) {
    asm volatile("ldmatrix.sync.aligned.m8n8.x4.trans.shared.b16 {%0,%1,%2,%3}, [%4];"
                 : "=r"(r0), "=r"(r1), "=r"(r2), "=r"(r3) : "r"(addr));
}
__device__ __forceinline__ void mma_bf16(float* c, const u32* a, const u32* b) {
    asm volatile("mma.sync.aligned.m16n8k16.row.col.f32.bf16.bf16.f32 "
                 "{%0,%1,%2,%3}, {%4,%5,%6,%7}, {%8,%9}, {%0,%1,%2,%3};"
                 : "+f"(c[0]), "+f"(c[1]), "+f"(c[2]), "+f"(c[3])
                 : "r"(a[0]), "r"(a[1]), "r"(a[2]), "r"(a[3]), "r"(b[0]), "r"(b[1]));
}
__device__ __forceinline__ u32 bpack(float lo, float hi) {
    u32 r;
    asm("cvt.rn.bf16x2.f32 %0, %1, %2;" : "=r"(r) : "f"(hi), "f"(lo));
    return r;
}
__device__ __forceinline__ void cvt8(const float* x, uint4& h4, uint4& l4) {
    u32 h[4], l[4];
    #pragma unroll
    for (int i = 0; i < 4; i++) {
        u32 p = bpack(x[2 * i], x[2 * i + 1]);
        h[i] = p;
        float r0 = x[2 * i]     - __uint_as_float(p << 16);
        float r1 = x[2 * i + 1] - __uint_as_float(p & 0xFFFF0000u);
        l[i] = bpack(r0, r1);
    }
    h4 = make_uint4(h[0], h[1], h[2], h[3]);
    l4 = make_uint4(l[0], l[1], l[2], l[3]);
}

__device__ __forceinline__ float fexp(float x) {
    x = fmaxf(x, -87.0f);
    float t = x * 1.4426950408889634f;
    float r = rintf(t);
    float f = t - r;
    float z = f * 0.6931471805599453f;
    float p = 1.0f + z * (1.0f + z * (0.5f + z * (0.16666667f +
              z * (0.041666667f + z * (0.0083333333f + z * 0.0013888889f)))));
    return __int_as_float(((int)r + 127) << 23) * p;
}
__device__ __forceinline__ float warpMax(float v) {
    #pragma unroll
    for (int o = 16; o; o >>= 1) v = fmaxf(v, __shfl_xor_sync(0xffffffffu, v, o));
    return v;
}
__device__ __forceinline__ void atomicMaxFloat(float* addr, float val) {
    int old = __float_as_int(*addr);
    while (__int_as_float(old) < val) {
        int prev = atomicCAS((int*)addr, old, __float_as_int(val));
        if (prev == old) break;
        old = prev;
    }
}

__global__ void init_kernel() {
    if (threadIdx.x < BB) g_bmax[threadIdx.x] = -INFINITY;
}

__global__ void prep_omega(const float* __restrict__ omega) {
    int id = blockIdx.x * 256 + threadIdx.x;   // 16384 total
    int m = id >> 6;
    int dp = id & 63;
    int d = dp * 2;
    float w0 = omega[(size_t)d * MM + m] * SCALE_U;
    float w1 = omega[(size_t)(d + 1) * MM + m] * SCALE_U;
    u32 hp = bpack(w0, w1);
    float r0 = w0 - __uint_as_float(hp << 16);
    float r1 = w1 - __uint_as_float(hp & 0xFFFF0000u);
    u32 lp = bpack(r0, r1);
    int idx = (((d >> 4) * 32 + (m >> 3)) * 2 + ((d >> 3) & 1)) * 32
            + (m & 7) * 4 + ((d & 7) >> 1);
    g_wfrag_hi[idx] = hp;
    g_wfrag_lo[idx] = lp;
}

// ---------------------------------------------------------------------------
// vsum: deterministic partials of Cvec[b][dv]=sum_n mask*V and Smask[b].
// ---------------------------------------------------------------------------
__global__ void __launch_bounds__(256)
vsum_kernel(const float* __restrict__ V, const float* __restrict__ mask) {
    __shared__ float sred[256];
    const int part = blockIdx.x;   // 16
    const int b = blockIdx.y;
    const int tid = threadIdx.x;
    const int dv = tid & 127, g = tid >> 7;

    float acc = 0.f;
    const int nb = part * 512 + g * 256;
    #pragma unroll 4
    for (int r = 0; r < 256; r++) {
        int n = nb + r;
        acc = fmaf(mask[b * NN + n], V[((size_t)(b * NN + n)) * DVV + dv], acc);
    }
    sred[tid] = acc;
    __syncthreads();
    if (tid < 128) g_CvecPart[part][b * DVV + tid] = sred[tid] + sred[tid + 128];
    __syncthreads();
    {
        int n0m = part * 512 + tid * 2;
        sred[tid] = mask[b * NN + n0m] + mask[b * NN + n0m + 1];
    }
    __syncthreads();
    for (int s = 128; s > 0; s >>= 1) {
        if (tid < s) sred[tid] += sred[tid + s];
        __syncthreads();
    }
    if (tid == 0) g_SmaskPart[part][b] = sred[0];
}

__global__ void fold_kernel() {
    int i = blockIdx.x * 256 + threadIdx.x;
    if (i < BB * DVV) {
        float s = 0.f;
        #pragma unroll
        for (int p = 0; p < 16; p++) s += g_CvecPart[p][i];
        g_Cvec[i] = s * EPSC;
    }
    if (i < BB) {
        float s = 0.f;
        #pragma unroll
        for (int p = 0; p < 16; p++) s += g_SmaskPart[p][i];
        g_SmaskEps[i] = s * EPSC;
    }
}

// ---------------------------------------------------------------------------
// Projections: CTA = 64 tok x 256 m, K=128. Warp tile 32 tok x 64 m.
// B (omega) streamed per-nb from gmem frags. smem: sA hi/lo; sU overlays.
// ---------------------------------------------------------------------------
#define P_SA 0
#define P_SA_LO 16384
#define P_SMEM 67584
#define SU_STRIDE 264

__device__ __forceinline__ void proj_mma_main(
    const float* __restrict__ Xb, char* dyn, u32 sb,
    float c[2][8][4], float* sHred)
{
    const int tid = threadIdx.x;
    const int lane = tid & 31;
    const int w = tid >> 5;

    {   // A: 64 tok x 128 d, f32 -> bf16 hi/lo, swizzled; h partials
        int row = tid >> 2, seg = (tid & 3) * 32;
        const float* src = Xb + (size_t)row * DD + seg;
        float hs = 0.f;
        #pragma unroll
        for (int q = 0; q < 4; q++) {
            float x[8];
            float4 v0 = *(const float4*)(src + q * 8);
            float4 v1 = *(const float4*)(src + q * 8 + 4);
            x[0] = v0.x; x[1] = v0.y; x[2] = v0.z; x[3] = v0.w;
            x[4] = v1.x; x[5] = v1.y; x[6] = v1.z; x[7] = v1.w;
            #pragma unroll
            for (int e = 0; e < 8; e++) hs = fmaf(x[e], x[e], hs);
            uint4 h4, l4;
            cvt8(x, h4, l4);
            int chunk = ((seg >> 3) + q) ^ (row & 7);
            *(uint4*)(dyn + P_SA + row * 256 + (chunk << 4)) = h4;
            *(uint4*)(dyn + P_SA_LO + row * 256 + (chunk << 4)) = l4;
        }
        sHred[tid] = hs;
    }
    __syncthreads();

    const int tok0 = (w & 1) * 32;
    const int m0w = (w >> 1) * 64;
    const int rowA0 = tok0 + ((lane >> 3) & 1) * 8 + (lane & 7);
    const int kselA = (lane >> 4) & 1;
    const int nbBase = (m0w >> 3);

    #pragma unroll
    for (int ks = 0; ks < 8; ks++) {
        int kc = ks * 2;
        u32 ah[2][4], al[2][4];
        #pragma unroll
        for (int mb = 0; mb < 2; mb++) {
            int row = rowA0 + mb * 16;
            u32 adr = sb + P_SA + row * 256 + (((kc + kselA) ^ (row & 7)) << 4);
            ldsm_x4(ah[mb][0], ah[mb][1], ah[mb][2], ah[mb][3], adr);
            ldsm_x4(al[mb][0], al[mb][1], al[mb][2], al[mb][3], adr + 16384);
        }
        #pragma unroll
        for (int nb = 0; nb < 8; nb++) {
            int base = ((ks * 32 + nbBase + nb) * 2) * 32 + lane;
            u32 bh[2], bl[2];
            bh[0] = g_wfrag_hi[base];
            bh[1] = g_wfrag_hi[base + 32];
            bl[0] = g_wfrag_lo[base];
            bl[1] = g_wfrag_lo[base + 32];
            #pragma unroll
            for (int mb = 0; mb < 2; mb++) {
                mma_bf16(c[mb][nb], ah[mb], bh);
                mma_bf16(c[mb][nb], al[mb], bh);
                mma_bf16(c[mb][nb], ah[mb], bl);
            }
        }
    }
    __syncthreads();
}

__device__ __forceinline__ void store_sU(float c[2][8][4], float* sU, int tid) {
    const int lane = tid & 31, w = tid >> 5;
    const int tok0 = (w & 1) * 32, m0w = (w >> 1) * 64;
    const int gid = lane >> 2, tig = lane & 3;
    #pragma unroll
    for (int mb = 0; mb < 2; mb++)
        #pragma unroll
        for (int nb = 0; nb < 8; nb++) {
            int r0 = tok0 + mb * 16 + gid;
            int m = m0w + nb * 8 + 2 * tig;
            *(float2*)&sU[r0 * SU_STRIDE + m] = make_float2(c[mb][nb][0], c[mb][nb][1]);
            *(float2*)&sU[(r0 + 8) * SU_STRIDE + m] = make_float2(c[mb][nb][2], c[mb][nb][3]);
        }
}

// kproj: writes Kp' = exp(U - h - lmax) as bf16 hi/lo into g_Qp_*, plus lmax.
__global__ void __launch_bounds__(256, 2)
kproj_mma(const float* __restrict__ Kin) {
    extern __shared__ __align__(16) char dyn[];
    __shared__ float sHred[256];
    __shared__ float wred[8];

    const int tid = threadIdx.x;
    const int b = blockIdx.y;
    const int n0 = blockIdx.x * 64;
    const u32 sbase = smem_u32(dyn);

    float c[2][8][4];
    #pragma unroll
    for (int mb = 0; mb < 2; mb++)
        #pragma unroll
        for (int nb = 0; nb < 8; nb++)
            #pragma unroll
            for (int q = 0; q < 4; q++) c[mb][nb][q] = 0.f;

    proj_mma_main(Kin + ((size_t)b * NN + n0) * DD, dyn, sbase, c, sHred);

    float* sU = (float*)dyn;
    store_sU(c, sU, tid);
    __syncthreads();

    const int tok = tid >> 2, t4 = tid & 3;
    const int seg = t4 * 64;
    const float* Urow = sU + tok * SU_STRIDE + seg;

    float mx = -INFINITY;
    #pragma unroll
    for (int i = 0; i < 64; i++) mx = fmaxf(mx, Urow[i]);
    mx = fmaxf(mx, __shfl_xor_sync(0xffffffffu, mx, 1));
    mx = fmaxf(mx, __shfl_xor_sync(0xffffffffu, mx, 2));   // per-token lmax

    float h = (sHred[tok * 4] + sHred[tok * 4 + 1] + sHred[tok * 4 + 2] + sHred[tok * 4 + 3]) * H_SCALE;
    float off = h + mx;
    const size_t gbase = ((size_t)(b * NN + n0 + tok)) * MM + seg;

    #pragma unroll
    for (int q = 0; q < 8; q++) {
        u32 h4[4], l4[4];
        #pragma unroll
        for (int e = 0; e < 4; e++) {
            int i = q * 8 + 2 * e;
            float q0 = fexp(Urow[i] - off);
            float q1 = fexp(Urow[i + 1] - off);
            u32 p = bpack(q0, q1);
            h4[e] = p;
            float r0 = q0 - __uint_as_float(p << 16);
            float r1 = q1 - __uint_as_float(p & 0xFFFF0000u);
            l4[e] = bpack(r0, r1);
        }
        *(uint4*)&g_Qp_hi[gbase + q * 8] = make_uint4(h4[0], h4[1], h4[2], h4[3]);
        *(uint4*)&g_Qp_lo[gbase + q * 8] = make_uint4(l4[0], l4[1], l4[2], l4[3]);
    }
    if (t4 == 0) g_lmax[b * NN + n0 + tok] = mx;

    float bm = warpMax(mx);
    if ((tid & 31) == 0) wred[tid >> 5] = bm;
    __syncthreads();
    if (tid == 0) {
        float m = wred[0];
        #pragma unroll
        for (int q = 1; q < 8; q++) m = fmaxf(m, wred[q]);
        atomicMaxFloat(&g_bmax[b], m);
    }
}

__global__ void __launch_bounds__(256, 2)
qproj_mma(const float* __restrict__ Qin, const float* __restrict__ mask) {
    extern __shared__ __align__(16) char dyn[];
    __shared__ float sHred[256];
    __shared__ float sKsum[MM];

    const int tid = threadIdx.x;
    const int b = blockIdx.y;
    const int n0 = blockIdx.x * 64;
    const u32 sbase = smem_u32(dyn);

    if (tid < MM) sKsum[tid] = g_Ksum[b * MM + tid];

    float c[2][8][4];
    #pragma unroll
    for (int mb = 0; mb < 2; mb++)
        #pragma unroll
        for (int nb = 0; nb < 8; nb++)
            #pragma unroll
            for (int q = 0; q < 4; q++) c[mb][nb][q] = 0.f;

    proj_mma_main(Qin + ((size_t)b * NN + n0) * DD, dyn, sbase, c, sHred);

    float* sU = (float*)dyn;
    store_sU(c, sU, tid);
    __syncthreads();

    const int tok = tid >> 2, t4 = tid & 3;
    const int seg = t4 * 64;
    const float* Urow = sU + tok * SU_STRIDE + seg;

    float mx = -INFINITY;
    #pragma unroll
    for (int i = 0; i < 64; i++) mx = fmaxf(mx, Urow[i]);
    mx = fmaxf(mx, __shfl_xor_sync(0xffffffffu, mx, 1));
    mx = fmaxf(mx, __shfl_xor_sync(0xffffffffu, mx, 2));

    float h = (sHred[tok * 4] + sHred[tok * 4 + 1] + sHred[tok * 4 + 2] + sHred[tok * 4 + 3]) * H_SCALE;
    float s = INV_SQRT_M * mask[b * NN + n0 + tok];
    const size_t gbase = ((size_t)(b * NN + n0 + tok)) * MM + seg;

    float np = 0.f;
    #pragma unroll
    for (int q = 0; q < 8; q++) {
        u32 h4[4], l4[4];
        #pragma unroll
        for (int e = 0; e < 4; e++) {
            int i = q * 8 + 2 * e;
            float q0 = (fexp(Urow[i] - h - mx) + 1e-4f) * s;
            float q1 = (fexp(Urow[i + 1] - h - mx) + 1e-4f) * s;
            np = fmaf(q0, sKsum[seg + i], np);
            np = fmaf(q1, sKsum[seg + i + 1], np);
            u32 p = bpack(q0, q1);
            h4[e] = p;
            float r0 = q0 - __uint_as_float(p << 16);
            float r1 = q1 - __uint_as_float(p & 0xFFFF0000u);
            l4[e] = bpack(r0, r1);
        }
        *(uint4*)&g_Qp_hi[gbase + q * 8] = make_uint4(h4[0], h4[1], h4[2], h4[3]);
        *(uint4*)&g_Qp_lo[gbase + q * 8] = make_uint4(l4[0], l4[1], l4[2], l4[3]);
    }
    np += __shfl_xor_sync(0xffffffffu, np, 1);
    np += __shfl_xor_sync(0xffffffffu, np, 2);
    if (t4 == 0) g_rinv[b * NN + n0 + tok] = 1.0f / (np + 1e-8f);
}

// ---------------------------------------------------------------------------
// kv_mma: KVT[dv][m] = sum_n a(n)*V[n][dv]*Kp'[n][m]. CTA 128 dv x 128 m.
// Kp' pre-split bf16 from kproj: plain swizzled copy. a(n)=exp(lmax-mx)*s(n)
// folded into the V conversion. Ksum accumulated from unpacked Kp' frags.
// ---------------------------------------------------------------------------
#define KV_SV 0
#define KV_SV_LO 16384
#define KV_SKP 32768
#define KV_SKP_LO 49152
#define KV_SMEM 65536

__global__ void __launch_bounds__(256, 2)
kv_mma(const float* __restrict__ V, const float* __restrict__ mask) {
    extern __shared__ __align__(16) char dyn[];

    const int tid = threadIdx.x;
    const int lane = tid & 31;
    const int w = tid >> 5;
    const int b = blockIdx.z;
    const int m0blk = blockIdx.y * 128;
    const int split = blockIdx.x;
    const float mx = g_bmax[b];
    const u32 sbase = smem_u32(dyn);

    const int dv0 = (w & 3) * 32;
    const int m0w = (w >> 2) * 64;
    const int gid = lane >> 2, tig = lane & 3;

    float c[2][8][4];
    #pragma unroll
    for (int mb = 0; mb < 2; mb++)
        #pragma unroll
        for (int nb = 0; nb < 8; nb++)
            #pragma unroll
            for (int q = 0; q < 4; q++) c[mb][nb][q] = 0.f;
    float ksloc[8];
    #pragma unroll
    for (int i = 0; i < 8; i++) ksloc[i] = 0.f;

    const int mg2 = tid & 15;          // Kp loader: 1 uint4 chunk (8 m)
    const int ng = tid >> 4;           // Kp loader: 4 rows each

    const int nbase = split * (NN / NSPLIT);
    for (int ch = 0; ch < (NN / NSPLIT) / 64; ch++) {
        const int n0c = nbase + ch * 64;
        {   // V: [64 n][128 dv] -> bf16 hi/lo swizzled, scaled by a(n)
            int row = tid >> 2, seg = (tid & 3) * 32;
            int bn = b * NN + n0c + row;
            float av = fexp(g_lmax[bn] - mx) * (INV_SQRT_M * mask[bn]);
            const float* src = V + ((size_t)bn) * DVV + seg;
            #pragma unroll
            for (int q = 0; q < 4; q++) {
                float x[8];
                float4 v0 = *(const float4*)(src + q * 8);
                float4 v1 = *(const float4*)(src + q * 8 + 4);
                x[0] = v0.x * av; x[1] = v0.y * av; x[2] = v0.z * av; x[3] = v0.w * av;
                x[4] = v1.x * av; x[5] = v1.y * av; x[6] = v1.z * av; x[7] = v1.w * av;
                uint4 h4, l4;
                cvt8(x, h4, l4);
                int chunk = ((seg >> 3) + q) ^ (row & 7);
                *(uint4*)(dyn + KV_SV + row * 256 + (chunk << 4)) = h4;
                *(uint4*)(dyn + KV_SV_LO + row * 256 + (chunk << 4)) = l4;
            }
        }
        {   // Kp': plain copy of pre-split bf16 + ksum accumulation
            #pragma unroll
            for (int r = 0; r < 4; r++) {
                int n = ng * 4 + r;
                int bn = b * NN + n0c + n;
                const uint4 hi4 = *(const uint4*)&g_Qp_hi[((size_t)bn) * MM + m0blk + mg2 * 8];
                const uint4 lo4 = *(const uint4*)&g_Qp_lo[((size_t)bn) * MM + m0blk + mg2 * 8];
                int chunk = mg2 ^ (n & 7);
                *(uint4*)(dyn + KV_SKP + n * 256 + (chunk << 4)) = hi4;
                *(uint4*)(dyn + KV_SKP_LO + n * 256 + (chunk << 4)) = lo4;
                float a = fexp(g_lmax[bn] - mx) * (INV_SQRT_M * mask[bn]);
                u32 hv[4] = {hi4.x, hi4.y, hi4.z, hi4.w};
                u32 lv[4] = {lo4.x, lo4.y, lo4.z, lo4.w};
                #pragma unroll
                for (int j = 0; j < 4; j++) {
                    float v0 = __uint_as_float(hv[j] << 16) + __uint_as_float(lv[j] << 16);
                    float v1 = __uint_as_float(hv[j] & 0xFFFF0000u) + __uint_as_float(lv[j] & 0xFFFF0000u);
                    ksloc[2 * j]     = fmaf(a, v0, ksloc[2 * j]);
                    ksloc[2 * j + 1] = fmaf(a, v1, ksloc[2 * j + 1]);
                }
            }
        }
        __syncthreads();

        #pragma unroll
        for (int ks = 0; ks < 4; ks++) {
            const int kk = ks * 16;
            u32 avh[2][4], avl[2][4];
            {
                int row = kk + ((lane >> 4) & 1) * 8 + (lane & 7);
                int cb = (dv0 >> 3) + ((lane >> 3) & 1);
                #pragma unroll
                for (int mb = 0; mb < 2; mb++) {
                    int chunk = (cb + mb * 2) ^ (row & 7);
                    u32 adr = sbase + KV_SV + row * 256 + (chunk << 4);
                    ldsm_x4t(avh[mb][0], avh[mb][1], avh[mb][2], avh[mb][3], adr);
                    ldsm_x4t(avl[mb][0], avl[mb][1], avl[mb][2], avl[mb][3], adr + 16384);
                }
            }
            {
                int row = kk + ((lane >> 3) & 1) * 8 + (lane & 7);
                int cb = (m0w >> 3) + ((lane >> 4) & 1);
                #pragma unroll
                for (int nbp = 0; nbp < 4; nbp++) {
                    int chunk = (cb + nbp * 2) ^ (row & 7);
                    u32 adr = sbase + KV_SKP + row * 256 + (chunk << 4);
                    u32 bh0[2], bh1[2], bl0[2], bl1[2];
                    ldsm_x4t(bh0[0], bh0[1], bh1[0], bh1[1], adr);
                    ldsm_x4t(bl0[0], bl0[1], bl1[0], bl1[1], adr + 16384);
                    #pragma unroll
                    for (int mb = 0; mb < 2; mb++) {
                        mma_bf16(c[mb][2 * nbp], avh[mb], bh0);
                        mma_bf16(c[mb][2 * nbp], avl[mb], bh0);
                        mma_bf16(c[mb][2 * nbp], avh[mb], bl0);
                        mma_bf16(c[mb][2 * nbp + 1], avh[mb], bh1);
                        mma_bf16(c[mb][2 * nbp + 1], avl[mb], bh1);
                        mma_bf16(c[mb][2 * nbp + 1], avh[mb], bl1);
                    }
                }
            }
        }
        __syncthreads();
    }

    float* outp = g_KVpart[split];
    #pragma unroll
    for (int mb = 0; mb < 2; mb++)
        #pragma unroll
        for (int nb = 0; nb < 8; nb++) {
            int dv = dv0 + mb * 16 + gid;
            int m = m0blk + m0w + nb * 8 + 2 * tig;
            *(float2*)&outp[(size_t)(b * DVV + dv) * MM + m] =
                make_float2(c[mb][nb][0], c[mb][nb][1]);
            *(float2*)&outp[(size_t)(b * DVV + dv + 8) * MM + m] =
                make_float2(c[mb][nb][2], c[mb][nb][3]);
        }

    // ksum: sKs [16 ng][128 m] f32 (overlays sV)
    float* sKs = (float*)dyn;
    __syncthreads();
    #pragma unroll
    for (int i = 0; i < 8; i++) sKs[ng * 128 + mg2 * 8 + i] = ksloc[i];
    __syncthreads();
    if (tid < 128) {
        float s = 0.f;
        #pragma unroll
        for (int r = 0; r < 16; r++) s += sKs[r * 128 + tid];
        g_KsumPart[split][b * MM + m0blk + tid] = s;
    }
}

__global__ void reduce_kernel() {
    int i = blockIdx.x * 256 + threadIdx.x;
    if (i < BB * DVV * MM) {
        float s = 0.f;
        #pragma unroll
        for (int p = 0; p < NSPLIT; p++) s += g_KVpart[p][i];
        int dv = (i >> 8) & 127, bb = i >> 15;
        s += g_Cvec[bb * DVV + dv];
        __nv_bfloat16 h = __float2bfloat16(s);
        g_KVT_hi[i] = h;
        g_KVT_lo[i] = __float2bfloat16(s - __bfloat162float(h));
    }
    int j = i - BB * DVV * MM;
    if (j >= 0 && j < BB * MM) {
        float s = 0.f;
        #pragma unroll
        for (int p = 0; p < NSPLIT; p++) s += g_KsumPart[p][j];
        g_Ksum[j] = s + g_SmaskEps[j >> 8];
    }
}

// ---------------------------------------------------------------------------
// out_mma: unchanged from R8.
// ---------------------------------------------------------------------------
#define O_SA 0
#define O_SA_LO 16384
#define O_SB 32768
#define O_SB_LO 49152
#define O_SMEM 65536

__global__ void __launch_bounds__(256, 2)
out_mma(float* __restrict__ out) {
    extern __shared__ __align__(16) char dyn[];
    const int tid = threadIdx.x;
    const int lane = tid & 31;
    const int w = tid >> 5;
    const int b = blockIdx.y;
    const int n0 = blockIdx.x * 128;
    const u32 sbase = smem_u32(dyn);

    const int tok0 = (w & 3) * 32;
    const int dv0 = (w >> 2) * 64;
    const int gid = lane >> 2, tig = lane & 3;

    float c[2][8][4];
    #pragma unroll
    for (int mb = 0; mb < 2; mb++)
        #pragma unroll
        for (int nb = 0; nb < 8; nb++)
            #pragma unroll
            for (int q = 0; q < 4; q++) c[mb][nb][q] = 0.f;

    const int rowA0 = tok0 + ((lane >> 3) & 1) * 8 + (lane & 7);
    const int kselA = (lane >> 4) & 1;
    const int rowB0 = dv0 + ((lane >> 4) & 1) * 8 + (lane & 7);
    const int kselB = (lane >> 3) & 1;

    for (int kc = 0; kc < 4; kc++) {
        const int mbase = kc * 64;
        {
            int row = tid >> 1, hf = tid & 1;
            const uint4* ah = (const uint4*)(g_Qp_hi + ((size_t)(b * NN + n0 + row)) * MM + mbase + hf * 32);
            const uint4* al = (const uint4*)(g_Qp_lo + ((size_t)(b * NN + n0 + row)) * MM + mbase + hf * 32);
            const uint4* kh = (const uint4*)(g_KVT_hi + (size_t)(b * DVV + row) * MM + mbase + hf * 32);
            const uint4* kl = (const uint4*)(g_KVT_lo + (size_t)(b * DVV + row) * MM + mbase + hf * 32);
            #pragma unroll
            for (int q = 0; q < 4; q++) {
                int chunk = (hf * 4 + q) ^ (row & 7);
                *(uint4*)(dyn + O_SA + row * 128 + (chunk << 4)) = ah[q];
                *(uint4*)(dyn + O_SA_LO + row * 128 + (chunk << 4)) = al[q];
                *(uint4*)(dyn + O_SB + row * 128 + (chunk << 4)) = kh[q];
                *(uint4*)(dyn + O_SB_LO + row * 128 + (chunk << 4)) = kl[q];
            }
        }
        __syncthreads();
        #pragma unroll
        for (int ks = 0; ks < 4; ks++) {
            int kcc = ks * 2;
            u32 ah[2][4], al[2][4];
            #pragma unroll
            for (int mb = 0; mb < 2; mb++) {
                int row = rowA0 + mb * 16;
                u32 adr = sbase + O_SA + row * 128 + (((kcc + kselA) ^ (row & 7)) << 4);
                ldsm_x4(ah[mb][0], ah[mb][1], ah[mb][2], ah[mb][3], adr);
                ldsm_x4(al[mb][0], al[mb][1], al[mb][2], al[mb][3], adr + 16384);
            }
            #pragma unroll
            for (int nbp = 0; nbp < 4; nbp++) {
                int row = rowB0 + nbp * 16;
                u32 adr = sbase + O_SB + row * 128 + (((kcc + kselB) ^ (row & 7)) << 4);
                u32 bh0[2], bh1[2], bl0[2], bl1[2];
                ldsm_x4(bh0[0], bh0[1], bh1[0], bh1[1], adr);
                ldsm_x4(bl0[0], bl0[1], bl1[0], bl1[1], adr + 16384);
                #pragma unroll
                for (int mb = 0; mb < 2; mb++) {
                    mma_bf16(c[mb][2 * nbp], ah[mb], bh0);
                    mma_bf16(c[mb][2 * nbp], al[mb], bh0);
                    mma_bf16(c[mb][2 * nbp], ah[mb], bl0);
                    mma_bf16(c[mb][2 * nbp + 1], ah[mb], bh1);
                    mma_bf16(c[mb][2 * nbp + 1], al[mb], bh1);
                    mma_bf16(c[mb][2 * nbp + 1], ah[mb], bl1);
                }
            }
        }
        __syncthreads();
    }

    #pragma unroll
    for (int mb = 0; mb < 2; mb++) {
        int t0 = tok0 + mb * 16 + gid;
        float r0 = g_rinv[b * NN + n0 + t0];
        float r1 = g_rinv[b * NN + n0 + t0 + 8];
        float* d0 = out + ((size_t)(b * NN + n0 + t0)) * DVV;
        float* d1 = d0 + (size_t)8 * DVV;
        #pragma unroll
        for (int nb = 0; nb < 8; nb++) {
            int dv = dv0 + nb * 8 + 2 * tig;
            *(float2*)(d0 + dv) = make_float2(c[mb][nb][0] * r0, c[mb][nb][1] * r0);
            *(float2*)(d1 + dv) = make_float2(c[mb][nb][2] * r1, c[mb][nb][3] * r1);
        }
    }
}

// ---------------------------------------------------------------------------
extern "C" void kernel_launch(void* const* d_in, const int* in_sizes, int n_in,
                              void* d_out, int out_size) {
    const float* Q     = (const float*)d_in[0];
    const float* K     = (const float*)d_in[1];
    const float* V     = (const float*)d_in[2];
    const float* amask = (const float*)d_in[3];
    const float* omega = (const float*)d_in[4];
    float* out = (float*)d_out;

    cudaFuncSetAttribute(kproj_mma, cudaFuncAttributeMaxDynamicSharedMemorySize, P_SMEM);
    cudaFuncSetAttribute(qproj_mma, cudaFuncAttributeMaxDynamicSharedMemorySize, P_SMEM);
    cudaFuncSetAttribute(kv_mma,    cudaFuncAttributeMaxDynamicSharedMemorySize, KV_SMEM);
    cudaFuncSetAttribute(out_mma,   cudaFuncAttributeMaxDynamicSharedMemorySize, O_SMEM);

    init_kernel<<<1, 32>>>();
    prep_omega<<<64, 256>>>(omega);
    vsum_kernel<<<dim3(16, BB), 256>>>(V, amask);
    fold_kernel<<<4, 256>>>();
    kproj_mma<<<dim3(NN / 64, BB), 256, P_SMEM>>>(K);
    kv_mma<<<dim3(NSPLIT, MM / 128, BB), 256, KV_SMEM>>>(V, amask);
    reduce_kernel<<<(BB * DVV * MM + BB * MM + 255) / 256, 256>>>();
    qproj_mma<<<dim3(NN / 64, BB), 256, P_SMEM>>>(Q, amask);
    out_mma<<<dim3(NN / 128, BB), 256, O_SMEM>>>(out);
}

// round 13
// speedup vs baseline: 1.8585x; 1.2748x over previous
#include <cuda_runtime.h>
#include <cuda_bf16.h>
#include <math.h>

#define BB 8
#define NN 8192
#define DD 128
#define DVV 128
#define MM 256
#define NSPLIT 16

#define SCALE_U 0.29730177875068026f   // 128^-0.25
#define H_SCALE 0.04419417382415922f   // 1/(2*sqrt(128))
#define INV_SQRT_M 0.0625f             // 1/sqrt(256)

typedef unsigned long long ull;
typedef unsigned int u32;

// ---------------------------------------------------------------------------
// Device scratch
// ---------------------------------------------------------------------------
__device__ float g_U[(size_t)BB * NN * MM];      // raw scaled U (K pass)
__device__ float g_h[BB * NN];
__device__ float g_bmax[BB];
__device__ float g_KVpart[NSPLIT][BB * DVV * MM];   // KV^T partials [b][dv][m]
__device__ float g_KsumPart[NSPLIT][BB * MM];
__device__ float g_Ksum[BB * MM];
// omega pre-packed as mma B-fragments: [kstep(8)][nb(32)][reg(2)][lane(32)]
__device__ u32 g_wfrag_hi[8 * 32 * 2 * 32];
__device__ u32 g_wfrag_lo[8 * 32 * 2 * 32];
__device__ __nv_bfloat16 g_KVT_hi[BB * DVV * MM];         // [b][dv][m]
__device__ __nv_bfloat16 g_KVT_lo[BB * DVV * MM];

// ---------------------------------------------------------------------------
// PTX helpers (sm_80-level)
// ---------------------------------------------------------------------------
__device__ __forceinline__ u32 smem_u32(const void* p) {
    u32 a;
    asm("{ .reg .u64 t; cvta.to.shared.u64 t, %1; cvt.u32.u64 %0, t; }" : "=r"(a) : "l"(p));
    return a;
}
__device__ __forceinline__ void ldsm_x4(u32& r0, u32& r1, u32& r2, u32& r3, u32 addr) {
    asm volatile("ldmatrix.sync.aligned.m8n8.x4.shared.b16 {%0,%1,%2,%3}, [%4];"
                 : "=r"(r0), "=r"(r1), "=r"(r2), "=r"(r3) : "r"(addr));
}
__device__ __forceinline__ void ldsm_x4t(u32& r0, u32& r1, u32& r2, u32& r3, u32 addr) {
    asm volatile("ldmatrix.sync.aligned.m8n8.x4.trans.shared.b16 {%0,%1,%2,%3}, [%4];"
                 : "=r"(r0), "=r"(r1), "=r"(r2), "=r"(r3) : "r"(addr));
}
__device__ __forceinline__ void mma_bf16(float* c, const u32* a, const u32* b) {
    asm volatile("mma.sync.aligned.m16n8k16.row.col.f32.bf16.bf16.f32 "
                 "{%0,%1,%2,%3}, {%4,%5,%6,%7}, {%8,%9}, {%0,%1,%2,%3};"
                 : "+f"(c[0]), "+f"(c[1]), "+f"(c[2]), "+f"(c[3])
                 : "r"(a[0]), "r"(a[1]), "r"(a[2]), "r"(a[3]), "r"(b[0]), "r"(b[1]));
}
__device__ __forceinline__ u32 bpack(float lo, float hi) {
    u32 r;
    asm("cvt.rn.bf16x2.f32 %0, %1, %2;" : "=r"(r) : "f"(hi), "f"(lo));
    return r;
}
__device__ __forceinline__ void cvt8(const float* x, uint4& h4, uint4& l4) {
    u32 h[4], l[4];
    #pragma unroll
    for (int i = 0; i < 4; i++) {
        u32 p = bpack(x[2 * i], x[2 * i + 1]);
        h[i] = p;
        float r0 = x[2 * i]     - __uint_as_float(p << 16);
        float r1 = x[2 * i + 1] - __uint_as_float(p & 0xFFFF0000u);
        l[i] = bpack(r0, r1);
    }
    h4 = make_uint4(h[0], h[1], h[2], h[3]);
    l4 = make_uint4(l[0], l[1], l[2], l[3]);
}

__device__ __forceinline__ float fexp(float x) {
    x = fmaxf(x, -87.0f);
    float t = x * 1.4426950408889634f;
    float r = rintf(t);
    float f = t - r;
    float z = f * 0.6931471805599453f;
    float p = 1.0f + z * (1.0f + z * (0.5f + z * (0.16666667f +
              z * (0.041666667f + z * (0.0083333333f + z * 0.0013888889f)))));
    return __int_as_float(((int)r + 127) << 23) * p;
}
__device__ __forceinline__ float warpMax(float v) {
    #pragma unroll
    for (int o = 16; o; o >>= 1) v = fmaxf(v, __shfl_xor_sync(0xffffffffu, v, o));
    return v;
}
__device__ __forceinline__ void atomicMaxFloat(float* addr, float val) {
    int old = __float_as_int(*addr);
    while (__int_as_float(old) < val) {
        int prev = atomicCAS((int*)addr, old, __float_as_int(val));
        if (prev == old) break;
        old = prev;
    }
}

__global__ void init_kernel() {
    if (threadIdx.x < BB) g_bmax[threadIdx.x] = -INFINITY;
}

__global__ void prep_omega(const float* __restrict__ omega) {
    int id = blockIdx.x * 256 + threadIdx.x;   // 16384 total
    int m = id >> 6;
    int dp = id & 63;
    int d = dp * 2;
    float w0 = omega[(size_t)d * MM + m] * SCALE_U;
    float w1 = omega[(size_t)(d + 1) * MM + m] * SCALE_U;
    u32 hp = bpack(w0, w1);
    float r0 = w0 - __uint_as_float(hp << 16);
    float r1 = w1 - __uint_as_float(hp & 0xFFFF0000u);
    u32 lp = bpack(r0, r1);
    int idx = (((d >> 4) * 32 + (m >> 3)) * 2 + ((d >> 3) & 1)) * 32
            + (m & 7) * 4 + ((d & 7) >> 1);
    g_wfrag_hi[idx] = hp;
    g_wfrag_lo[idx] = lp;
}

// ---------------------------------------------------------------------------
// Shared projection mainloop: CTA = 64 tok x 256 m, K=128.
// Warp tile 32 tok x 64 m. A converted to smem at (saHi/saLo); B from frags.
// ---------------------------------------------------------------------------
__device__ __forceinline__ void proj_mma_main(
    const float* __restrict__ Xb, char* dyn, u32 sb,
    float c[2][8][4], float* sHred, int saHi, int saLo)
{
    const int tid = threadIdx.x;
    const int lane = tid & 31;
    const int w = tid >> 5;

    {   // A: 64 tok x 128 d, f32 -> bf16 hi/lo, swizzled; h partials
        int row = tid >> 2, seg = (tid & 3) * 32;
        const float* src = Xb + (size_t)row * DD + seg;
        float hs = 0.f;
        #pragma unroll
        for (int q = 0; q < 4; q++) {
            float x[8];
            float4 v0 = *(const float4*)(src + q * 8);
            float4 v1 = *(const float4*)(src + q * 8 + 4);
            x[0] = v0.x; x[1] = v0.y; x[2] = v0.z; x[3] = v0.w;
            x[4] = v1.x; x[5] = v1.y; x[6] = v1.z; x[7] = v1.w;
            #pragma unroll
            for (int e = 0; e < 8; e++) hs = fmaf(x[e], x[e], hs);
            uint4 h4, l4;
            cvt8(x, h4, l4);
            int chunk = ((seg >> 3) + q) ^ (row & 7);
            *(uint4*)(dyn + saHi + row * 256 + (chunk << 4)) = h4;
            *(uint4*)(dyn + saLo + row * 256 + (chunk << 4)) = l4;
        }
        sHred[tid] = hs;
    }
    __syncthreads();

    const int tok0 = (w & 1) * 32;
    const int m0w = (w >> 1) * 64;
    const int rowA0 = tok0 + ((lane >> 3) & 1) * 8 + (lane & 7);
    const int kselA = (lane >> 4) & 1;
    const int nbBase = (m0w >> 3);

    #pragma unroll
    for (int ks = 0; ks < 8; ks++) {
        int kc = ks * 2;
        u32 ah[2][4], al[2][4];
        #pragma unroll
        for (int mb = 0; mb < 2; mb++) {
            int row = rowA0 + mb * 16;
            u32 adr = sb + saHi + row * 256 + (((kc + kselA) ^ (row & 7)) << 4);
            ldsm_x4(ah[mb][0], ah[mb][1], ah[mb][2], ah[mb][3], adr);
            ldsm_x4(al[mb][0], al[mb][1], al[mb][2], al[mb][3], adr + (saLo - saHi));
        }
        #pragma unroll
        for (int nb = 0; nb < 8; nb++) {
            int base = ((ks * 32 + nbBase + nb) * 2) * 32 + lane;
            u32 bh[2], bl[2];
            bh[0] = g_wfrag_hi[base];
            bh[1] = g_wfrag_hi[base + 32];
            bl[0] = g_wfrag_lo[base];
            bl[1] = g_wfrag_lo[base + 32];
            #pragma unroll
            for (int mb = 0; mb < 2; mb++) {
                mma_bf16(c[mb][nb], ah[mb], bh);
                mma_bf16(c[mb][nb], al[mb], bh);
                mma_bf16(c[mb][nb], ah[mb], bl);
            }
        }
    }
    __syncthreads();
}

// ---------------------------------------------------------------------------
// kproj: R8 version. smem: sA@0/16K; sU f32 [64][264] overlays from 0.
// ---------------------------------------------------------------------------
#define P_SMEM 67584
#define SU_STRIDE 264

__global__ void __launch_bounds__(256, 2)
kproj_mma(const float* __restrict__ Kin) {
    extern __shared__ __align__(16) char dyn[];
    __shared__ float sHred[256];
    __shared__ float wred[8];

    const int tid = threadIdx.x;
    const int b = blockIdx.y;
    const int n0 = blockIdx.x * 64;
    const u32 sbase = smem_u32(dyn);

    float c[2][8][4];
    #pragma unroll
    for (int mb = 0; mb < 2; mb++)
        #pragma unroll
        for (int nb = 0; nb < 8; nb++)
            #pragma unroll
            for (int q = 0; q < 4; q++) c[mb][nb][q] = 0.f;

    proj_mma_main(Kin + ((size_t)b * NN + n0) * DD, dyn, sbase, c, sHred, 0, 16384);

    float* sU = (float*)dyn;
    const int lane = tid & 31, w = tid >> 5;
    const int tok0 = (w & 1) * 32, m0w = (w >> 1) * 64;
    const int gid = lane >> 2, tig = lane & 3;
    float lmax = -INFINITY;
    #pragma unroll
    for (int mb = 0; mb < 2; mb++)
        #pragma unroll
        for (int nb = 0; nb < 8; nb++) {
            int r0 = tok0 + mb * 16 + gid;
            int m = m0w + nb * 8 + 2 * tig;
            float2 p0 = make_float2(c[mb][nb][0], c[mb][nb][1]);
            float2 p1 = make_float2(c[mb][nb][2], c[mb][nb][3]);
            *(float2*)&sU[r0 * SU_STRIDE + m] = p0;
            *(float2*)&sU[(r0 + 8) * SU_STRIDE + m] = p1;
            lmax = fmaxf(lmax, fmaxf(fmaxf(p0.x, p0.y), fmaxf(p1.x, p1.y)));
        }
    __syncthreads();

    {
        int row = tid >> 2, seg = (tid & 3) * 64;
        float* dst = g_U + ((size_t)(b * NN + n0 + row)) * MM + seg;
        const float* srcr = sU + row * SU_STRIDE + seg;
        #pragma unroll
        for (int q = 0; q < 16; q++)
            *(float4*)(dst + q * 4) = *(const float4*)(srcr + q * 4);
    }
    if (tid < 64) {
        float h = sHred[tid * 4] + sHred[tid * 4 + 1] + sHred[tid * 4 + 2] + sHred[tid * 4 + 3];
        g_h[b * NN + n0 + tid] = h * H_SCALE;
    }
    lmax = warpMax(lmax);
    if ((tid & 31) == 0) wred[tid >> 5] = lmax;
    __syncthreads();
    if (tid == 0) {
        float m = wred[0];
        #pragma unroll
        for (int q = 1; q < 8; q++) m = fmaxf(m, wred[q]);
        atomicMaxFloat(&g_bmax[b], m);
    }
}

// ---------------------------------------------------------------------------
// kv_mma: R8 version. KVT[dv][m] = sum_n V[n][dv]*Kp[n][m], CTA 128dv x 128m.
// ---------------------------------------------------------------------------
#define KV_SV 0
#define KV_SV_LO 16384
#define KV_SKP 32768
#define KV_SKP_LO 49152
#define KV_SMEM 65536

__global__ void __launch_bounds__(256, 2)
kv_mma(const float* __restrict__ V, const float* __restrict__ mask) {
    extern __shared__ __align__(16) char dyn[];

    const int tid = threadIdx.x;
    const int lane = tid & 31;
    const int w = tid >> 5;
    const int b = blockIdx.z;
    const int m0blk = blockIdx.y * 128;
    const int split = blockIdx.x;
    const float mx = g_bmax[b];
    const u32 sbase = smem_u32(dyn);

    const int dv0 = (w & 3) * 32;
    const int m0w = (w >> 2) * 64;
    const int gid = lane >> 2, tig = lane & 3;

    float c[2][8][4];
    #pragma unroll
    for (int mb = 0; mb < 2; mb++)
        #pragma unroll
        for (int nb = 0; nb < 8; nb++)
            #pragma unroll
            for (int q = 0; q < 4; q++) c[mb][nb][q] = 0.f;
    float ksloc[8];
    #pragma unroll
    for (int i = 0; i < 8; i++) ksloc[i] = 0.f;

    const int mg2 = tid & 15;
    const int ng = tid >> 4;

    const int nbase = split * (NN / NSPLIT);
    for (int ch = 0; ch < (NN / NSPLIT) / 64; ch++) {
        const int n0c = nbase + ch * 64;
        {   // V
            int row = tid >> 2, seg = (tid & 3) * 32;
            const float* src = V + ((size_t)(b * NN + n0c + row)) * DVV + seg;
            #pragma unroll
            for (int q = 0; q < 4; q++) {
                float x[8];
                float4 v0 = *(const float4*)(src + q * 8);
                float4 v1 = *(const float4*)(src + q * 8 + 4);
                x[0] = v0.x; x[1] = v0.y; x[2] = v0.z; x[3] = v0.w;
                x[4] = v1.x; x[5] = v1.y; x[6] = v1.z; x[7] = v1.w;
                uint4 h4, l4;
                cvt8(x, h4, l4);
                int chunk = ((seg >> 3) + q) ^ (row & 7);
                *(uint4*)(dyn + KV_SV + row * 256 + (chunk << 4)) = h4;
                *(uint4*)(dyn + KV_SV_LO + row * 256 + (chunk << 4)) = l4;
            }
        }
        {   // Kp
            #pragma unroll
            for (int r = 0; r < 4; r++) {
                int n = ng * 4 + r;
                const float* up = g_U + ((size_t)(b * NN + n0c + n)) * MM + m0blk + mg2 * 8;
                float off = g_h[b * NN + n0c + n] + mx;
                float s = INV_SQRT_M * mask[b * NN + n0c + n];
                float kp[8];
                float4 u0 = *(const float4*)(up);
                float4 u1 = *(const float4*)(up + 4);
                kp[0] = (fexp(u0.x - off) + 1e-4f) * s;
                kp[1] = (fexp(u0.y - off) + 1e-4f) * s;
                kp[2] = (fexp(u0.z - off) + 1e-4f) * s;
                kp[3] = (fexp(u0.w - off) + 1e-4f) * s;
                kp[4] = (fexp(u1.x - off) + 1e-4f) * s;
                kp[5] = (fexp(u1.y - off) + 1e-4f) * s;
                kp[6] = (fexp(u1.z - off) + 1e-4f) * s;
                kp[7] = (fexp(u1.w - off) + 1e-4f) * s;
                #pragma unroll
                for (int i = 0; i < 8; i++) ksloc[i] += kp[i];
                uint4 h4, l4;
                cvt8(kp, h4, l4);
                int chunk = mg2 ^ (n & 7);
                *(uint4*)(dyn + KV_SKP + n * 256 + (chunk << 4)) = h4;
                *(uint4*)(dyn + KV_SKP_LO + n * 256 + (chunk << 4)) = l4;
            }
        }
        __syncthreads();

        #pragma unroll
        for (int ks = 0; ks < 4; ks++) {
            const int kk = ks * 16;
            u32 avh[2][4], avl[2][4];
            {
                int row = kk + ((lane >> 4) & 1) * 8 + (lane & 7);
                int cb = (dv0 >> 3) + ((lane >> 3) & 1);
                #pragma unroll
                for (int mb = 0; mb < 2; mb++) {
                    int chunk = (cb + mb * 2) ^ (row & 7);
                    u32 adr = sbase + KV_SV + row * 256 + (chunk << 4);
                    ldsm_x4t(avh[mb][0], avh[mb][1], avh[mb][2], avh[mb][3], adr);
                    ldsm_x4t(avl[mb][0], avl[mb][1], avl[mb][2], avl[mb][3], adr + 16384);
                }
            }
            {
                int row = kk + ((lane >> 3) & 1) * 8 + (lane & 7);
                int cb = (m0w >> 3) + ((lane >> 4) & 1);
                #pragma unroll
                for (int nbp = 0; nbp < 4; nbp++) {
                    int chunk = (cb + nbp * 2) ^ (row & 7);
                    u32 adr = sbase + KV_SKP + row * 256 + (chunk << 4);
                    u32 bh0[2], bh1[2], bl0[2], bl1[2];
                    ldsm_x4t(bh0[0], bh0[1], bh1[0], bh1[1], adr);
                    ldsm_x4t(bl0[0], bl0[1], bl1[0], bl1[1], adr + 16384);
                    #pragma unroll
                    for (int mb = 0; mb < 2; mb++) {
                        mma_bf16(c[mb][2 * nbp], avh[mb], bh0);
                        mma_bf16(c[mb][2 * nbp], avl[mb], bh0);
                        mma_bf16(c[mb][2 * nbp], avh[mb], bl0);
                        mma_bf16(c[mb][2 * nbp + 1], avh[mb], bh1);
                        mma_bf16(c[mb][2 * nbp + 1], avl[mb], bh1);
                        mma_bf16(c[mb][2 * nbp + 1], avh[mb], bl1);
                    }
                }
            }
        }
        __syncthreads();
    }

    float* outp = g_KVpart[split];
    #pragma unroll
    for (int mb = 0; mb < 2; mb++)
        #pragma unroll
        for (int nb = 0; nb < 8; nb++) {
            int dv = dv0 + mb * 16 + gid;
            int m = m0blk + m0w + nb * 8 + 2 * tig;
            *(float2*)&outp[(size_t)(b * DVV + dv) * MM + m] =
                make_float2(c[mb][nb][0], c[mb][nb][1]);
            *(float2*)&outp[(size_t)(b * DVV + dv + 8) * MM + m] =
                make_float2(c[mb][nb][2], c[mb][nb][3]);
        }

    float* sKs = (float*)dyn;
    __syncthreads();
    #pragma unroll
    for (int i = 0; i < 8; i++) sKs[ng * 128 + mg2 * 8 + i] = ksloc[i];
    __syncthreads();
    if (tid < 128) {
        float s = 0.f;
        #pragma unroll
        for (int r = 0; r < 16; r++) s += sKs[r * 128 + tid];
        g_KsumPart[split][b * MM + m0blk + tid] = s;
    }
}

__global__ void reduce_kernel() {
    int i = blockIdx.x * 256 + threadIdx.x;
    if (i < BB * DVV * MM) {
        float s = 0.f;
        #pragma unroll
        for (int p = 0; p < NSPLIT; p++) s += g_KVpart[p][i];
        __nv_bfloat16 h = __float2bfloat16(s);
        g_KVT_hi[i] = h;
        g_KVT_lo[i] = __float2bfloat16(s - __bfloat162float(h));
    }
    int j = i - BB * DVV * MM;
    if (j >= 0 && j < BB * MM) {
        float s = 0.f;
        #pragma unroll
        for (int p = 0; p < NSPLIT; p++) s += g_KsumPart[p][j];
        g_Ksum[j] = s;
    }
}

// ---------------------------------------------------------------------------
// qout_fused: Q projection + exp/norm epilogue + Out GEMM in one kernel.
// CTA = 64 tok. Phase 1: U frags (proj_mma_main, sA@64K). Epilogue: per-token
// max/exp/norm on fragments (quad shuffles + smem), Qp -> smem swizzled bf16.
// Phase 2: Out = Qp @ KVT^T, KVT streamed in 64-m chunks into sA region.
// ---------------------------------------------------------------------------
#define Q_QPH 0
#define Q_QPL 32768
#define Q_SA 65536
#define Q_SA_LO 81920
#define Q_SMEM 98304

__global__ void __launch_bounds__(256, 2)
qout_fused(const float* __restrict__ Qin, const float* __restrict__ mask,
           float* __restrict__ out) {
    extern __shared__ __align__(16) char dyn[];
    __shared__ float sHred[256];
    __shared__ float sKsum[MM];
    __shared__ float sMx[64 * 4];
    __shared__ float sNp[64 * 4];

    const int tid = threadIdx.x;
    const int lane = tid & 31;
    const int w = tid >> 5;
    const int b = blockIdx.y;
    const int n0 = blockIdx.x * 64;
    const u32 sbase = smem_u32(dyn);

    if (tid < MM) sKsum[tid] = g_Ksum[b * MM + tid];

    float c[2][8][4];
    #pragma unroll
    for (int mb = 0; mb < 2; mb++)
        #pragma unroll
        for (int nb = 0; nb < 8; nb++)
            #pragma unroll
            for (int q = 0; q < 4; q++) c[mb][nb][q] = 0.f;

    proj_mma_main(Qin + ((size_t)b * NN + n0) * DD, dyn, sbase, c, sHred, Q_SA, Q_SA_LO);

    // ---- epilogue on fragments ----
    const int tok0 = (w & 1) * 32;
    const int m0w = (w >> 1) * 64;
    const int mg = w >> 1;
    const int gid = lane >> 2, tig = lane & 3;

    #pragma unroll
    for (int mb = 0; mb < 2; mb++) {
        float mA = -INFINITY, mB = -INFINITY;
        #pragma unroll
        for (int nb = 0; nb < 8; nb++) {
            mA = fmaxf(mA, fmaxf(c[mb][nb][0], c[mb][nb][1]));
            mB = fmaxf(mB, fmaxf(c[mb][nb][2], c[mb][nb][3]));
        }
        mA = fmaxf(mA, __shfl_xor_sync(0xffffffffu, mA, 1));
        mA = fmaxf(mA, __shfl_xor_sync(0xffffffffu, mA, 2));
        mB = fmaxf(mB, __shfl_xor_sync(0xffffffffu, mB, 1));
        mB = fmaxf(mB, __shfl_xor_sync(0xffffffffu, mB, 2));
        if (tig == 0) {
            int tA = tok0 + mb * 16 + gid;
            sMx[tA * 4 + mg] = mA;
            sMx[(tA + 8) * 4 + mg] = mB;
        }
    }
    __syncthreads();

    #pragma unroll
    for (int mb = 0; mb < 2; mb++) {
        int tA = tok0 + mb * 16 + gid;
        int tB = tA + 8;
        float mxA = fmaxf(fmaxf(sMx[tA * 4], sMx[tA * 4 + 1]), fmaxf(sMx[tA * 4 + 2], sMx[tA * 4 + 3]));
        float mxB = fmaxf(fmaxf(sMx[tB * 4], sMx[tB * 4 + 1]), fmaxf(sMx[tB * 4 + 2], sMx[tB * 4 + 3]));
        float hA = (sHred[tA * 4] + sHred[tA * 4 + 1] + sHred[tA * 4 + 2] + sHred[tA * 4 + 3]) * H_SCALE;
        float hB = (sHred[tB * 4] + sHred[tB * 4 + 1] + sHred[tB * 4 + 2] + sHred[tB * 4 + 3]) * H_SCALE;
        float sA_ = INV_SQRT_M * mask[b * NN + n0 + tA];
        float sB_ = INV_SQRT_M * mask[b * NN + n0 + tB];
        float offA = hA + mxA, offB = hB + mxB;
        float npA = 0.f, npB = 0.f;
        #pragma unroll
        for (int nb = 0; nb < 8; nb++) {
            int m = m0w + nb * 8 + 2 * tig;
            float q0 = (fexp(c[mb][nb][0] - offA) + 1e-4f) * sA_;
            float q1 = (fexp(c[mb][nb][1] - offA) + 1e-4f) * sA_;
            float q2 = (fexp(c[mb][nb][2] - offB) + 1e-4f) * sB_;
            float q3 = (fexp(c[mb][nb][3] - offB) + 1e-4f) * sB_;
            npA = fmaf(q0, sKsum[m], fmaf(q1, sKsum[m + 1], npA));
            npB = fmaf(q2, sKsum[m], fmaf(q3, sKsum[m + 1], npB));
            int cbase = (m0w >> 3) + nb;
            u32 pA = bpack(q0, q1);
            u32 lA = bpack(q0 - __uint_as_float(pA << 16), q1 - __uint_as_float(pA & 0xFFFF0000u));
            u32 pB = bpack(q2, q3);
            u32 lB = bpack(q2 - __uint_as_float(pB << 16), q3 - __uint_as_float(pB & 0xFFFF0000u));
            *(u32*)(dyn + Q_QPH + tA * 512 + ((cbase ^ (tA & 7)) << 4) + tig * 4) = pA;
            *(u32*)(dyn + Q_QPL + tA * 512 + ((cbase ^ (tA & 7)) << 4) + tig * 4) = lA;
            *(u32*)(dyn + Q_QPH + tB * 512 + ((cbase ^ (tB & 7)) << 4) + tig * 4) = pB;
            *(u32*)(dyn + Q_QPL + tB * 512 + ((cbase ^ (tB & 7)) << 4) + tig * 4) = lB;
        }
        npA += __shfl_xor_sync(0xffffffffu, npA, 1);
        npA += __shfl_xor_sync(0xffffffffu, npA, 2);
        npB += __shfl_xor_sync(0xffffffffu, npB, 1);
        npB += __shfl_xor_sync(0xffffffffu, npB, 2);
        if (tig == 0) {
            sNp[tA * 4 + mg] = npA;
            sNp[tB * 4 + mg] = npB;
        }
    }
    __syncthreads();

    // ---- phase 2: Out = Qp @ KVT^T ----
    const int tg = w & 1;
    const int dg = w >> 1;                  // 4 dv-groups of 32
    float c2[2][4][4];
    #pragma unroll
    for (int mb = 0; mb < 2; mb++)
        #pragma unroll
        for (int nb = 0; nb < 4; nb++)
            #pragma unroll
            for (int q = 0; q < 4; q++) c2[mb][nb][q] = 0.f;

    const int rowA0 = tg * 32 + ((lane >> 3) & 1) * 8 + (lane & 7);
    const int kselA = (lane >> 4) & 1;
    const int rowB0 = dg * 32 + ((lane >> 4) & 1) * 8 + (lane & 7);
    const int kselB = (lane >> 3) & 1;

    for (int kc = 0; kc < 4; kc++) {
        {   // load KVT chunk: 128 dv x 64 m, hi/lo -> Q_SA / Q_SA_LO
            int row = tid >> 1, hf = tid & 1;
            const uint4* kh = (const uint4*)(g_KVT_hi + (size_t)(b * DVV + row) * MM + kc * 64 + hf * 32);
            const uint4* kl = (const uint4*)(g_KVT_lo + (size_t)(b * DVV + row) * MM + kc * 64 + hf * 32);
            #pragma unroll
            for (int q = 0; q < 4; q++) {
                int chunk = (hf * 4 + q) ^ (row & 7);
                *(uint4*)(dyn + Q_SA + row * 128 + (chunk << 4)) = kh[q];
                *(uint4*)(dyn + Q_SA_LO + row * 128 + (chunk << 4)) = kl[q];
            }
        }
        __syncthreads();
        #pragma unroll
        for (int ks = 0; ks < 4; ks++) {
            u32 ah[2][4], al[2][4];
            #pragma unroll
            for (int mb = 0; mb < 2; mb++) {
                int row = rowA0 + mb * 16;
                int chunk = (kc * 8 + ks * 2 + kselA) ^ (row & 7);
                u32 adr = sbase + Q_QPH + row * 512 + (chunk << 4);
                ldsm_x4(ah[mb][0], ah[mb][1], ah[mb][2], ah[mb][3], adr);
                ldsm_x4(al[mb][0], al[mb][1], al[mb][2], al[mb][3], adr + 32768);
            }
            #pragma unroll
            for (int nbp = 0; nbp < 2; nbp++) {
                int row = rowB0 + nbp * 16;
                int chunk = (ks * 2 + kselB) ^ (row & 7);
                u32 adr = sbase + Q_SA + row * 128 + (chunk << 4);
                u32 bh0[2], bh1[2], bl0[2], bl1[2];
                ldsm_x4(bh0[0], bh0[1], bh1[0], bh1[1], adr);
                ldsm_x4(bl0[0], bl0[1], bl1[0], bl1[1], adr + 16384);
                #pragma unroll
                for (int mb = 0; mb < 2; mb++) {
                    mma_bf16(c2[mb][2 * nbp], ah[mb], bh0);
                    mma_bf16(c2[mb][2 * nbp], al[mb], bh0);
                    mma_bf16(c2[mb][2 * nbp], ah[mb], bl0);
                    mma_bf16(c2[mb][2 * nbp + 1], ah[mb], bh1);
                    mma_bf16(c2[mb][2 * nbp + 1], al[mb], bh1);
                    mma_bf16(c2[mb][2 * nbp + 1], ah[mb], bl1);
                }
            }
        }
        __syncthreads();
    }

    // ---- write out ----
    #pragma unroll
    for (int mb = 0; mb < 2; mb++) {
        int t0 = tg * 32 + mb * 16 + gid;
        float r0 = 1.0f / (sNp[t0 * 4] + sNp[t0 * 4 + 1] + sNp[t0 * 4 + 2] + sNp[t0 * 4 + 3] + 1e-8f);
        float r1 = 1.0f / (sNp[(t0 + 8) * 4] + sNp[(t0 + 8) * 4 + 1] + sNp[(t0 + 8) * 4 + 2] + sNp[(t0 + 8) * 4 + 3] + 1e-8f);
        float* d0 = out + ((size_t)(b * NN + n0 + t0)) * DVV;
        float* d1 = d0 + (size_t)8 * DVV;
        #pragma unroll
        for (int nb = 0; nb < 4; nb++) {
            int dv = dg * 32 + nb * 8 + 2 * tig;
            *(float2*)(d0 + dv) = make_float2(c2[mb][nb][0] * r0, c2[mb][nb][1] * r0);
            *(float2*)(d1 + dv) = make_float2(c2[mb][nb][2] * r1, c2[mb][nb][3] * r1);
        }
    }
}

// ---------------------------------------------------------------------------
extern "C" void kernel_launch(void* const* d_in, const int* in_sizes, int n_in,
                              void* d_out, int out_size) {
    const float* Q     = (const float*)d_in[0];
    const float* K     = (const float*)d_in[1];
    const float* V     = (const float*)d_in[2];
    const float* amask = (const float*)d_in[3];
    const float* omega = (const float*)d_in[4];
    float* out = (float*)d_out;

    cudaFuncSetAttribute(kproj_mma,  cudaFuncAttributeMaxDynamicSharedMemorySize, P_SMEM);
    cudaFuncSetAttribute(kv_mma,     cudaFuncAttributeMaxDynamicSharedMemorySize, KV_SMEM);
    cudaFuncSetAttribute(qout_fused, cudaFuncAttributeMaxDynamicSharedMemorySize, Q_SMEM);

    init_kernel<<<1, 32>>>();
    prep_omega<<<64, 256>>>(omega);
    kproj_mma<<<dim3(NN / 64, BB), 256, P_SMEM>>>(K);
    kv_mma<<<dim3(NSPLIT, MM / 128, BB), 256, KV_SMEM>>>(V, amask);
    reduce_kernel<<<(BB * DVV * MM + BB * MM + 255) / 256, 256>>>();
    qout_fused<<<dim3(NN / 64, BB), 256, Q_SMEM>>>(Q, amask, out);
}

// round 15
// speedup vs baseline: 1.9398x; 1.0437x over previous
#include <cuda_runtime.h>
#include <cuda_bf16.h>
#include <math.h>

#define BB 8
#define NN 8192
#define DD 128
#define DVV 128
#define MM 256
#define NSPLIT 16

#define SCALE_U 0.29730177875068026f   // 128^-0.25
#define H_SCALE 0.04419417382415922f   // 1/(2*sqrt(128))
#define INV_SQRT_M 0.0625f             // 1/sqrt(256)

typedef unsigned long long ull;
typedef unsigned int u32;

// ---------------------------------------------------------------------------
// Device scratch
// ---------------------------------------------------------------------------
__device__ float g_U[(size_t)BB * NN * MM];      // raw scaled U (K pass)
__device__ float g_h[BB * NN];
__device__ float g_bmax[BB];
__device__ float g_KVpart[NSPLIT][BB * DVV * MM];   // KV^T partials [b][dv][m]
__device__ float g_KsumPart[NSPLIT][BB * MM];
__device__ float g_Ksum[BB * MM];
// omega as packed mma B-fragments: [kstep(8)][nb(32)][lane(32)] x uint4
// uint4 = {hi_reg0, hi_reg1, lo_reg0, lo_reg1}
__device__ u32 g_wfrag[8 * 32 * 32 * 4];
__device__ __nv_bfloat16 g_KVT_hi[BB * DVV * MM];         // [b][dv][m]
__device__ __nv_bfloat16 g_KVT_lo[BB * DVV * MM];

// ---------------------------------------------------------------------------
// PTX helpers (sm_80-level)
// ---------------------------------------------------------------------------
__device__ __forceinline__ u32 smem_u32(const void* p) {
    u32 a;
    asm("{ .reg .u64 t; cvta.to.shared.u64 t, %1; cvt.u32.u64 %0, t; }" : "=r"(a) : "l"(p));
    return a;
}
__device__ __forceinline__ void ldsm_x4(u32& r0, u32& r1, u32& r2, u32& r3, u32 addr) {
    asm volatile("ldmatrix.sync.aligned.m8n8.x4.shared.b16 {%0,%1,%2,%3}, [%4];"
                 : "=r"(r0), "=r"(r1), "=r"(r2), "=r"(r3) : "r"(addr));
}
__device__ __forceinline__ void ldsm_x4t(u32& r0, u32& r1, u32& r2, u32& r3, u32 addr) {
    asm volatile("ldmatrix.sync.aligned.m8n8.x4.trans.shared.b16 {%0,%1,%2,%3}, [%4];"
                 : "=r"(r0), "=r"(r1), "=r"(r2), "=r"(r3) : "r"(addr));
}
__device__ __forceinline__ void mma_bf16(float* c, const u32* a, const u32* b) {
    asm volatile("mma.sync.aligned.m16n8k16.row.col.f32.bf16.bf16.f32 "
                 "{%0,%1,%2,%3}, {%4,%5,%6,%7}, {%8,%9}, {%0,%1,%2,%3};"
                 : "+f"(c[0]), "+f"(c[1]), "+f"(c[2]), "+f"(c[3])
                 : "r"(a[0]), "r"(a[1]), "r"(a[2]), "r"(a[3]), "r"(b[0]), "r"(b[1]));
}
__device__ __forceinline__ u32 bpack(float lo, float hi) {
    u32 r;
    asm("cvt.rn.bf16x2.f32 %0, %1, %2;" : "=r"(r) : "f"(hi), "f"(lo));
    return r;
}
__device__ __forceinline__ void cvt8(const float* x, uint4& h4, uint4& l4) {
    u32 h[4], l[4];
    #pragma unroll
    for (int i = 0; i < 4; i++) {
        u32 p = bpack(x[2 * i], x[2 * i + 1]);
        h[i] = p;
        float r0 = x[2 * i]     - __uint_as_float(p << 16);
        float r1 = x[2 * i + 1] - __uint_as_float(p & 0xFFFF0000u);
        l[i] = bpack(r0, r1);
    }
    h4 = make_uint4(h[0], h[1], h[2], h[3]);
    l4 = make_uint4(l[0], l[1], l[2], l[3]);
}

__device__ __forceinline__ float fexp(float x) {
    x = fmaxf(x, -87.0f);
    float t = x * 1.4426950408889634f;
    float r = rintf(t);
    float f = t - r;
    float z = f * 0.6931471805599453f;
    float p = 1.0f + z * (1.0f + z * (0.5f + z * (0.16666667f +
              z * (0.041666667f + z * (0.0083333333f + z * 0.0013888889f)))));
    return __int_as_float(((int)r + 127) << 23) * p;
}
__device__ __forceinline__ float warpMax(float v) {
    #pragma unroll
    for (int o = 16; o; o >>= 1) v = fmaxf(v, __shfl_xor_sync(0xffffffffu, v, o));
    return v;
}
__device__ __forceinline__ void atomicMaxFloat(float* addr, float val) {
    int old = __float_as_int(*addr);
    while (__int_as_float(old) < val) {
        int prev = atomicCAS((int*)addr, old, __float_as_int(val));
        if (prev == old) break;
        old = prev;
    }
}

__global__ void init_kernel() {
    if (threadIdx.x < BB) g_bmax[threadIdx.x] = -INFINITY;
}

// prep_omega: omegaT element (m, d): ks=d>>4, nb=m>>3, reg=(d>>3)&1,
// lane=(m&7)*4+((d&7)>>1). Packed uint4 at [(ks*32+nb)*32+lane].
__global__ void prep_omega(const float* __restrict__ omega) {
    int id = blockIdx.x * 256 + threadIdx.x;   // 16384 total
    int m = id >> 6;
    int dp = id & 63;
    int d = dp * 2;
    float w0 = omega[(size_t)d * MM + m] * SCALE_U;
    float w1 = omega[(size_t)(d + 1) * MM + m] * SCALE_U;
    u32 hp = bpack(w0, w1);
    float r0 = w0 - __uint_as_float(hp << 16);
    float r1 = w1 - __uint_as_float(hp & 0xFFFF0000u);
    u32 lp = bpack(r0, r1);
    int idx4 = (((d >> 4) * 32 + (m >> 3)) * 32 + (m & 7) * 4 + ((d & 7) >> 1)) * 4;
    int reg = (d >> 3) & 1;
    g_wfrag[idx4 + reg] = hp;
    g_wfrag[idx4 + 2 + reg] = lp;
}

// ---------------------------------------------------------------------------
// Shared projection mainloop: CTA = 64 tok x 256 m, K=128.
// Warp tile 32 tok x 64 m. A converted to smem at (saHi/saLo); B from frags.
// ---------------------------------------------------------------------------
__device__ __forceinline__ void proj_mma_main(
    const float* __restrict__ Xb, char* dyn, u32 sb,
    float c[2][8][4], float* sHred, int saHi, int saLo)
{
    const int tid = threadIdx.x;
    const int lane = tid & 31;
    const int w = tid >> 5;

    {   // A: 64 tok x 128 d, f32 -> bf16 hi/lo, swizzled; h partials
        int row = tid >> 2, seg = (tid & 3) * 32;
        const float* src = Xb + (size_t)row * DD + seg;
        float hs = 0.f;
        #pragma unroll
        for (int q = 0; q < 4; q++) {
            float x[8];
            float4 v0 = *(const float4*)(src + q * 8);
            float4 v1 = *(const float4*)(src + q * 8 + 4);
            x[0] = v0.x; x[1] = v0.y; x[2] = v0.z; x[3] = v0.w;
            x[4] = v1.x; x[5] = v1.y; x[6] = v1.z; x[7] = v1.w;
            #pragma unroll
            for (int e = 0; e < 8; e++) hs = fmaf(x[e], x[e], hs);
            uint4 h4, l4;
            cvt8(x, h4, l4);
            int chunk = ((seg >> 3) + q) ^ (row & 7);
            *(uint4*)(dyn + saHi + row * 256 + (chunk << 4)) = h4;
            *(uint4*)(dyn + saLo + row * 256 + (chunk << 4)) = l4;
        }
        sHred[tid] = hs;
    }
    __syncthreads();

    const int tok0 = (w & 1) * 32;
    const int m0w = (w >> 1) * 64;
    const int rowA0 = tok0 + ((lane >> 3) & 1) * 8 + (lane & 7);
    const int kselA = (lane >> 4) & 1;
    const int nbBase = (m0w >> 3);

    #pragma unroll
    for (int ks = 0; ks < 8; ks++) {
        int kc = ks * 2;
        u32 ah[2][4], al[2][4];
        #pragma unroll
        for (int mb = 0; mb < 2; mb++) {
            int row = rowA0 + mb * 16;
            u32 adr = sb + saHi + row * 256 + (((kc + kselA) ^ (row & 7)) << 4);
            ldsm_x4(ah[mb][0], ah[mb][1], ah[mb][2], ah[mb][3], adr);
            ldsm_x4(al[mb][0], al[mb][1], al[mb][2], al[mb][3], adr + (saLo - saHi));
        }
        #pragma unroll
        for (int nb = 0; nb < 8; nb++) {
            uint4 f = *(const uint4*)&g_wfrag[((ks * 32 + nbBase + nb) * 32 + lane) * 4];
            u32 bh[2] = {f.x, f.y};
            u32 bl[2] = {f.z, f.w};
            #pragma unroll
            for (int mb = 0; mb < 2; mb++) {
                mma_bf16(c[mb][nb], ah[mb], bh);
                mma_bf16(c[mb][nb], al[mb], bh);
                mma_bf16(c[mb][nb], ah[mb], bl);
            }
        }
    }
    __syncthreads();
}

// ---------------------------------------------------------------------------
// kproj: smem: sA@0/16K; sU f32 [64][264] overlays from 0.
// ---------------------------------------------------------------------------
#define P_SMEM 67584
#define SU_STRIDE 264

__global__ void __launch_bounds__(256, 2)
kproj_mma(const float* __restrict__ Kin) {
    extern __shared__ __align__(16) char dyn[];
    __shared__ float sHred[256];
    __shared__ float wred[8];

    const int tid = threadIdx.x;
    const int b = blockIdx.y;
    const int n0 = blockIdx.x * 64;
    const u32 sbase = smem_u32(dyn);

    float c[2][8][4];
    #pragma unroll
    for (int mb = 0; mb < 2; mb++)
        #pragma unroll
        for (int nb = 0; nb < 8; nb++)
            #pragma unroll
            for (int q = 0; q < 4; q++) c[mb][nb][q] = 0.f;

    proj_mma_main(Kin + ((size_t)b * NN + n0) * DD, dyn, sbase, c, sHred, 0, 16384);

    float* sU = (float*)dyn;
    const int lane = tid & 31, w = tid >> 5;
    const int tok0 = (w & 1) * 32, m0w = (w >> 1) * 64;
    const int gid = lane >> 2, tig = lane & 3;
    float lmax = -INFINITY;
    #pragma unroll
    for (int mb = 0; mb < 2; mb++)
        #pragma unroll
        for (int nb = 0; nb < 8; nb++) {
            int r0 = tok0 + mb * 16 + gid;
            int m = m0w + nb * 8 + 2 * tig;
            float2 p0 = make_float2(c[mb][nb][0], c[mb][nb][1]);
            float2 p1 = make_float2(c[mb][nb][2], c[mb][nb][3]);
            *(float2*)&sU[r0 * SU_STRIDE + m] = p0;
            *(float2*)&sU[(r0 + 8) * SU_STRIDE + m] = p1;
            lmax = fmaxf(lmax, fmaxf(fmaxf(p0.x, p0.y), fmaxf(p1.x, p1.y)));
        }
    __syncthreads();

    {
        int row = tid >> 2, seg = (tid & 3) * 64;
        float* dst = g_U + ((size_t)(b * NN + n0 + row)) * MM + seg;
        const float* srcr = sU + row * SU_STRIDE + seg;
        #pragma unroll
        for (int q = 0; q < 16; q++)
            *(float4*)(dst + q * 4) = *(const float4*)(srcr + q * 4);
    }
    if (tid < 64) {
        float h = sHred[tid * 4] + sHred[tid * 4 + 1] + sHred[tid * 4 + 2] + sHred[tid * 4 + 3];
        g_h[b * NN + n0 + tid] = h * H_SCALE;
    }
    lmax = warpMax(lmax);
    if ((tid & 31) == 0) wred[tid >> 5] = lmax;
    __syncthreads();
    if (tid == 0) {
        float m = wred[0];
        #pragma unroll
        for (int q = 1; q < 8; q++) m = fmaxf(m, wred[q]);
        atomicMaxFloat(&g_bmax[b], m);
    }
}

// ---------------------------------------------------------------------------
// kv_mma: KVT[dv][m] = sum_n V[n][dv]*Kp[n][m], CTA 128dv x 128m. (R8 code)
// ---------------------------------------------------------------------------
#define KV_SV 0
#define KV_SV_LO 16384
#define KV_SKP 32768
#define KV_SKP_LO 49152
#define KV_SMEM 65536

__global__ void __launch_bounds__(256, 2)
kv_mma(const float* __restrict__ V, const float* __restrict__ mask) {
    extern __shared__ __align__(16) char dyn[];

    const int tid = threadIdx.x;
    const int lane = tid & 31;
    const int w = tid >> 5;
    const int b = blockIdx.z;
    const int m0blk = blockIdx.y * 128;
    const int split = blockIdx.x;
    const float mx = g_bmax[b];
    const u32 sbase = smem_u32(dyn);

    const int dv0 = (w & 3) * 32;
    const int m0w = (w >> 2) * 64;
    const int gid = lane >> 2, tig = lane & 3;

    float c[2][8][4];
    #pragma unroll
    for (int mb = 0; mb < 2; mb++)
        #pragma unroll
        for (int nb = 0; nb < 8; nb++)
            #pragma unroll
            for (int q = 0; q < 4; q++) c[mb][nb][q] = 0.f;
    float ksloc[8];
    #pragma unroll
    for (int i = 0; i < 8; i++) ksloc[i] = 0.f;

    const int mg2 = tid & 15;
    const int ng = tid >> 4;

    const int nbase = split * (NN / NSPLIT);
    for (int ch = 0; ch < (NN / NSPLIT) / 64; ch++) {
        const int n0c = nbase + ch * 64;
        {   // V
            int row = tid >> 2, seg = (tid & 3) * 32;
            const float* src = V + ((size_t)(b * NN + n0c + row)) * DVV + seg;
            #pragma unroll
            for (int q = 0; q < 4; q++) {
                float x[8];
                float4 v0 = *(const float4*)(src + q * 8);
                float4 v1 = *(const float4*)(src + q * 8 + 4);
                x[0] = v0.x; x[1] = v0.y; x[2] = v0.z; x[3] = v0.w;
                x[4] = v1.x; x[5] = v1.y; x[6] = v1.z; x[7] = v1.w;
                uint4 h4, l4;
                cvt8(x, h4, l4);
                int chunk = ((seg >> 3) + q) ^ (row & 7);
                *(uint4*)(dyn + KV_SV + row * 256 + (chunk << 4)) = h4;
                *(uint4*)(dyn + KV_SV_LO + row * 256 + (chunk << 4)) = l4;
            }
        }
        {   // Kp
            #pragma unroll
            for (int r = 0; r < 4; r++) {
                int n = ng * 4 + r;
                const float* up = g_U + ((size_t)(b * NN + n0c + n)) * MM + m0blk + mg2 * 8;
                float off = g_h[b * NN + n0c + n] + mx;
                float s = INV_SQRT_M * mask[b * NN + n0c + n];
                float kp[8];
                float4 u0 = *(const float4*)(up);
                float4 u1 = *(const float4*)(up + 4);
                kp[0] = (fexp(u0.x - off) + 1e-4f) * s;
                kp[1] = (fexp(u0.y - off) + 1e-4f) * s;
                kp[2] = (fexp(u0.z - off) + 1e-4f) * s;
                kp[3] = (fexp(u0.w - off) + 1e-4f) * s;
                kp[4] = (fexp(u1.x - off) + 1e-4f) * s;
                kp[5] = (fexp(u1.y - off) + 1e-4f) * s;
                kp[6] = (fexp(u1.z - off) + 1e-4f) * s;
                kp[7] = (fexp(u1.w - off) + 1e-4f) * s;
                #pragma unroll
                for (int i = 0; i < 8; i++) ksloc[i] += kp[i];
                uint4 h4, l4;
                cvt8(kp, h4, l4);
                int chunk = mg2 ^ (n & 7);
                *(uint4*)(dyn + KV_SKP + n * 256 + (chunk << 4)) = h4;
                *(uint4*)(dyn + KV_SKP_LO + n * 256 + (chunk << 4)) = l4;
            }
        }
        __syncthreads();

        #pragma unroll
        for (int ks = 0; ks < 4; ks++) {
            const int kk = ks * 16;
            u32 avh[2][4], avl[2][4];
            {
                int row = kk + ((lane >> 4) & 1) * 8 + (lane & 7);
                int cb = (dv0 >> 3) + ((lane >> 3) & 1);
                #pragma unroll
                for (int mb = 0; mb < 2; mb++) {
                    int chunk = (cb + mb * 2) ^ (row & 7);
                    u32 adr = sbase + KV_SV + row * 256 + (chunk << 4);
                    ldsm_x4t(avh[mb][0], avh[mb][1], avh[mb][2], avh[mb][3], adr);
                    ldsm_x4t(avl[mb][0], avl[mb][1], avl[mb][2], avl[mb][3], adr + 16384);
                }
            }
            {
                int row = kk + ((lane >> 3) & 1) * 8 + (lane & 7);
                int cb = (m0w >> 3) + ((lane >> 4) & 1);
                #pragma unroll
                for (int nbp = 0; nbp < 4; nbp++) {
                    int chunk = (cb + nbp * 2) ^ (row & 7);
                    u32 adr = sbase + KV_SKP + row * 256 + (chunk << 4);
                    u32 bh0[2], bh1[2], bl0[2], bl1[2];
                    ldsm_x4t(bh0[0], bh0[1], bh1[0], bh1[1], adr);
                    ldsm_x4t(bl0[0], bl0[1], bl1[0], bl1[1], adr + 16384);
                    #pragma unroll
                    for (int mb = 0; mb < 2; mb++) {
                        mma_bf16(c[mb][2 * nbp], avh[mb], bh0);
                        mma_bf16(c[mb][2 * nbp], avl[mb], bh0);
                        mma_bf16(c[mb][2 * nbp], avh[mb], bl0);
                        mma_bf16(c[mb][2 * nbp + 1], avh[mb], bh1);
                        mma_bf16(c[mb][2 * nbp + 1], avl[mb], bh1);
                        mma_bf16(c[mb][2 * nbp + 1], avh[mb], bl1);
                    }
                }
            }
        }
        __syncthreads();
    }

    float* outp = g_KVpart[split];
    #pragma unroll
    for (int mb = 0; mb < 2; mb++)
        #pragma unroll
        for (int nb = 0; nb < 8; nb++) {
            int dv = dv0 + mb * 16 + gid;
            int m = m0blk + m0w + nb * 8 + 2 * tig;
            *(float2*)&outp[(size_t)(b * DVV + dv) * MM + m] =
                make_float2(c[mb][nb][0], c[mb][nb][1]);
            *(float2*)&outp[(size_t)(b * DVV + dv + 8) * MM + m] =
                make_float2(c[mb][nb][2], c[mb][nb][3]);
        }

    float* sKs = (float*)dyn;
    __syncthreads();
    #pragma unroll
    for (int i = 0; i < 8; i++) sKs[ng * 128 + mg2 * 8 + i] = ksloc[i];
    __syncthreads();
    if (tid < 128) {
        float s = 0.f;
        #pragma unroll
        for (int r = 0; r < 16; r++) s += sKs[r * 128 + tid];
        g_KsumPart[split][b * MM + m0blk + tid] = s;
    }
}

__global__ void reduce_kernel() {
    int i = blockIdx.x * 256 + threadIdx.x;
    if (i < BB * DVV * MM) {
        float s = 0.f;
        #pragma unroll
        for (int p = 0; p < NSPLIT; p++) s += g_KVpart[p][i];
        __nv_bfloat16 h = __float2bfloat16(s);
        g_KVT_hi[i] = h;
        g_KVT_lo[i] = __float2bfloat16(s - __bfloat162float(h));
    }
    int j = i - BB * DVV * MM;
    if (j >= 0 && j < BB * MM) {
        float s = 0.f;
        #pragma unroll
        for (int p = 0; p < NSPLIT; p++) s += g_KsumPart[p][j];
        g_Ksum[j] = s;
    }
}

// ---------------------------------------------------------------------------
// qout_fused: Q projection + exp/norm epilogue + Out GEMM.
// Phase 2 KVT loads are software-pipelined (prefetch chunk kc+1 into regs).
// ---------------------------------------------------------------------------
#define Q_QPH 0
#define Q_QPL 32768
#define Q_SA 65536
#define Q_SA_LO 81920
#define Q_SMEM 98304

__global__ void __launch_bounds__(256, 2)
qout_fused(const float* __restrict__ Qin, const float* __restrict__ mask,
           float* __restrict__ out) {
    extern __shared__ __align__(16) char dyn[];
    __shared__ float sHred[256];
    __shared__ float sKsum[MM];
    __shared__ float sMx[64 * 4];
    __shared__ float sNp[64 * 4];

    const int tid = threadIdx.x;
    const int lane = tid & 31;
    const int w = tid >> 5;
    const int b = blockIdx.y;
    const int n0 = blockIdx.x * 64;
    const u32 sbase = smem_u32(dyn);

    if (tid < MM) sKsum[tid] = g_Ksum[b * MM + tid];

    float c[2][8][4];
    #pragma unroll
    for (int mb = 0; mb < 2; mb++)
        #pragma unroll
        for (int nb = 0; nb < 8; nb++)
            #pragma unroll
            for (int q = 0; q < 4; q++) c[mb][nb][q] = 0.f;

    proj_mma_main(Qin + ((size_t)b * NN + n0) * DD, dyn, sbase, c, sHred, Q_SA, Q_SA_LO);

    // ---- epilogue on fragments ----
    const int tok0 = (w & 1) * 32;
    const int m0w = (w >> 1) * 64;
    const int mg = w >> 1;
    const int gid = lane >> 2, tig = lane & 3;

    #pragma unroll
    for (int mb = 0; mb < 2; mb++) {
        float mA = -INFINITY, mB = -INFINITY;
        #pragma unroll
        for (int nb = 0; nb < 8; nb++) {
            mA = fmaxf(mA, fmaxf(c[mb][nb][0], c[mb][nb][1]));
            mB = fmaxf(mB, fmaxf(c[mb][nb][2], c[mb][nb][3]));
        }
        mA = fmaxf(mA, __shfl_xor_sync(0xffffffffu, mA, 1));
        mA = fmaxf(mA, __shfl_xor_sync(0xffffffffu, mA, 2));
        mB = fmaxf(mB, __shfl_xor_sync(0xffffffffu, mB, 1));
        mB = fmaxf(mB, __shfl_xor_sync(0xffffffffu, mB, 2));
        if (tig == 0) {
            int tA = tok0 + mb * 16 + gid;
            sMx[tA * 4 + mg] = mA;
            sMx[(tA + 8) * 4 + mg] = mB;
        }
    }
    __syncthreads();

    #pragma unroll
    for (int mb = 0; mb < 2; mb++) {
        int tA = tok0 + mb * 16 + gid;
        int tB = tA + 8;
        float mxA = fmaxf(fmaxf(sMx[tA * 4], sMx[tA * 4 + 1]), fmaxf(sMx[tA * 4 + 2], sMx[tA * 4 + 3]));
        float mxB = fmaxf(fmaxf(sMx[tB * 4], sMx[tB * 4 + 1]), fmaxf(sMx[tB * 4 + 2], sMx[tB * 4 + 3]));
        float hA = (sHred[tA * 4] + sHred[tA * 4 + 1] + sHred[tA * 4 + 2] + sHred[tA * 4 + 3]) * H_SCALE;
        float hB = (sHred[tB * 4] + sHred[tB * 4 + 1] + sHred[tB * 4 + 2] + sHred[tB * 4 + 3]) * H_SCALE;
        float sA_ = INV_SQRT_M * mask[b * NN + n0 + tA];
        float sB_ = INV_SQRT_M * mask[b * NN + n0 + tB];
        float offA = hA + mxA, offB = hB + mxB;
        float npA = 0.f, npB = 0.f;
        #pragma unroll
        for (int nb = 0; nb < 8; nb++) {
            int m = m0w + nb * 8 + 2 * tig;
            float q0 = (fexp(c[mb][nb][0] - offA) + 1e-4f) * sA_;
            float q1 = (fexp(c[mb][nb][1] - offA) + 1e-4f) * sA_;
            float q2 = (fexp(c[mb][nb][2] - offB) + 1e-4f) * sB_;
            float q3 = (fexp(c[mb][nb][3] - offB) + 1e-4f) * sB_;
            npA = fmaf(q0, sKsum[m], fmaf(q1, sKsum[m + 1], npA));
            npB = fmaf(q2, sKsum[m], fmaf(q3, sKsum[m + 1], npB));
            int cbase = (m0w >> 3) + nb;
            u32 pA = bpack(q0, q1);
            u32 lA = bpack(q0 - __uint_as_float(pA << 16), q1 - __uint_as_float(pA & 0xFFFF0000u));
            u32 pB = bpack(q2, q3);
            u32 lB = bpack(q2 - __uint_as_float(pB << 16), q3 - __uint_as_float(pB & 0xFFFF0000u));
            *(u32*)(dyn + Q_QPH + tA * 512 + ((cbase ^ (tA & 7)) << 4) + tig * 4) = pA;
            *(u32*)(dyn + Q_QPL + tA * 512 + ((cbase ^ (tA & 7)) << 4) + tig * 4) = lA;
            *(u32*)(dyn + Q_QPH + tB * 512 + ((cbase ^ (tB & 7)) << 4) + tig * 4) = pB;
            *(u32*)(dyn + Q_QPL + tB * 512 + ((cbase ^ (tB & 7)) << 4) + tig * 4) = lB;
        }
        npA += __shfl_xor_sync(0xffffffffu, npA, 1);
        npA += __shfl_xor_sync(0xffffffffu, npA, 2);
        npB += __shfl_xor_sync(0xffffffffu, npB, 1);
        npB += __shfl_xor_sync(0xffffffffu, npB, 2);
        if (tig == 0) {
            sNp[tA * 4 + mg] = npA;
            sNp[tB * 4 + mg] = npB;
        }
    }
    __syncthreads();

    // ---- phase 2: Out = Qp @ KVT^T, KVT loads pipelined ----
    const int tg = w & 1;
    const int dg = w >> 1;
    float c2[2][4][4];
    #pragma unroll
    for (int mb = 0; mb < 2; mb++)
        #pragma unroll
        for (int nb = 0; nb < 4; nb++)
            #pragma unroll
            for (int q = 0; q < 4; q++) c2[mb][nb][q] = 0.f;

    const int rowA0 = tg * 32 + ((lane >> 3) & 1) * 8 + (lane & 7);
    const int kselA = (lane >> 4) & 1;
    const int rowB0 = dg * 32 + ((lane >> 4) & 1) * 8 + (lane & 7);
    const int kselB = (lane >> 3) & 1;

    const int row2 = tid >> 1, hf = tid & 1;
    uint4 rkh[4], rkl[4];
    {   // prologue: chunk 0
        const uint4* kh = (const uint4*)(g_KVT_hi + (size_t)(b * DVV + row2) * MM + hf * 32);
        const uint4* kl = (const uint4*)(g_KVT_lo + (size_t)(b * DVV + row2) * MM + hf * 32);
        #pragma unroll
        for (int q = 0; q < 4; q++) { rkh[q] = kh[q]; rkl[q] = kl[q]; }
    }

    for (int kc = 0; kc < 4; kc++) {
        {   // store prefetched chunk
            #pragma unroll
            for (int q = 0; q < 4; q++) {
                int chunk = (hf * 4 + q) ^ (row2 & 7);
                *(uint4*)(dyn + Q_SA + row2 * 128 + (chunk << 4)) = rkh[q];
                *(uint4*)(dyn + Q_SA_LO + row2 * 128 + (chunk << 4)) = rkl[q];
            }
        }
        __syncthreads();
        if (kc < 3) {   // prefetch next chunk (latency hidden behind MMA)
            const uint4* kh = (const uint4*)(g_KVT_hi + (size_t)(b * DVV + row2) * MM + (kc + 1) * 64 + hf * 32);
            const uint4* kl = (const uint4*)(g_KVT_lo + (size_t)(b * DVV + row2) * MM + (kc + 1) * 64 + hf * 32);
            #pragma unroll
            for (int q = 0; q < 4; q++) { rkh[q] = kh[q]; rkl[q] = kl[q]; }
        }
        #pragma unroll
        for (int ks = 0; ks < 4; ks++) {
            u32 ah[2][4], al[2][4];
            #pragma unroll
            for (int mb = 0; mb < 2; mb++) {
                int row = rowA0 + mb * 16;
                int chunk = (kc * 8 + ks * 2 + kselA) ^ (row & 7);
                u32 adr = sbase + Q_QPH + row * 512 + (chunk << 4);
                ldsm_x4(ah[mb][0], ah[mb][1], ah[mb][2], ah[mb][3], adr);
                ldsm_x4(al[mb][0], al[mb][1], al[mb][2], al[mb][3], adr + 32768);
            }
            #pragma unroll
            for (int nbp = 0; nbp < 2; nbp++) {
                int row = rowB0 + nbp * 16;
                int chunk = (ks * 2 + kselB) ^ (row & 7);
                u32 adr = sbase + Q_SA + row * 128 + (chunk << 4);
                u32 bh0[2], bh1[2], bl0[2], bl1[2];
                ldsm_x4(bh0[0], bh0[1], bh1[0], bh1[1], adr);
                ldsm_x4(bl0[0], bl0[1], bl1[0], bl1[1], adr + 16384);
                #pragma unroll
                for (int mb = 0; mb < 2; mb++) {
                    mma_bf16(c2[mb][2 * nbp], ah[mb], bh0);
                    mma_bf16(c2[mb][2 * nbp], al[mb], bh0);
                    mma_bf16(c2[mb][2 * nbp], ah[mb], bl0);
                    mma_bf16(c2[mb][2 * nbp + 1], ah[mb], bh1);
                    mma_bf16(c2[mb][2 * nbp + 1], al[mb], bh1);
                    mma_bf16(c2[mb][2 * nbp + 1], ah[mb], bl1);
                }
            }
        }
        __syncthreads();
    }

    // ---- write out ----
    #pragma unroll
    for (int mb = 0; mb < 2; mb++) {
        int t0 = tg * 32 + mb * 16 + gid;
        float r0 = 1.0f / (sNp[t0 * 4] + sNp[t0 * 4 + 1] + sNp[t0 * 4 + 2] + sNp[t0 * 4 + 3] + 1e-8f);
        float r1 = 1.0f / (sNp[(t0 + 8) * 4] + sNp[(t0 + 8) * 4 + 1] + sNp[(t0 + 8) * 4 + 2] + sNp[(t0 + 8) * 4 + 3] + 1e-8f);
        float* d0 = out + ((size_t)(b * NN + n0 + t0)) * DVV;
        float* d1 = d0 + (size_t)8 * DVV;
        #pragma unroll
        for (int nb = 0; nb < 4; nb++) {
            int dv = dg * 32 + nb * 8 + 2 * tig;
            *(float2*)(d0 + dv) = make_float2(c2[mb][nb][0] * r0, c2[mb][nb][1] * r0);
            *(float2*)(d1 + dv) = make_float2(c2[mb][nb][2] * r1, c2[mb][nb][3] * r1);
        }
    }
}

// ---------------------------------------------------------------------------
extern "C" void kernel_launch(void* const* d_in, const int* in_sizes, int n_in,
                              void* d_out, int out_size) {
    const float* Q     = (const float*)d_in[0];
    const float* K     = (const float*)d_in[1];
    const float* V     = (const float*)d_in[2];
    const float* amask = (const float*)d_in[3];
    const float* omega = (const float*)d_in[4];
    float* out = (float*)d_out;

    cudaFuncSetAttribute(kproj_mma,  cudaFuncAttributeMaxDynamicSharedMemorySize, P_SMEM);
    cudaFuncSetAttribute(kv_mma,     cudaFuncAttributeMaxDynamicSharedMemorySize, KV_SMEM);
    cudaFuncSetAttribute(qout_fused, cudaFuncAttributeMaxDynamicSharedMemorySize, Q_SMEM);

    init_kernel<<<1, 32>>>();
    prep_omega<<<64, 256>>>(omega);
    kproj_mma<<<dim3(NN / 64, BB), 256, P_SMEM>>>(K);
    kv_mma<<<dim3(NSPLIT, MM / 128, BB), 256, KV_SMEM>>>(V, amask);
    reduce_kernel<<<(BB * DVV * MM + BB * MM + 255) / 256, 256>>>();
    qout_fused<<<dim3(NN / 64, BB), 256, Q_SMEM>>>(Q, amask, out);
}

// round 16
// speedup vs baseline: 1.9684x; 1.0148x over previous
#include <cuda_runtime.h>
#include <cuda_bf16.h>
#include <math.h>

#define BB 8
#define NN 8192
#define DD 128
#define DVV 128
#define MM 256
#define NSPLIT 16

#define SCALE_U 0.29730177875068026f   // 128^-0.25
#define H_SCALE 0.04419417382415922f   // 1/(2*sqrt(128))
#define INV_SQRT_M 0.0625f             // 1/sqrt(256)

typedef unsigned long long ull;
typedef unsigned int u32;

// ---------------------------------------------------------------------------
// Device scratch
// ---------------------------------------------------------------------------
__device__ float g_U[(size_t)BB * NN * MM];      // raw scaled U (K pass)
__device__ float g_h[BB * NN];
__device__ float g_bmax[BB];
__device__ float g_KVpart[NSPLIT][BB * DVV * MM];   // KV^T partials [b][dv][m]
__device__ float g_KsumPart[NSPLIT][BB * MM];
__device__ float g_Ksum[BB * MM];
// omega as packed mma B-fragments: [kstep(8)][nb(32)][lane(32)] x uint4
__device__ u32 g_wfrag[8 * 32 * 32 * 4];
__device__ __nv_bfloat16 g_KVT_hi[BB * DVV * MM];         // [b][dv][m]
__device__ __nv_bfloat16 g_KVT_lo[BB * DVV * MM];

// ---------------------------------------------------------------------------
// PTX helpers (sm_80-level)
// ---------------------------------------------------------------------------
__device__ __forceinline__ u32 smem_u32(const void* p) {
    u32 a;
    asm("{ .reg .u64 t; cvta.to.shared.u64 t, %1; cvt.u32.u64 %0, t; }" : "=r"(a) : "l"(p));
    return a;
}
__device__ __forceinline__ void ldsm_x4(u32& r0, u32& r1, u32& r2, u32& r3, u32 addr) {
    asm volatile("ldmatrix.sync.aligned.m8n8.x4.shared.b16 {%0,%1,%2,%3}, [%4];"
                 : "=r"(r0), "=r"(r1), "=r"(r2), "=r"(r3) : "r"(addr));
}
__device__ __forceinline__ void ldsm_x4t(u32& r0, u32& r1, u32& r2, u32& r3, u32 addr) {
    asm volatile("ldmatrix.sync.aligned.m8n8.x4.trans.shared.b16 {%0,%1,%2,%3}, [%4];"
                 : "=r"(r0), "=r"(r1), "=r"(r2), "=r"(r3) : "r"(addr));
}
__device__ __forceinline__ void mma_bf16(float* c, const u32* a, const u32* b) {
    asm volatile("mma.sync.aligned.m16n8k16.row.col.f32.bf16.bf16.f32 "
                 "{%0,%1,%2,%3}, {%4,%5,%6,%7}, {%8,%9}, {%0,%1,%2,%3};"
                 : "+f"(c[0]), "+f"(c[1]), "+f"(c[2]), "+f"(c[3])
                 : "r"(a[0]), "r"(a[1]), "r"(a[2]), "r"(a[3]), "r"(b[0]), "r"(b[1]));
}
#define CP_ASYNC16(saddr, gptr) \
    asm volatile("cp.async.cg.shared.global [%0], [%1], 16;" :: "r"(saddr), "l"(gptr) : "memory")
#define CP_COMMIT() asm volatile("cp.async.commit_group;" ::: "memory")

__device__ __forceinline__ u32 bpack(float lo, float hi) {
    u32 r;
    asm("cvt.rn.bf16x2.f32 %0, %1, %2;" : "=r"(r) : "f"(hi), "f"(lo));
    return r;
}
__device__ __forceinline__ void cvt8(const float* x, uint4& h4, uint4& l4) {
    u32 h[4], l[4];
    #pragma unroll
    for (int i = 0; i < 4; i++) {
        u32 p = bpack(x[2 * i], x[2 * i + 1]);
        h[i] = p;
        float r0 = x[2 * i]     - __uint_as_float(p << 16);
        float r1 = x[2 * i + 1] - __uint_as_float(p & 0xFFFF0000u);
        l[i] = bpack(r0, r1);
    }
    h4 = make_uint4(h[0], h[1], h[2], h[3]);
    l4 = make_uint4(l[0], l[1], l[2], l[3]);
}

__device__ __forceinline__ float fexp(float x) {
    x = fmaxf(x, -87.0f);
    float t = x * 1.4426950408889634f;
    float r = rintf(t);
    float f = t - r;
    float z = f * 0.6931471805599453f;
    float p = 1.0f + z * (1.0f + z * (0.5f + z * (0.16666667f +
              z * (0.041666667f + z * (0.0083333333f + z * 0.0013888889f)))));
    return __int_as_float(((int)r + 127) << 23) * p;
}
__device__ __forceinline__ float warpMax(float v) {
    #pragma unroll
    for (int o = 16; o; o >>= 1) v = fmaxf(v, __shfl_xor_sync(0xffffffffu, v, o));
    return v;
}
__device__ __forceinline__ void atomicMaxFloat(float* addr, float val) {
    int old = __float_as_int(*addr);
    while (__int_as_float(old) < val) {
        int prev = atomicCAS((int*)addr, old, __float_as_int(val));
        if (prev == old) break;
        old = prev;
    }
}

__global__ void init_kernel() {
    if (threadIdx.x < BB) g_bmax[threadIdx.x] = -INFINITY;
}

__global__ void prep_omega(const float* __restrict__ omega) {
    int id = blockIdx.x * 256 + threadIdx.x;   // 16384 total
    int m = id >> 6;
    int dp = id & 63;
    int d = dp * 2;
    float w0 = omega[(size_t)d * MM + m] * SCALE_U;
    float w1 = omega[(size_t)(d + 1) * MM + m] * SCALE_U;
    u32 hp = bpack(w0, w1);
    float r0 = w0 - __uint_as_float(hp << 16);
    float r1 = w1 - __uint_as_float(hp & 0xFFFF0000u);
    u32 lp = bpack(r0, r1);
    int idx4 = (((d >> 4) * 32 + (m >> 3)) * 32 + (m & 7) * 4 + ((d & 7) >> 1)) * 4;
    int reg = (d >> 3) & 1;
    g_wfrag[idx4 + reg] = hp;
    g_wfrag[idx4 + 2 + reg] = lp;
}

// ---------------------------------------------------------------------------
// Shared projection mainloop (R15): CTA = 64 tok x 256 m, K=128.
// ---------------------------------------------------------------------------
__device__ __forceinline__ void proj_mma_main(
    const float* __restrict__ Xb, char* dyn, u32 sb,
    float c[2][8][4], float* sHred, int saHi, int saLo)
{
    const int tid = threadIdx.x;
    const int lane = tid & 31;
    const int w = tid >> 5;

    {   // A: 64 tok x 128 d, f32 -> bf16 hi/lo, swizzled; h partials
        int row = tid >> 2, seg = (tid & 3) * 32;
        const float* src = Xb + (size_t)row * DD + seg;
        float hs = 0.f;
        #pragma unroll
        for (int q = 0; q < 4; q++) {
            float x[8];
            float4 v0 = *(const float4*)(src + q * 8);
            float4 v1 = *(const float4*)(src + q * 8 + 4);
            x[0] = v0.x; x[1] = v0.y; x[2] = v0.z; x[3] = v0.w;
            x[4] = v1.x; x[5] = v1.y; x[6] = v1.z; x[7] = v1.w;
            #pragma unroll
            for (int e = 0; e < 8; e++) hs = fmaf(x[e], x[e], hs);
            uint4 h4, l4;
            cvt8(x, h4, l4);
            int chunk = ((seg >> 3) + q) ^ (row & 7);
            *(uint4*)(dyn + saHi + row * 256 + (chunk << 4)) = h4;
            *(uint4*)(dyn + saLo + row * 256 + (chunk << 4)) = l4;
        }
        sHred[tid] = hs;
    }
    __syncthreads();

    const int tok0 = (w & 1) * 32;
    const int m0w = (w >> 1) * 64;
    const int rowA0 = tok0 + ((lane >> 3) & 1) * 8 + (lane & 7);
    const int kselA = (lane >> 4) & 1;
    const int nbBase = (m0w >> 3);

    #pragma unroll
    for (int ks = 0; ks < 8; ks++) {
        int kc = ks * 2;
        u32 ah[2][4], al[2][4];
        #pragma unroll
        for (int mb = 0; mb < 2; mb++) {
            int row = rowA0 + mb * 16;
            u32 adr = sb + saHi + row * 256 + (((kc + kselA) ^ (row & 7)) << 4);
            ldsm_x4(ah[mb][0], ah[mb][1], ah[mb][2], ah[mb][3], adr);
            ldsm_x4(al[mb][0], al[mb][1], al[mb][2], al[mb][3], adr + (saLo - saHi));
        }
        #pragma unroll
        for (int nb = 0; nb < 8; nb++) {
            uint4 f = *(const uint4*)&g_wfrag[((ks * 32 + nbBase + nb) * 32 + lane) * 4];
            u32 bh[2] = {f.x, f.y};
            u32 bl[2] = {f.z, f.w};
            #pragma unroll
            for (int mb = 0; mb < 2; mb++) {
                mma_bf16(c[mb][nb], ah[mb], bh);
                mma_bf16(c[mb][nb], al[mb], bh);
                mma_bf16(c[mb][nb], ah[mb], bl);
            }
        }
    }
    __syncthreads();
}

// ---------------------------------------------------------------------------
// kproj: R15 version.
// ---------------------------------------------------------------------------
#define P_SMEM 67584
#define SU_STRIDE 264

__global__ void __launch_bounds__(256, 2)
kproj_mma(const float* __restrict__ Kin) {
    extern __shared__ __align__(16) char dyn[];
    __shared__ float sHred[256];
    __shared__ float wred[8];

    const int tid = threadIdx.x;
    const int b = blockIdx.y;
    const int n0 = blockIdx.x * 64;
    const u32 sbase = smem_u32(dyn);

    float c[2][8][4];
    #pragma unroll
    for (int mb = 0; mb < 2; mb++)
        #pragma unroll
        for (int nb = 0; nb < 8; nb++)
            #pragma unroll
            for (int q = 0; q < 4; q++) c[mb][nb][q] = 0.f;

    proj_mma_main(Kin + ((size_t)b * NN + n0) * DD, dyn, sbase, c, sHred, 0, 16384);

    float* sU = (float*)dyn;
    const int lane = tid & 31, w = tid >> 5;
    const int tok0 = (w & 1) * 32, m0w = (w >> 1) * 64;
    const int gid = lane >> 2, tig = lane & 3;
    float lmax = -INFINITY;
    #pragma unroll
    for (int mb = 0; mb < 2; mb++)
        #pragma unroll
        for (int nb = 0; nb < 8; nb++) {
            int r0 = tok0 + mb * 16 + gid;
            int m = m0w + nb * 8 + 2 * tig;
            float2 p0 = make_float2(c[mb][nb][0], c[mb][nb][1]);
            float2 p1 = make_float2(c[mb][nb][2], c[mb][nb][3]);
            *(float2*)&sU[r0 * SU_STRIDE + m] = p0;
            *(float2*)&sU[(r0 + 8) * SU_STRIDE + m] = p1;
            lmax = fmaxf(lmax, fmaxf(fmaxf(p0.x, p0.y), fmaxf(p1.x, p1.y)));
        }
    __syncthreads();

    {
        int row = tid >> 2, seg = (tid & 3) * 64;
        float* dst = g_U + ((size_t)(b * NN + n0 + row)) * MM + seg;
        const float* srcr = sU + row * SU_STRIDE + seg;
        #pragma unroll
        for (int q = 0; q < 16; q++)
            *(float4*)(dst + q * 4) = *(const float4*)(srcr + q * 4);
    }
    if (tid < 64) {
        float h = sHred[tid * 4] + sHred[tid * 4 + 1] + sHred[tid * 4 + 2] + sHred[tid * 4 + 3];
        g_h[b * NN + n0 + tid] = h * H_SCALE;
    }
    lmax = warpMax(lmax);
    if ((tid & 31) == 0) wred[tid >> 5] = lmax;
    __syncthreads();
    if (tid == 0) {
        float m = wred[0];
        #pragma unroll
        for (int q = 1; q < 8; q++) m = fmaxf(m, wred[q]);
        atomicMaxFloat(&g_bmax[b], m);
    }
}

// ---------------------------------------------------------------------------
// kv_mma: cp.async double-buffered pipeline. CTA 128dv x 128m, chunks of 32 n.
// smem: SKP hi@0/lo@8K, SV hi@16K/lo@24K, stages (V 16K + U 16K) @32K and @64K.
// ---------------------------------------------------------------------------
#define KV_SKP 0
#define KV_SKP_LO 8192
#define KV_SV 16384
#define KV_SV_LO 24576
#define KV_STAGE 32768
#define KV_SMEM 98304

__global__ void __launch_bounds__(256, 2)
kv_mma(const float* __restrict__ V, const float* __restrict__ mask) {
    extern __shared__ __align__(16) char dyn[];

    const int tid = threadIdx.x;
    const int lane = tid & 31;
    const int w = tid >> 5;
    const int b = blockIdx.z;
    const int m0blk = blockIdx.y * 128;
    const int split = blockIdx.x;
    const float mx = g_bmax[b];
    const u32 sbase = smem_u32(dyn);

    const int dv0 = (w & 3) * 32;
    const int m0w = (w >> 2) * 64;
    const int gid = lane >> 2, tig = lane & 3;

    float c[2][8][4];
    #pragma unroll
    for (int mb = 0; mb < 2; mb++)
        #pragma unroll
        for (int nb = 0; nb < 8; nb++)
            #pragma unroll
            for (int q = 0; q < 4; q++) c[mb][nb][q] = 0.f;
    float ksloc[8];
    #pragma unroll
    for (int i = 0; i < 8; i++) ksloc[i] = 0.f;

    const int mg2 = tid & 15;          // Kp conv: 8-m group
    const int ng = tid >> 4;           // Kp conv: 2 rows per chunk
    const int urow = tid >> 3, upart = tid & 7;   // U staging

    const int nbase = split * (NN / NSPLIT);

    // prologue: stage chunk 0
    {
        const char* gV = (const char*)(V + ((size_t)(b * NN + nbase)) * DVV) + tid * 64;
        u32 sv = sbase + KV_STAGE + tid * 64;
        #pragma unroll
        for (int q = 0; q < 4; q++) CP_ASYNC16(sv + q * 16, gV + q * 16);
        const char* gU = (const char*)(g_U + ((size_t)(b * NN + nbase + urow)) * MM + m0blk) + upart * 64;
        u32 su = sbase + KV_STAGE + 16384 + urow * 512 + upart * 64;
        #pragma unroll
        for (int q = 0; q < 4; q++) CP_ASYNC16(su + q * 16, gU + q * 16);
        CP_COMMIT();
    }
    float hpre0 = g_h[b * NN + nbase + ng * 2];
    float hpre1 = g_h[b * NN + nbase + ng * 2 + 1];
    float mpre0 = mask[b * NN + nbase + ng * 2];
    float mpre1 = mask[b * NN + nbase + ng * 2 + 1];

    for (int ch = 0; ch < 16; ch++) {
        const int cur = ch & 1;
        const u32 stage = sbase + KV_STAGE + cur * 32768;
        float hc0 = hpre0, hc1 = hpre1, mc0 = mpre0, mc1 = mpre1;

        if (ch < 15) {
            const int n1 = nbase + (ch + 1) * 32;
            const char* gV = (const char*)(V + ((size_t)(b * NN + n1)) * DVV) + tid * 64;
            u32 sv = sbase + KV_STAGE + (cur ^ 1) * 32768 + tid * 64;
            #pragma unroll
            for (int q = 0; q < 4; q++) CP_ASYNC16(sv + q * 16, gV + q * 16);
            const char* gU = (const char*)(g_U + ((size_t)(b * NN + n1 + urow)) * MM + m0blk) + upart * 64;
            u32 su = sbase + KV_STAGE + (cur ^ 1) * 32768 + 16384 + urow * 512 + upart * 64;
            #pragma unroll
            for (int q = 0; q < 4; q++) CP_ASYNC16(su + q * 16, gU + q * 16);
            CP_COMMIT();
            hpre0 = g_h[b * NN + n1 + ng * 2];
            hpre1 = g_h[b * NN + n1 + ng * 2 + 1];
            mpre0 = mask[b * NN + n1 + ng * 2];
            mpre1 = mask[b * NN + n1 + ng * 2 + 1];
            asm volatile("cp.async.wait_group 1;" ::: "memory");
        } else {
            asm volatile("cp.async.wait_group 0;" ::: "memory");
        }
        __syncthreads();   // stage[cur] visible; previous MMA done (tiles reusable)

        {   // V convert: 32 n x 128 dv from stage -> bf16 tiles
            int row = tid >> 3, seg = (tid & 7) * 16;
            const float* src = (const float*)(dyn + KV_STAGE + cur * 32768) + row * 128 + seg;
            #pragma unroll
            for (int q = 0; q < 2; q++) {
                float x[8];
                float4 v0 = *(const float4*)(src + q * 8);
                float4 v1 = *(const float4*)(src + q * 8 + 4);
                x[0] = v0.x; x[1] = v0.y; x[2] = v0.z; x[3] = v0.w;
                x[4] = v1.x; x[5] = v1.y; x[6] = v1.z; x[7] = v1.w;
                uint4 h4, l4;
                cvt8(x, h4, l4);
                int chunk = ((seg >> 3) + q) ^ (row & 7);
                *(uint4*)(dyn + KV_SV + row * 256 + (chunk << 4)) = h4;
                *(uint4*)(dyn + KV_SV_LO + row * 256 + (chunk << 4)) = l4;
            }
        }
        {   // Kp convert: 32 n x 128 m
            #pragma unroll
            for (int r = 0; r < 2; r++) {
                int n = ng * 2 + r;
                const float* up = (const float*)(dyn + KV_STAGE + cur * 32768 + 16384) + n * 128 + mg2 * 8;
                float off = (r ? hc1 : hc0) + mx;
                float s = INV_SQRT_M * (r ? mc1 : mc0);
                float kp[8];
                float4 u0 = *(const float4*)(up);
                float4 u1 = *(const float4*)(up + 4);
                kp[0] = (fexp(u0.x - off) + 1e-4f) * s;
                kp[1] = (fexp(u0.y - off) + 1e-4f) * s;
                kp[2] = (fexp(u0.z - off) + 1e-4f) * s;
                kp[3] = (fexp(u0.w - off) + 1e-4f) * s;
                kp[4] = (fexp(u1.x - off) + 1e-4f) * s;
                kp[5] = (fexp(u1.y - off) + 1e-4f) * s;
                kp[6] = (fexp(u1.z - off) + 1e-4f) * s;
                kp[7] = (fexp(u1.w - off) + 1e-4f) * s;
                #pragma unroll
                for (int i = 0; i < 8; i++) ksloc[i] += kp[i];
                uint4 h4, l4;
                cvt8(kp, h4, l4);
                int chunk = mg2 ^ (n & 7);
                *(uint4*)(dyn + KV_SKP + n * 256 + (chunk << 4)) = h4;
                *(uint4*)(dyn + KV_SKP_LO + n * 256 + (chunk << 4)) = l4;
            }
        }
        __syncthreads();

        #pragma unroll
        for (int ks = 0; ks < 2; ks++) {
            const int kk = ks * 16;
            u32 avh[2][4], avl[2][4];
            {
                int row = kk + ((lane >> 4) & 1) * 8 + (lane & 7);
                int cb = (dv0 >> 3) + ((lane >> 3) & 1);
                #pragma unroll
                for (int mb = 0; mb < 2; mb++) {
                    int chunk = (cb + mb * 2) ^ (row & 7);
                    u32 adr = sbase + KV_SV + row * 256 + (chunk << 4);
                    ldsm_x4t(avh[mb][0], avh[mb][1], avh[mb][2], avh[mb][3], adr);
                    ldsm_x4t(avl[mb][0], avl[mb][1], avl[mb][2], avl[mb][3], adr + 8192);
                }
            }
            {
                int row = kk + ((lane >> 3) & 1) * 8 + (lane & 7);
                int cb = (m0w >> 3) + ((lane >> 4) & 1);
                #pragma unroll
                for (int nbp = 0; nbp < 4; nbp++) {
                    int chunk = (cb + nbp * 2) ^ (row & 7);
                    u32 adr = sbase + KV_SKP + row * 256 + (chunk << 4);
                    u32 bh0[2], bh1[2], bl0[2], bl1[2];
                    ldsm_x4t(bh0[0], bh0[1], bh1[0], bh1[1], adr);
                    ldsm_x4t(bl0[0], bl0[1], bl1[0], bl1[1], adr + 8192);
                    #pragma unroll
                    for (int mb = 0; mb < 2; mb++) {
                        mma_bf16(c[mb][2 * nbp], avh[mb], bh0);
                        mma_bf16(c[mb][2 * nbp], avl[mb], bh0);
                        mma_bf16(c[mb][2 * nbp], avh[mb], bl0);
                        mma_bf16(c[mb][2 * nbp + 1], avh[mb], bh1);
                        mma_bf16(c[mb][2 * nbp + 1], avl[mb], bh1);
                        mma_bf16(c[mb][2 * nbp + 1], avh[mb], bl1);
                    }
                }
            }
        }
    }

    float* outp = g_KVpart[split];
    #pragma unroll
    for (int mb = 0; mb < 2; mb++)
        #pragma unroll
        for (int nb = 0; nb < 8; nb++) {
            int dv = dv0 + mb * 16 + gid;
            int m = m0blk + m0w + nb * 8 + 2 * tig;
            *(float2*)&outp[(size_t)(b * DVV + dv) * MM + m] =
                make_float2(c[mb][nb][0], c[mb][nb][1]);
            *(float2*)&outp[(size_t)(b * DVV + dv + 8) * MM + m] =
                make_float2(c[mb][nb][2], c[mb][nb][3]);
        }

    // ksum: sKs [16 ng][128 m] f32 (overlays stage region)
    float* sKs = (float*)(dyn + KV_STAGE);
    __syncthreads();
    #pragma unroll
    for (int i = 0; i < 8; i++) sKs[ng * 128 + mg2 * 8 + i] = ksloc[i];
    __syncthreads();
    if (tid < 128) {
        float s = 0.f;
        #pragma unroll
        for (int r = 0; r < 16; r++) s += sKs[r * 128 + tid];
        g_KsumPart[split][b * MM + m0blk + tid] = s;
    }
}

__global__ void reduce_kernel() {
    int i = blockIdx.x * 256 + threadIdx.x;
    if (i < BB * DVV * MM) {
        float s = 0.f;
        #pragma unroll
        for (int p = 0; p < NSPLIT; p++) s += g_KVpart[p][i];
        __nv_bfloat16 h = __float2bfloat16(s);
        g_KVT_hi[i] = h;
        g_KVT_lo[i] = __float2bfloat16(s - __bfloat162float(h));
    }
    int j = i - BB * DVV * MM;
    if (j >= 0 && j < BB * MM) {
        float s = 0.f;
        #pragma unroll
        for (int p = 0; p < NSPLIT; p++) s += g_KsumPart[p][j];
        g_Ksum[j] = s;
    }
}

// ---------------------------------------------------------------------------
// qout_fused: R15 version (projection + epilogue + pipelined Out GEMM).
// ---------------------------------------------------------------------------
#define Q_QPH 0
#define Q_QPL 32768
#define Q_SA 65536
#define Q_SA_LO 81920
#define Q_SMEM 98304

__global__ void __launch_bounds__(256, 2)
qout_fused(const float* __restrict__ Qin, const float* __restrict__ mask,
           float* __restrict__ out) {
    extern __shared__ __align__(16) char dyn[];
    __shared__ float sHred[256];
    __shared__ float sKsum[MM];
    __shared__ float sMx[64 * 4];
    __shared__ float sNp[64 * 4];

    const int tid = threadIdx.x;
    const int lane = tid & 31;
    const int w = tid >> 5;
    const int b = blockIdx.y;
    const int n0 = blockIdx.x * 64;
    const u32 sbase = smem_u32(dyn);

    if (tid < MM) sKsum[tid] = g_Ksum[b * MM + tid];

    float c[2][8][4];
    #pragma unroll
    for (int mb = 0; mb < 2; mb++)
        #pragma unroll
        for (int nb = 0; nb < 8; nb++)
            #pragma unroll
            for (int q = 0; q < 4; q++) c[mb][nb][q] = 0.f;

    proj_mma_main(Qin + ((size_t)b * NN + n0) * DD, dyn, sbase, c, sHred, Q_SA, Q_SA_LO);

    // ---- epilogue on fragments ----
    const int tok0 = (w & 1) * 32;
    const int m0w = (w >> 1) * 64;
    const int mg = w >> 1;
    const int gid = lane >> 2, tig = lane & 3;

    #pragma unroll
    for (int mb = 0; mb < 2; mb++) {
        float mA = -INFINITY, mB = -INFINITY;
        #pragma unroll
        for (int nb = 0; nb < 8; nb++) {
            mA = fmaxf(mA, fmaxf(c[mb][nb][0], c[mb][nb][1]));
            mB = fmaxf(mB, fmaxf(c[mb][nb][2], c[mb][nb][3]));
        }
        mA = fmaxf(mA, __shfl_xor_sync(0xffffffffu, mA, 1));
        mA = fmaxf(mA, __shfl_xor_sync(0xffffffffu, mA, 2));
        mB = fmaxf(mB, __shfl_xor_sync(0xffffffffu, mB, 1));
        mB = fmaxf(mB, __shfl_xor_sync(0xffffffffu, mB, 2));
        if (tig == 0) {
            int tA = tok0 + mb * 16 + gid;
            sMx[tA * 4 + mg] = mA;
            sMx[(tA + 8) * 4 + mg] = mB;
        }
    }
    __syncthreads();

    #pragma unroll
    for (int mb = 0; mb < 2; mb++) {
        int tA = tok0 + mb * 16 + gid;
        int tB = tA + 8;
        float mxA = fmaxf(fmaxf(sMx[tA * 4], sMx[tA * 4 + 1]), fmaxf(sMx[tA * 4 + 2], sMx[tA * 4 + 3]));
        float mxB = fmaxf(fmaxf(sMx[tB * 4], sMx[tB * 4 + 1]), fmaxf(sMx[tB * 4 + 2], sMx[tB * 4 + 3]));
        float hA = (sHred[tA * 4] + sHred[tA * 4 + 1] + sHred[tA * 4 + 2] + sHred[tA * 4 + 3]) * H_SCALE;
        float hB = (sHred[tB * 4] + sHred[tB * 4 + 1] + sHred[tB * 4 + 2] + sHred[tB * 4 + 3]) * H_SCALE;
        float sA_ = INV_SQRT_M * mask[b * NN + n0 + tA];
        float sB_ = INV_SQRT_M * mask[b * NN + n0 + tB];
        float offA = hA + mxA, offB = hB + mxB;
        float npA = 0.f, npB = 0.f;
        #pragma unroll
        for (int nb = 0; nb < 8; nb++) {
            int m = m0w + nb * 8 + 2 * tig;
            float q0 = (fexp(c[mb][nb][0] - offA) + 1e-4f) * sA_;
            float q1 = (fexp(c[mb][nb][1] - offA) + 1e-4f) * sA_;
            float q2 = (fexp(c[mb][nb][2] - offB) + 1e-4f) * sB_;
            float q3 = (fexp(c[mb][nb][3] - offB) + 1e-4f) * sB_;
            npA = fmaf(q0, sKsum[m], fmaf(q1, sKsum[m + 1], npA));
            npB = fmaf(q2, sKsum[m], fmaf(q3, sKsum[m + 1], npB));
            int cbase = (m0w >> 3) + nb;
            u32 pA = bpack(q0, q1);
            u32 lA = bpack(q0 - __uint_as_float(pA << 16), q1 - __uint_as_float(pA & 0xFFFF0000u));
            u32 pB = bpack(q2, q3);
            u32 lB = bpack(q2 - __uint_as_float(pB << 16), q3 - __uint_as_float(pB & 0xFFFF0000u));
            *(u32*)(dyn + Q_QPH + tA * 512 + ((cbase ^ (tA & 7)) << 4) + tig * 4) = pA;
            *(u32*)(dyn + Q_QPL + tA * 512 + ((cbase ^ (tA & 7)) << 4) + tig * 4) = lA;
            *(u32*)(dyn + Q_QPH + tB * 512 + ((cbase ^ (tB & 7)) << 4) + tig * 4) = pB;
            *(u32*)(dyn + Q_QPL + tB * 512 + ((cbase ^ (tB & 7)) << 4) + tig * 4) = lB;
        }
        npA += __shfl_xor_sync(0xffffffffu, npA, 1);
        npA += __shfl_xor_sync(0xffffffffu, npA, 2);
        npB += __shfl_xor_sync(0xffffffffu, npB, 1);
        npB += __shfl_xor_sync(0xffffffffu, npB, 2);
        if (tig == 0) {
            sNp[tA * 4 + mg] = npA;
            sNp[tB * 4 + mg] = npB;
        }
    }
    __syncthreads();

    // ---- phase 2: Out = Qp @ KVT^T, KVT loads pipelined ----
    const int tg = w & 1;
    const int dg = w >> 1;
    float c2[2][4][4];
    #pragma unroll
    for (int mb = 0; mb < 2; mb++)
        #pragma unroll
        for (int nb = 0; nb < 4; nb++)
            #pragma unroll
            for (int q = 0; q < 4; q++) c2[mb][nb][q] = 0.f;

    const int rowA0 = tg * 32 + ((lane >> 3) & 1) * 8 + (lane & 7);
    const int kselA = (lane >> 4) & 1;
    const int rowB0 = dg * 32 + ((lane >> 4) & 1) * 8 + (lane & 7);
    const int kselB = (lane >> 3) & 1;

    const int row2 = tid >> 1, hf = tid & 1;
    uint4 rkh[4], rkl[4];
    {   // prologue: chunk 0
        const uint4* kh = (const uint4*)(g_KVT_hi + (size_t)(b * DVV + row2) * MM + hf * 32);
        const uint4* kl = (const uint4*)(g_KVT_lo + (size_t)(b * DVV + row2) * MM + hf * 32);
        #pragma unroll
        for (int q = 0; q < 4; q++) { rkh[q] = kh[q]; rkl[q] = kl[q]; }
    }

    for (int kc = 0; kc < 4; kc++) {
        {
            #pragma unroll
            for (int q = 0; q < 4; q++) {
                int chunk = (hf * 4 + q) ^ (row2 & 7);
                *(uint4*)(dyn + Q_SA + row2 * 128 + (chunk << 4)) = rkh[q];
                *(uint4*)(dyn + Q_SA_LO + row2 * 128 + (chunk << 4)) = rkl[q];
            }
        }
        __syncthreads();
        if (kc < 3) {
            const uint4* kh = (const uint4*)(g_KVT_hi + (size_t)(b * DVV + row2) * MM + (kc + 1) * 64 + hf * 32);
            const uint4* kl = (const uint4*)(g_KVT_lo + (size_t)(b * DVV + row2) * MM + (kc + 1) * 64 + hf * 32);
            #pragma unroll
            for (int q = 0; q < 4; q++) { rkh[q] = kh[q]; rkl[q] = kl[q]; }
        }
        #pragma unroll
        for (int ks = 0; ks < 4; ks++) {
            u32 ah[2][4], al[2][4];
            #pragma unroll
            for (int mb = 0; mb < 2; mb++) {
                int row = rowA0 + mb * 16;
                int chunk = (kc * 8 + ks * 2 + kselA) ^ (row & 7);
                u32 adr = sbase + Q_QPH + row * 512 + (chunk << 4);
                ldsm_x4(ah[mb][0], ah[mb][1], ah[mb][2], ah[mb][3], adr);
                ldsm_x4(al[mb][0], al[mb][1], al[mb][2], al[mb][3], adr + 32768);
            }
            #pragma unroll
            for (int nbp = 0; nbp < 2; nbp++) {
                int row = rowB0 + nbp * 16;
                int chunk = (ks * 2 + kselB) ^ (row & 7);
                u32 adr = sbase + Q_SA + row * 128 + (chunk << 4);
                u32 bh0[2], bh1[2], bl0[2], bl1[2];
                ldsm_x4(bh0[0], bh0[1], bh1[0], bh1[1], adr);
                ldsm_x4(bl0[0], bl0[1], bl1[0], bl1[1], adr + 16384);
                #pragma unroll
                for (int mb = 0; mb < 2; mb++) {
                    mma_bf16(c2[mb][2 * nbp], ah[mb], bh0);
                    mma_bf16(c2[mb][2 * nbp], al[mb], bh0);
                    mma_bf16(c2[mb][2 * nbp], ah[mb], bl0);
                    mma_bf16(c2[mb][2 * nbp + 1], ah[mb], bh1);
                    mma_bf16(c2[mb][2 * nbp + 1], al[mb], bh1);
                    mma_bf16(c2[mb][2 * nbp + 1], ah[mb], bl1);
                }
            }
        }
        __syncthreads();
    }

    // ---- write out ----
    #pragma unroll
    for (int mb = 0; mb < 2; mb++) {
        int t0 = tg * 32 + mb * 16 + gid;
        float r0 = 1.0f / (sNp[t0 * 4] + sNp[t0 * 4 + 1] + sNp[t0 * 4 + 2] + sNp[t0 * 4 + 3] + 1e-8f);
        float r1 = 1.0f / (sNp[(t0 + 8) * 4] + sNp[(t0 + 8) * 4 + 1] + sNp[(t0 + 8) * 4 + 2] + sNp[(t0 + 8) * 4 + 3] + 1e-8f);
        float* d0 = out + ((size_t)(b * NN + n0 + t0)) * DVV;
        float* d1 = d0 + (size_t)8 * DVV;
        #pragma unroll
        for (int nb = 0; nb < 4; nb++) {
            int dv = dg * 32 + nb * 8 + 2 * tig;
            *(float2*)(d0 + dv) = make_float2(c2[mb][nb][0] * r0, c2[mb][nb][1] * r0);
            *(float2*)(d1 + dv) = make_float2(c2[mb][nb][2] * r1, c2[mb][nb][3] * r1);
        }
    }
}

// ---------------------------------------------------------------------------
extern "C" void kernel_launch(void* const* d_in, const int* in_sizes, int n_in,
                              void* d_out, int out_size) {
    const float* Q     = (const float*)d_in[0];
    const float* K     = (const float*)d_in[1];
    const float* V     = (const float*)d_in[2];
    const float* amask = (const float*)d_in[3];
    const float* omega = (const float*)d_in[4];
    float* out = (float*)d_out;

    cudaFuncSetAttribute(kproj_mma,  cudaFuncAttributeMaxDynamicSharedMemorySize, P_SMEM);
    cudaFuncSetAttribute(kv_mma,     cudaFuncAttributeMaxDynamicSharedMemorySize, KV_SMEM);
    cudaFuncSetAttribute(qout_fused, cudaFuncAttributeMaxDynamicSharedMemorySize, Q_SMEM);

    init_kernel<<<1, 32>>>();
    prep_omega<<<64, 256>>>(omega);
    kproj_mma<<<dim3(NN / 64, BB), 256, P_SMEM>>>(K);
    kv_mma<<<dim3(NSPLIT, MM / 128, BB), 256, KV_SMEM>>>(V, amask);
    reduce_kernel<<<(BB * DVV * MM + BB * MM + 255) / 256, 256>>>();
    qout_fused<<<dim3(NN / 64, BB), 256, Q_SMEM>>>(Q, amask, out);
}

// round 17
// speedup vs baseline: 1.9857x; 1.0088x over previous
#include <cuda_runtime.h>
#include <cuda_bf16.h>
#include <math.h>

#define BB 8
#define NN 8192
#define DD 128
#define DVV 128
#define MM 256
#define NSPLIT 16

#define SCALE_U 0.29730177875068026f   // 128^-0.25
#define H_SCALE 0.04419417382415922f   // 1/(2*sqrt(128))
#define INV_SQRT_M 0.0625f             // 1/sqrt(256)

typedef unsigned long long ull;
typedef unsigned int u32;

// ---------------------------------------------------------------------------
// Device scratch
// ---------------------------------------------------------------------------
__device__ float g_U[(size_t)BB * NN * MM];      // raw scaled U (K pass)
__device__ float g_h[BB * NN];
__device__ float g_bmax[BB];
__device__ float g_KVpart[NSPLIT][BB * DVV * MM];   // KV^T partials [b][dv][m]
__device__ float g_KsumPart[NSPLIT][BB * MM];
__device__ float g_Ksum[BB * MM];
// omega as packed mma B-fragments: [kstep(8)][nb(32)][lane(32)] x uint4
__device__ u32 g_wfrag[8 * 32 * 32 * 4];
__device__ __nv_bfloat16 g_KVT_hi[BB * DVV * MM];         // [b][dv][m]
__device__ __nv_bfloat16 g_KVT_lo[BB * DVV * MM];

// ---------------------------------------------------------------------------
// PTX helpers (sm_80-level)
// ---------------------------------------------------------------------------
__device__ __forceinline__ u32 smem_u32(const void* p) {
    u32 a;
    asm("{ .reg .u64 t; cvta.to.shared.u64 t, %1; cvt.u32.u64 %0, t; }" : "=r"(a) : "l"(p));
    return a;
}
__device__ __forceinline__ void ldsm_x4(u32& r0, u32& r1, u32& r2, u32& r3, u32 addr) {
    asm volatile("ldmatrix.sync.aligned.m8n8.x4.shared.b16 {%0,%1,%2,%3}, [%4];"
                 : "=r"(r0), "=r"(r1), "=r"(r2), "=r"(r3) : "r"(addr));
}
__device__ __forceinline__ void ldsm_x4t(u32& r0, u32& r1, u32& r2, u32& r3, u32 addr) {
    asm volatile("ldmatrix.sync.aligned.m8n8.x4.trans.shared.b16 {%0,%1,%2,%3}, [%4];"
                 : "=r"(r0), "=r"(r1), "=r"(r2), "=r"(r3) : "r"(addr));
}
__device__ __forceinline__ void mma_bf16(float* c, const u32* a, const u32* b) {
    asm volatile("mma.sync.aligned.m16n8k16.row.col.f32.bf16.bf16.f32 "
                 "{%0,%1,%2,%3}, {%4,%5,%6,%7}, {%8,%9}, {%0,%1,%2,%3};"
                 : "+f"(c[0]), "+f"(c[1]), "+f"(c[2]), "+f"(c[3])
                 : "r"(a[0]), "r"(a[1]), "r"(a[2]), "r"(a[3]), "r"(b[0]), "r"(b[1]));
}
#define CP_ASYNC16(saddr, gptr) \
    asm volatile("cp.async.cg.shared.global [%0], [%1], 16;" :: "r"(saddr), "l"(gptr) : "memory")
#define CP_COMMIT() asm volatile("cp.async.commit_group;" ::: "memory")

__device__ __forceinline__ u32 bpack(float lo, float hi) {
    u32 r;
    asm("cvt.rn.bf16x2.f32 %0, %1, %2;" : "=r"(r) : "f"(hi), "f"(lo));
    return r;
}
__device__ __forceinline__ void cvt8(const float* x, uint4& h4, uint4& l4) {
    u32 h[4], l[4];
    #pragma unroll
    for (int i = 0; i < 4; i++) {
        u32 p = bpack(x[2 * i], x[2 * i + 1]);
        h[i] = p;
        float r0 = x[2 * i]     - __uint_as_float(p << 16);
        float r1 = x[2 * i + 1] - __uint_as_float(p & 0xFFFF0000u);
        l[i] = bpack(r0, r1);
    }
    h4 = make_uint4(h[0], h[1], h[2], h[3]);
    l4 = make_uint4(l[0], l[1], l[2], l[3]);
}

__device__ __forceinline__ float fexp(float x) {
    x = fmaxf(x, -87.0f);
    float t = x * 1.4426950408889634f;
    float r = rintf(t);
    float f = t - r;
    float z = f * 0.6931471805599453f;
    float p = 1.0f + z * (1.0f + z * (0.5f + z * (0.16666667f +
              z * (0.041666667f + z * (0.0083333333f + z * 0.0013888889f)))));
    return __int_as_float(((int)r + 127) << 23) * p;
}
__device__ __forceinline__ float warpMax(float v) {
    #pragma unroll
    for (int o = 16; o; o >>= 1) v = fmaxf(v, __shfl_xor_sync(0xffffffffu, v, o));
    return v;
}
__device__ __forceinline__ void atomicMaxFloat(float* addr, float val) {
    int old = __float_as_int(*addr);
    while (__int_as_float(old) < val) {
        int prev = atomicCAS((int*)addr, old, __float_as_int(val));
        if (prev == old) break;
        old = prev;
    }
}

// prep_omega also performs bmax init (fused; saves a launch)
__global__ void prep_omega(const float* __restrict__ omega) {
    int id = blockIdx.x * 256 + threadIdx.x;   // 16384 total
    if (id < BB) g_bmax[id] = -INFINITY;
    int m = id >> 6;
    int dp = id & 63;
    int d = dp * 2;
    float w0 = omega[(size_t)d * MM + m] * SCALE_U;
    float w1 = omega[(size_t)(d + 1) * MM + m] * SCALE_U;
    u32 hp = bpack(w0, w1);
    float r0 = w0 - __uint_as_float(hp << 16);
    float r1 = w1 - __uint_as_float(hp & 0xFFFF0000u);
    u32 lp = bpack(r0, r1);
    int idx4 = (((d >> 4) * 32 + (m >> 3)) * 32 + (m & 7) * 4 + ((d & 7) >> 1)) * 4;
    int reg = (d >> 3) & 1;
    g_wfrag[idx4 + reg] = hp;
    g_wfrag[idx4 + 2 + reg] = lp;
}

// ---------------------------------------------------------------------------
// Shared projection mainloop: CTA = 64 tok x 256 m, K=128.
// MMAs issued term-major across 4 accumulators (dep distance 4, bit-identical
// per-accumulator order: hh, lh, hl).
// ---------------------------------------------------------------------------
__device__ __forceinline__ void proj_mma_main(
    const float* __restrict__ Xb, char* dyn, u32 sb,
    float c[2][8][4], float* sHred, int saHi, int saLo)
{
    const int tid = threadIdx.x;
    const int lane = tid & 31;
    const int w = tid >> 5;

    {   // A: 64 tok x 128 d, f32 -> bf16 hi/lo, swizzled; h partials
        int row = tid >> 2, seg = (tid & 3) * 32;
        const float* src = Xb + (size_t)row * DD + seg;
        float hs = 0.f;
        #pragma unroll
        for (int q = 0; q < 4; q++) {
            float x[8];
            float4 v0 = *(const float4*)(src + q * 8);
            float4 v1 = *(const float4*)(src + q * 8 + 4);
            x[0] = v0.x; x[1] = v0.y; x[2] = v0.z; x[3] = v0.w;
            x[4] = v1.x; x[5] = v1.y; x[6] = v1.z; x[7] = v1.w;
            #pragma unroll
            for (int e = 0; e < 8; e++) hs = fmaf(x[e], x[e], hs);
            uint4 h4, l4;
            cvt8(x, h4, l4);
            int chunk = ((seg >> 3) + q) ^ (row & 7);
            *(uint4*)(dyn + saHi + row * 256 + (chunk << 4)) = h4;
            *(uint4*)(dyn + saLo + row * 256 + (chunk << 4)) = l4;
        }
        sHred[tid] = hs;
    }
    __syncthreads();

    const int tok0 = (w & 1) * 32;
    const int m0w = (w >> 1) * 64;
    const int rowA0 = tok0 + ((lane >> 3) & 1) * 8 + (lane & 7);
    const int kselA = (lane >> 4) & 1;
    const int nbBase = (m0w >> 3);

    #pragma unroll
    for (int ks = 0; ks < 8; ks++) {
        int kc = ks * 2;
        u32 ah[2][4], al[2][4];
        #pragma unroll
        for (int mb = 0; mb < 2; mb++) {
            int row = rowA0 + mb * 16;
            u32 adr = sb + saHi + row * 256 + (((kc + kselA) ^ (row & 7)) << 4);
            ldsm_x4(ah[mb][0], ah[mb][1], ah[mb][2], ah[mb][3], adr);
            ldsm_x4(al[mb][0], al[mb][1], al[mb][2], al[mb][3], adr + (saLo - saHi));
        }
        #pragma unroll
        for (int nbp = 0; nbp < 4; nbp++) {
            int nb0 = 2 * nbp, nb1 = 2 * nbp + 1;
            uint4 f0 = *(const uint4*)&g_wfrag[((ks * 32 + nbBase + nb0) * 32 + lane) * 4];
            uint4 f1 = *(const uint4*)&g_wfrag[((ks * 32 + nbBase + nb1) * 32 + lane) * 4];
            u32 bh0[2] = {f0.x, f0.y}, bl0[2] = {f0.z, f0.w};
            u32 bh1[2] = {f1.x, f1.y}, bl1[2] = {f1.z, f1.w};
            // hh
            mma_bf16(c[0][nb0], ah[0], bh0);
            mma_bf16(c[1][nb0], ah[1], bh0);
            mma_bf16(c[0][nb1], ah[0], bh1);
            mma_bf16(c[1][nb1], ah[1], bh1);
            // lh
            mma_bf16(c[0][nb0], al[0], bh0);
            mma_bf16(c[1][nb0], al[1], bh0);
            mma_bf16(c[0][nb1], al[0], bh1);
            mma_bf16(c[1][nb1], al[1], bh1);
            // hl
            mma_bf16(c[0][nb0], ah[0], bl0);
            mma_bf16(c[1][nb0], ah[1], bl0);
            mma_bf16(c[0][nb1], ah[0], bl1);
            mma_bf16(c[1][nb1], ah[1], bl1);
        }
    }
    __syncthreads();
}

// ---------------------------------------------------------------------------
// kproj
// ---------------------------------------------------------------------------
#define P_SMEM 67584
#define SU_STRIDE 264

__global__ void __launch_bounds__(256, 2)
kproj_mma(const float* __restrict__ Kin) {
    extern __shared__ __align__(16) char dyn[];
    __shared__ float sHred[256];
    __shared__ float wred[8];

    const int tid = threadIdx.x;
    const int b = blockIdx.y;
    const int n0 = blockIdx.x * 64;
    const u32 sbase = smem_u32(dyn);

    float c[2][8][4];
    #pragma unroll
    for (int mb = 0; mb < 2; mb++)
        #pragma unroll
        for (int nb = 0; nb < 8; nb++)
            #pragma unroll
            for (int q = 0; q < 4; q++) c[mb][nb][q] = 0.f;

    proj_mma_main(Kin + ((size_t)b * NN + n0) * DD, dyn, sbase, c, sHred, 0, 16384);

    float* sU = (float*)dyn;
    const int lane = tid & 31, w = tid >> 5;
    const int tok0 = (w & 1) * 32, m0w = (w >> 1) * 64;
    const int gid = lane >> 2, tig = lane & 3;
    float lmax = -INFINITY;
    #pragma unroll
    for (int mb = 0; mb < 2; mb++)
        #pragma unroll
        for (int nb = 0; nb < 8; nb++) {
            int r0 = tok0 + mb * 16 + gid;
            int m = m0w + nb * 8 + 2 * tig;
            float2 p0 = make_float2(c[mb][nb][0], c[mb][nb][1]);
            float2 p1 = make_float2(c[mb][nb][2], c[mb][nb][3]);
            *(float2*)&sU[r0 * SU_STRIDE + m] = p0;
            *(float2*)&sU[(r0 + 8) * SU_STRIDE + m] = p1;
            lmax = fmaxf(lmax, fmaxf(fmaxf(p0.x, p0.y), fmaxf(p1.x, p1.y)));
        }
    __syncthreads();

    {
        int row = tid >> 2, seg = (tid & 3) * 64;
        float* dst = g_U + ((size_t)(b * NN + n0 + row)) * MM + seg;
        const float* srcr = sU + row * SU_STRIDE + seg;
        #pragma unroll
        for (int q = 0; q < 16; q++)
            *(float4*)(dst + q * 4) = *(const float4*)(srcr + q * 4);
    }
    if (tid < 64) {
        float h = sHred[tid * 4] + sHred[tid * 4 + 1] + sHred[tid * 4 + 2] + sHred[tid * 4 + 3];
        g_h[b * NN + n0 + tid] = h * H_SCALE;
    }
    lmax = warpMax(lmax);
    if ((tid & 31) == 0) wred[tid >> 5] = lmax;
    __syncthreads();
    if (tid == 0) {
        float m = wred[0];
        #pragma unroll
        for (int q = 1; q < 8; q++) m = fmaxf(m, wred[q]);
        atomicMaxFloat(&g_bmax[b], m);
    }
}

// ---------------------------------------------------------------------------
// kv_mma: cp.async double-buffered pipeline (R16), MMAs term-major.
// ---------------------------------------------------------------------------
#define KV_SKP 0
#define KV_SKP_LO 8192
#define KV_SV 16384
#define KV_SV_LO 24576
#define KV_STAGE 32768
#define KV_SMEM 98304

__global__ void __launch_bounds__(256, 2)
kv_mma(const float* __restrict__ V, const float* __restrict__ mask) {
    extern __shared__ __align__(16) char dyn[];

    const int tid = threadIdx.x;
    const int lane = tid & 31;
    const int w = tid >> 5;
    const int b = blockIdx.z;
    const int m0blk = blockIdx.y * 128;
    const int split = blockIdx.x;
    const float mx = g_bmax[b];
    const u32 sbase = smem_u32(dyn);

    const int dv0 = (w & 3) * 32;
    const int m0w = (w >> 2) * 64;
    const int gid = lane >> 2, tig = lane & 3;

    float c[2][8][4];
    #pragma unroll
    for (int mb = 0; mb < 2; mb++)
        #pragma unroll
        for (int nb = 0; nb < 8; nb++)
            #pragma unroll
            for (int q = 0; q < 4; q++) c[mb][nb][q] = 0.f;
    float ksloc[8];
    #pragma unroll
    for (int i = 0; i < 8; i++) ksloc[i] = 0.f;

    const int mg2 = tid & 15;
    const int ng = tid >> 4;
    const int urow = tid >> 3, upart = tid & 7;

    const int nbase = split * (NN / NSPLIT);

    {   // prologue: stage chunk 0
        const char* gV = (const char*)(V + ((size_t)(b * NN + nbase)) * DVV) + tid * 64;
        u32 sv = sbase + KV_STAGE + tid * 64;
        #pragma unroll
        for (int q = 0; q < 4; q++) CP_ASYNC16(sv + q * 16, gV + q * 16);
        const char* gU = (const char*)(g_U + ((size_t)(b * NN + nbase + urow)) * MM + m0blk) + upart * 64;
        u32 su = sbase + KV_STAGE + 16384 + urow * 512 + upart * 64;
        #pragma unroll
        for (int q = 0; q < 4; q++) CP_ASYNC16(su + q * 16, gU + q * 16);
        CP_COMMIT();
    }
    float hpre0 = g_h[b * NN + nbase + ng * 2];
    float hpre1 = g_h[b * NN + nbase + ng * 2 + 1];
    float mpre0 = mask[b * NN + nbase + ng * 2];
    float mpre1 = mask[b * NN + nbase + ng * 2 + 1];

    for (int ch = 0; ch < 16; ch++) {
        const int cur = ch & 1;
        float hc0 = hpre0, hc1 = hpre1, mc0 = mpre0, mc1 = mpre1;

        if (ch < 15) {
            const int n1 = nbase + (ch + 1) * 32;
            const char* gV = (const char*)(V + ((size_t)(b * NN + n1)) * DVV) + tid * 64;
            u32 sv = sbase + KV_STAGE + (cur ^ 1) * 32768 + tid * 64;
            #pragma unroll
            for (int q = 0; q < 4; q++) CP_ASYNC16(sv + q * 16, gV + q * 16);
            const char* gU = (const char*)(g_U + ((size_t)(b * NN + n1 + urow)) * MM + m0blk) + upart * 64;
            u32 su = sbase + KV_STAGE + (cur ^ 1) * 32768 + 16384 + urow * 512 + upart * 64;
            #pragma unroll
            for (int q = 0; q < 4; q++) CP_ASYNC16(su + q * 16, gU + q * 16);
            CP_COMMIT();
            hpre0 = g_h[b * NN + n1 + ng * 2];
            hpre1 = g_h[b * NN + n1 + ng * 2 + 1];
            mpre0 = mask[b * NN + n1 + ng * 2];
            mpre1 = mask[b * NN + n1 + ng * 2 + 1];
            asm volatile("cp.async.wait_group 1;" ::: "memory");
        } else {
            asm volatile("cp.async.wait_group 0;" ::: "memory");
        }
        __syncthreads();

        {   // V convert
            int row = tid >> 3, seg = (tid & 7) * 16;
            const float* src = (const float*)(dyn + KV_STAGE + cur * 32768) + row * 128 + seg;
            #pragma unroll
            for (int q = 0; q < 2; q++) {
                float x[8];
                float4 v0 = *(const float4*)(src + q * 8);
                float4 v1 = *(const float4*)(src + q * 8 + 4);
                x[0] = v0.x; x[1] = v0.y; x[2] = v0.z; x[3] = v0.w;
                x[4] = v1.x; x[5] = v1.y; x[6] = v1.z; x[7] = v1.w;
                uint4 h4, l4;
                cvt8(x, h4, l4);
                int chunk = ((seg >> 3) + q) ^ (row & 7);
                *(uint4*)(dyn + KV_SV + row * 256 + (chunk << 4)) = h4;
                *(uint4*)(dyn + KV_SV_LO + row * 256 + (chunk << 4)) = l4;
            }
        }
        {   // Kp convert
            #pragma unroll
            for (int r = 0; r < 2; r++) {
                int n = ng * 2 + r;
                const float* up = (const float*)(dyn + KV_STAGE + cur * 32768 + 16384) + n * 128 + mg2 * 8;
                float off = (r ? hc1 : hc0) + mx;
                float s = INV_SQRT_M * (r ? mc1 : mc0);
                float kp[8];
                float4 u0 = *(const float4*)(up);
                float4 u1 = *(const float4*)(up + 4);
                kp[0] = (fexp(u0.x - off) + 1e-4f) * s;
                kp[1] = (fexp(u0.y - off) + 1e-4f) * s;
                kp[2] = (fexp(u0.z - off) + 1e-4f) * s;
                kp[3] = (fexp(u0.w - off) + 1e-4f) * s;
                kp[4] = (fexp(u1.x - off) + 1e-4f) * s;
                kp[5] = (fexp(u1.y - off) + 1e-4f) * s;
                kp[6] = (fexp(u1.z - off) + 1e-4f) * s;
                kp[7] = (fexp(u1.w - off) + 1e-4f) * s;
                #pragma unroll
                for (int i = 0; i < 8; i++) ksloc[i] += kp[i];
                uint4 h4, l4;
                cvt8(kp, h4, l4);
                int chunk = mg2 ^ (n & 7);
                *(uint4*)(dyn + KV_SKP + n * 256 + (chunk << 4)) = h4;
                *(uint4*)(dyn + KV_SKP_LO + n * 256 + (chunk << 4)) = l4;
            }
        }
        __syncthreads();

        #pragma unroll
        for (int ks = 0; ks < 2; ks++) {
            const int kk = ks * 16;
            u32 avh[2][4], avl[2][4];
            {
                int row = kk + ((lane >> 4) & 1) * 8 + (lane & 7);
                int cb = (dv0 >> 3) + ((lane >> 3) & 1);
                #pragma unroll
                for (int mb = 0; mb < 2; mb++) {
                    int chunk = (cb + mb * 2) ^ (row & 7);
                    u32 adr = sbase + KV_SV + row * 256 + (chunk << 4);
                    ldsm_x4t(avh[mb][0], avh[mb][1], avh[mb][2], avh[mb][3], adr);
                    ldsm_x4t(avl[mb][0], avl[mb][1], avl[mb][2], avl[mb][3], adr + 8192);
                }
            }
            {
                int row = kk + ((lane >> 3) & 1) * 8 + (lane & 7);
                int cb = (m0w >> 3) + ((lane >> 4) & 1);
                #pragma unroll
                for (int nbp = 0; nbp < 4; nbp++) {
                    int chunk = (cb + nbp * 2) ^ (row & 7);
                    u32 adr = sbase + KV_SKP + row * 256 + (chunk << 4);
                    u32 bh0[2], bh1[2], bl0[2], bl1[2];
                    ldsm_x4t(bh0[0], bh0[1], bh1[0], bh1[1], adr);
                    ldsm_x4t(bl0[0], bl0[1], bl1[0], bl1[1], adr + 8192);
                    int nb0 = 2 * nbp, nb1 = 2 * nbp + 1;
                    // hh
                    mma_bf16(c[0][nb0], avh[0], bh0);
                    mma_bf16(c[1][nb0], avh[1], bh0);
                    mma_bf16(c[0][nb1], avh[0], bh1);
                    mma_bf16(c[1][nb1], avh[1], bh1);
                    // lh
                    mma_bf16(c[0][nb0], avl[0], bh0);
                    mma_bf16(c[1][nb0], avl[1], bh0);
                    mma_bf16(c[0][nb1], avl[0], bh1);
                    mma_bf16(c[1][nb1], avl[1], bh1);
                    // hl
                    mma_bf16(c[0][nb0], avh[0], bl0);
                    mma_bf16(c[1][nb0], avh[1], bl0);
                    mma_bf16(c[0][nb1], avh[0], bl1);
                    mma_bf16(c[1][nb1], avh[1], bl1);
                }
            }
        }
    }

    float* outp = g_KVpart[split];
    #pragma unroll
    for (int mb = 0; mb < 2; mb++)
        #pragma unroll
        for (int nb = 0; nb < 8; nb++) {
            int dv = dv0 + mb * 16 + gid;
            int m = m0blk + m0w + nb * 8 + 2 * tig;
            *(float2*)&outp[(size_t)(b * DVV + dv) * MM + m] =
                make_float2(c[mb][nb][0], c[mb][nb][1]);
            *(float2*)&outp[(size_t)(b * DVV + dv + 8) * MM + m] =
                make_float2(c[mb][nb][2], c[mb][nb][3]);
        }

    float* sKs = (float*)(dyn + KV_STAGE);
    __syncthreads();
    #pragma unroll
    for (int i = 0; i < 8; i++) sKs[ng * 128 + mg2 * 8 + i] = ksloc[i];
    __syncthreads();
    if (tid < 128) {
        float s = 0.f;
        #pragma unroll
        for (int r = 0; r < 16; r++) s += sKs[r * 128 + tid];
        g_KsumPart[split][b * MM + m0blk + tid] = s;
    }
}

__global__ void reduce_kernel() {
    int i = blockIdx.x * 256 + threadIdx.x;
    if (i < BB * DVV * MM) {
        float s = 0.f;
        #pragma unroll
        for (int p = 0; p < NSPLIT; p++) s += g_KVpart[p][i];
        __nv_bfloat16 h = __float2bfloat16(s);
        g_KVT_hi[i] = h;
        g_KVT_lo[i] = __float2bfloat16(s - __bfloat162float(h));
    }
    int j = i - BB * DVV * MM;
    if (j >= 0 && j < BB * MM) {
        float s = 0.f;
        #pragma unroll
        for (int p = 0; p < NSPLIT; p++) s += g_KsumPart[p][j];
        g_Ksum[j] = s;
    }
}

// ---------------------------------------------------------------------------
// qout_fused: projection + exp/norm epilogue + pipelined Out GEMM (term-major)
// ---------------------------------------------------------------------------
#define Q_QPH 0
#define Q_QPL 32768
#define Q_SA 65536
#define Q_SA_LO 81920
#define Q_SMEM 98304

__global__ void __launch_bounds__(256, 2)
qout_fused(const float* __restrict__ Qin, const float* __restrict__ mask,
           float* __restrict__ out) {
    extern __shared__ __align__(16) char dyn[];
    __shared__ float sHred[256];
    __shared__ float sKsum[MM];
    __shared__ float sMx[64 * 4];
    __shared__ float sNp[64 * 4];

    const int tid = threadIdx.x;
    const int lane = tid & 31;
    const int w = tid >> 5;
    const int b = blockIdx.y;
    const int n0 = blockIdx.x * 64;
    const u32 sbase = smem_u32(dyn);

    if (tid < MM) sKsum[tid] = g_Ksum[b * MM + tid];

    float c[2][8][4];
    #pragma unroll
    for (int mb = 0; mb < 2; mb++)
        #pragma unroll
        for (int nb = 0; nb < 8; nb++)
            #pragma unroll
            for (int q = 0; q < 4; q++) c[mb][nb][q] = 0.f;

    proj_mma_main(Qin + ((size_t)b * NN + n0) * DD, dyn, sbase, c, sHred, Q_SA, Q_SA_LO);

    // ---- epilogue on fragments ----
    const int tok0 = (w & 1) * 32;
    const int m0w = (w >> 1) * 64;
    const int mg = w >> 1;
    const int gid = lane >> 2, tig = lane & 3;

    #pragma unroll
    for (int mb = 0; mb < 2; mb++) {
        float mA = -INFINITY, mB = -INFINITY;
        #pragma unroll
        for (int nb = 0; nb < 8; nb++) {
            mA = fmaxf(mA, fmaxf(c[mb][nb][0], c[mb][nb][1]));
            mB = fmaxf(mB, fmaxf(c[mb][nb][2], c[mb][nb][3]));
        }
        mA = fmaxf(mA, __shfl_xor_sync(0xffffffffu, mA, 1));
        mA = fmaxf(mA, __shfl_xor_sync(0xffffffffu, mA, 2));
        mB = fmaxf(mB, __shfl_xor_sync(0xffffffffu, mB, 1));
        mB = fmaxf(mB, __shfl_xor_sync(0xffffffffu, mB, 2));
        if (tig == 0) {
            int tA = tok0 + mb * 16 + gid;
            sMx[tA * 4 + mg] = mA;
            sMx[(tA + 8) * 4 + mg] = mB;
        }
    }
    __syncthreads();

    #pragma unroll
    for (int mb = 0; mb < 2; mb++) {
        int tA = tok0 + mb * 16 + gid;
        int tB = tA + 8;
        float mxA = fmaxf(fmaxf(sMx[tA * 4], sMx[tA * 4 + 1]), fmaxf(sMx[tA * 4 + 2], sMx[tA * 4 + 3]));
        float mxB = fmaxf(fmaxf(sMx[tB * 4], sMx[tB * 4 + 1]), fmaxf(sMx[tB * 4 + 2], sMx[tB * 4 + 3]));
        float hA = (sHred[tA * 4] + sHred[tA * 4 + 1] + sHred[tA * 4 + 2] + sHred[tA * 4 + 3]) * H_SCALE;
        float hB = (sHred[tB * 4] + sHred[tB * 4 + 1] + sHred[tB * 4 + 2] + sHred[tB * 4 + 3]) * H_SCALE;
        float sA_ = INV_SQRT_M * mask[b * NN + n0 + tA];
        float sB_ = INV_SQRT_M * mask[b * NN + n0 + tB];
        float offA = hA + mxA, offB = hB + mxB;
        float npA = 0.f, npB = 0.f;
        #pragma unroll
        for (int nb = 0; nb < 8; nb++) {
            int m = m0w + nb * 8 + 2 * tig;
            float q0 = (fexp(c[mb][nb][0] - offA) + 1e-4f) * sA_;
            float q1 = (fexp(c[mb][nb][1] - offA) + 1e-4f) * sA_;
            float q2 = (fexp(c[mb][nb][2] - offB) + 1e-4f) * sB_;
            float q3 = (fexp(c[mb][nb][3] - offB) + 1e-4f) * sB_;
            npA = fmaf(q0, sKsum[m], fmaf(q1, sKsum[m + 1], npA));
            npB = fmaf(q2, sKsum[m], fmaf(q3, sKsum[m + 1], npB));
            int cbase = (m0w >> 3) + nb;
            u32 pA = bpack(q0, q1);
            u32 lA = bpack(q0 - __uint_as_float(pA << 16), q1 - __uint_as_float(pA & 0xFFFF0000u));
            u32 pB = bpack(q2, q3);
            u32 lB = bpack(q2 - __uint_as_float(pB << 16), q3 - __uint_as_float(pB & 0xFFFF0000u));
            *(u32*)(dyn + Q_QPH + tA * 512 + ((cbase ^ (tA & 7)) << 4) + tig * 4) = pA;
            *(u32*)(dyn + Q_QPL + tA * 512 + ((cbase ^ (tA & 7)) << 4) + tig * 4) = lA;
            *(u32*)(dyn + Q_QPH + tB * 512 + ((cbase ^ (tB & 7)) << 4) + tig * 4) = pB;
            *(u32*)(dyn + Q_QPL + tB * 512 + ((cbase ^ (tB & 7)) << 4) + tig * 4) = lB;
        }
        npA += __shfl_xor_sync(0xffffffffu, npA, 1);
        npA += __shfl_xor_sync(0xffffffffu, npA, 2);
        npB += __shfl_xor_sync(0xffffffffu, npB, 1);
        npB += __shfl_xor_sync(0xffffffffu, npB, 2);
        if (tig == 0) {
            sNp[tA * 4 + mg] = npA;
            sNp[tB * 4 + mg] = npB;
        }
    }
    __syncthreads();

    // ---- phase 2: Out = Qp @ KVT^T, KVT loads pipelined, MMAs term-major ----
    const int tg = w & 1;
    const int dg = w >> 1;
    float c2[2][4][4];
    #pragma unroll
    for (int mb = 0; mb < 2; mb++)
        #pragma unroll
        for (int nb = 0; nb < 4; nb++)
            #pragma unroll
            for (int q = 0; q < 4; q++) c2[mb][nb][q] = 0.f;

    const int rowA0 = tg * 32 + ((lane >> 3) & 1) * 8 + (lane & 7);
    const int kselA = (lane >> 4) & 1;
    const int rowB0 = dg * 32 + ((lane >> 4) & 1) * 8 + (lane & 7);
    const int kselB = (lane >> 3) & 1;

    const int row2 = tid >> 1, hf = tid & 1;
    uint4 rkh[4], rkl[4];
    {
        const uint4* kh = (const uint4*)(g_KVT_hi + (size_t)(b * DVV + row2) * MM + hf * 32);
        const uint4* kl = (const uint4*)(g_KVT_lo + (size_t)(b * DVV + row2) * MM + hf * 32);
        #pragma unroll
        for (int q = 0; q < 4; q++) { rkh[q] = kh[q]; rkl[q] = kl[q]; }
    }

    for (int kc = 0; kc < 4; kc++) {
        {
            #pragma unroll
            for (int q = 0; q < 4; q++) {
                int chunk = (hf * 4 + q) ^ (row2 & 7);
                *(uint4*)(dyn + Q_SA + row2 * 128 + (chunk << 4)) = rkh[q];
                *(uint4*)(dyn + Q_SA_LO + row2 * 128 + (chunk << 4)) = rkl[q];
            }
        }
        __syncthreads();
        if (kc < 3) {
            const uint4* kh = (const uint4*)(g_KVT_hi + (size_t)(b * DVV + row2) * MM + (kc + 1) * 64 + hf * 32);
            const uint4* kl = (const uint4*)(g_KVT_lo + (size_t)(b * DVV + row2) * MM + (kc + 1) * 64 + hf * 32);
            #pragma unroll
            for (int q = 0; q < 4; q++) { rkh[q] = kh[q]; rkl[q] = kl[q]; }
        }
        #pragma unroll
        for (int ks = 0; ks < 4; ks++) {
            u32 ah[2][4], al[2][4];
            #pragma unroll
            for (int mb = 0; mb < 2; mb++) {
                int row = rowA0 + mb * 16;
                int chunk = (kc * 8 + ks * 2 + kselA) ^ (row & 7);
                u32 adr = sbase + Q_QPH + row * 512 + (chunk << 4);
                ldsm_x4(ah[mb][0], ah[mb][1], ah[mb][2], ah[mb][3], adr);
                ldsm_x4(al[mb][0], al[mb][1], al[mb][2], al[mb][3], adr + 32768);
            }
            #pragma unroll
            for (int nbp = 0; nbp < 2; nbp++) {
                int row = rowB0 + nbp * 16;
                int chunk = (ks * 2 + kselB) ^ (row & 7);
                u32 adr = sbase + Q_SA + row * 128 + (chunk << 4);
                u32 bh0[2], bh1[2], bl0[2], bl1[2];
                ldsm_x4(bh0[0], bh0[1], bh1[0], bh1[1], adr);
                ldsm_x4(bl0[0], bl0[1], bl1[0], bl1[1], adr + 16384);
                int nb0 = 2 * nbp, nb1 = 2 * nbp + 1;
                // hh
                mma_bf16(c2[0][nb0], ah[0], bh0);
                mma_bf16(c2[1][nb0], ah[1], bh0);
                mma_bf16(c2[0][nb1], ah[0], bh1);
                mma_bf16(c2[1][nb1], ah[1], bh1);
                // lh
                mma_bf16(c2[0][nb0], al[0], bh0);
                mma_bf16(c2[1][nb0], al[1], bh0);
                mma_bf16(c2[0][nb1], al[0], bh1);
                mma_bf16(c2[1][nb1], al[1], bh1);
                // hl
                mma_bf16(c2[0][nb0], ah[0], bl0);
                mma_bf16(c2[1][nb0], ah[1], bl0);
                mma_bf16(c2[0][nb1], ah[0], bl1);
                mma_bf16(c2[1][nb1], ah[1], bl1);
            }
        }
        __syncthreads();
    }

    // ---- write out ----
    #pragma unroll
    for (int mb = 0; mb < 2; mb++) {
        int t0 = tg * 32 + mb * 16 + gid;
        float r0 = 1.0f / (sNp[t0 * 4] + sNp[t0 * 4 + 1] + sNp[t0 * 4 + 2] + sNp[t0 * 4 + 3] + 1e-8f);
        float r1 = 1.0f / (sNp[(t0 + 8) * 4] + sNp[(t0 + 8) * 4 + 1] + sNp[(t0 + 8) * 4 + 2] + sNp[(t0 + 8) * 4 + 3] + 1e-8f);
        float* d0 = out + ((size_t)(b * NN + n0 + t0)) * DVV;
        float* d1 = d0 + (size_t)8 * DVV;
        #pragma unroll
        for (int nb = 0; nb < 4; nb++) {
            int dv = dg * 32 + nb * 8 + 2 * tig;
            *(float2*)(d0 + dv) = make_float2(c2[mb][nb][0] * r0, c2[mb][nb][1] * r0);
            *(float2*)(d1 + dv) = make_float2(c2[mb][nb][2] * r1, c2[mb][nb][3] * r1);
        }
    }
}

// ---------------------------------------------------------------------------
extern "C" void kernel_launch(void* const* d_in, const int* in_sizes, int n_in,
                              void* d_out, int out_size) {
    const float* Q     = (const float*)d_in[0];
    const float* K     = (const float*)d_in[1];
    const float* V     = (const float*)d_in[2];
    const float* amask = (const float*)d_in[3];
    const float* omega = (const float*)d_in[4];
    float* out = (float*)d_out;

    cudaFuncSetAttribute(kproj_mma,  cudaFuncAttributeMaxDynamicSharedMemorySize, P_SMEM);
    cudaFuncSetAttribute(kv_mma,     cudaFuncAttributeMaxDynamicSharedMemorySize, KV_SMEM);
    cudaFuncSetAttribute(qout_fused, cudaFuncAttributeMaxDynamicSharedMemorySize, Q_SMEM);

    prep_omega<<<64, 256>>>(omega);
    kproj_mma<<<dim3(NN / 64, BB), 256, P_SMEM>>>(K);
    kv_mma<<<dim3(NSPLIT, MM / 128, BB), 256, KV_SMEM>>>(V, amask);
    reduce_kernel<<<(BB * DVV * MM + BB * MM + 255) / 256, 256>>>();
    qout_fused<<<dim3(NN / 64, BB), 256, Q_SMEM>>>(Q, amask, out);
}